// round 5
// baseline (speedup 1.0000x reference)
#include <cuda_runtime.h>
#include <cstdint>
#include <math.h>

#define BB   8
#define SS   4096
#define DIMM 1024
#define HH   16
#define HDD  64
#define BSR  (BB * SS)          /* 32768 rows */
#define QKVN (3 * DIMM)         /* 3072 */
#define TSPLIT 32
#define SCALE_F 0.125f          /* 64^-0.5 */
#define KDIM 1024               /* K of both big GEMMs */

/* -------- scratch (device globals: allocation-free rule) -------- */
__device__ float g_qkv[(size_t)BSR * QKVN];                       /* 402 MB */
__device__ float g_attn[(size_t)BSR * DIMM];                      /* 134 MB */
__device__ float g_Apart[(size_t)TSPLIT * BB * HH * HDD * HDD];   /* 67 MB  */
__device__ float g_A[(size_t)BB * HH * HDD * HDD];                /* 2 MB   */
__device__ float g_WqkvT[(size_t)QKVN * DIMM];                    /* 12 MB  */
__device__ float g_WprojT[(size_t)DIMM * DIMM];                   /* 4 MB   */
__device__ float g_xr[(size_t)BSR * DIMM];                        /* 134 MB */

__device__ __forceinline__ uint32_t f2tf32(float x) {
    uint32_t r;
    asm("cvt.rna.tf32.f32 %0, %1;" : "=r"(r) : "f"(x));
    return r;
}
__device__ __forceinline__ float roundtf(float x) {
    return __uint_as_float(f2tf32(x));
}

/* K-dim of all GEMM inputs is stored PERMUTED within each 32-float block:
 * stored position q(k) = (k&3)*8 + (k>>2).  Applied consistently to both
 * GEMM operands -> result invariant.  Lets fragments load as float4. */

/* ================= tf32 mma.sync GEMM ================= */

#define BKK   32
#define ASTR  36                      /* padded row stride in floats */
#define STG_F (128 * ASTR)            /* floats per stage per matrix */
#define SMEM_DYN_G (4 * STG_F * 4)    /* 2 stages x (A+B) = 73728 B */
#define NCH   (KDIM / BKK)            /* 32 */

__device__ __forceinline__ uint32_t smem_u32(const void* p) {
    uint32_t a;
    asm("{ .reg .u64 t; cvta.to.shared.u64 t, %1; cvt.u32.u64 %0, t; }"
        : "=r"(a) : "l"(p));
    return a;
}
__device__ __forceinline__ void cp16(uint32_t dst, const void* src) {
    asm volatile("cp.async.cg.shared.global [%0], [%1], 16;"
                 :: "r"(dst), "l"(src) : "memory");
}
__device__ __forceinline__ void mma_tf32(float* c, const uint32_t* a, const uint32_t* b) {
    asm volatile("mma.sync.aligned.m16n8k8.row.col.f32.tf32.tf32.f32 "
                 "{%0,%1,%2,%3}, {%4,%5,%6,%7}, {%8,%9}, {%0,%1,%2,%3};"
                 : "+f"(c[0]), "+f"(c[1]), "+f"(c[2]), "+f"(c[3])
                 : "r"(a[0]), "r"(a[1]), "r"(a[2]), "r"(a[3]),
                   "r"(b[0]), "r"(b[1]));
}

__global__ void __launch_bounds__(256, 2)
gemm_tc(const float* __restrict__ A, const float* __restrict__ BT,
        const float* __restrict__ bias, float* __restrict__ C, int N)
{
    extern __shared__ __align__(16) float sm[];
    float* Bsm = sm + 2 * STG_F;
    const uint32_t uA = smem_u32(sm);
    const uint32_t uB = uA + 2 * STG_F * 4;

    const int tid  = threadIdx.x;
    const int lane = tid & 31;
    const int warp = tid >> 5;
    const int wm   = warp & 1;          /* warp row: 0..1 */
    const int wn   = warp >> 1;         /* warp col: 0..3 */
    const int g    = lane >> 2;         /* group 0..7 */
    const int tig  = lane & 3;          /* 0..3 */

    const int arow = tid >> 1;          /* 0..127 */
    const int seg  = (tid & 1) * 16;
    const float* Ag = A  + (size_t)(blockIdx.y * 128 + arow) * KDIM + seg;
    const float* Bg = BT + (size_t)(blockIdx.x * 128 + arow) * KDIM + seg;
    const uint32_t dstA = uA + (uint32_t)(arow * ASTR + seg) * 4;
    const uint32_t dstB = uB + (uint32_t)(arow * ASTR + seg) * 4;

    float acc[4][4][4];
#pragma unroll
    for (int i = 0; i < 4; i++)
#pragma unroll
        for (int j = 0; j < 4; j++)
#pragma unroll
            for (int r = 0; r < 4; r++) acc[i][j][r] = 0.f;

#pragma unroll
    for (int i = 0; i < 4; i++) {
        cp16(dstA + i * 16, Ag + i * 4);
        cp16(dstB + i * 16, Bg + i * 4);
    }
    asm volatile("cp.async.commit_group;" ::: "memory");

    const int rb = wm * 64;
    const int cb = wn * 32;

    for (int c = 0; c < NCH; c++) {
        const int cur = c & 1;
        if (c + 1 < NCH) {
            const int nxt = (c + 1) & 1;
            const int k0 = (c + 1) * BKK;
#pragma unroll
            for (int i = 0; i < 4; i++) {
                cp16(dstA + (uint32_t)(nxt * STG_F * 4) + i * 16, Ag + k0 + i * 4);
                cp16(dstB + (uint32_t)(nxt * STG_F * 4) + i * 16, Bg + k0 + i * 4);
            }
            asm volatile("cp.async.commit_group;" ::: "memory");
            asm volatile("cp.async.wait_group 1;" ::: "memory");
        } else {
            asm volatile("cp.async.wait_group 0;" ::: "memory");
        }
        __syncthreads();

        const float* As = sm  + cur * STG_F;
        const float* Bs = Bsm + cur * STG_F;

        /* permuted layout: pos tig*8 + h*4 + j holds orig k = 16h + 4j + tig.
         * One float4 per (row, h) = both k-frag elements of ks=2h and 2h+1. */
#pragma unroll
        for (int h = 0; h < 2; h++) {
            float4 alo[4], ahi[4], bv[4];
#pragma unroll
            for (int mf = 0; mf < 4; mf++) {
                const float* ap = As + (rb + mf * 16 + g) * ASTR + tig * 8 + h * 4;
                alo[mf] = *(const float4*)ap;
                ahi[mf] = *(const float4*)(ap + 8 * ASTR);
            }
#pragma unroll
            for (int nf = 0; nf < 4; nf++)
                bv[nf] = *(const float4*)(Bs + (cb + nf * 8 + g) * ASTR + tig * 8 + h * 4);
            /* ks = 2h : components x (k_low), y (k_hi) */
#pragma unroll
            for (int mf = 0; mf < 4; mf++) {
                uint32_t af[4] = { __float_as_uint(alo[mf].x), __float_as_uint(ahi[mf].x),
                                   __float_as_uint(alo[mf].y), __float_as_uint(ahi[mf].y) };
#pragma unroll
                for (int nf = 0; nf < 4; nf++) {
                    uint32_t bf[2] = { __float_as_uint(bv[nf].x), __float_as_uint(bv[nf].y) };
                    mma_tf32(acc[mf][nf], af, bf);
                }
            }
            /* ks = 2h+1 : components z, w */
#pragma unroll
            for (int mf = 0; mf < 4; mf++) {
                uint32_t af[4] = { __float_as_uint(alo[mf].z), __float_as_uint(ahi[mf].z),
                                   __float_as_uint(alo[mf].w), __float_as_uint(ahi[mf].w) };
#pragma unroll
                for (int nf = 0; nf < 4; nf++) {
                    uint32_t bf[2] = { __float_as_uint(bv[nf].z), __float_as_uint(bv[nf].w) };
                    mma_tf32(acc[mf][nf], af, bf);
                }
            }
        }
        __syncthreads();
    }

    const int row0 = blockIdx.y * 128 + rb + g;
    const int col0 = blockIdx.x * 128 + cb + tig * 2;
#pragma unroll
    for (int nf = 0; nf < 4; nf++) {
        const int col = col0 + nf * 8;
        const float b0 = bias[col], b1 = bias[col + 1];
#pragma unroll
        for (int mf = 0; mf < 4; mf++) {
            const int r = row0 + mf * 16;
            float2 v0 = make_float2(acc[mf][nf][0] + b0, acc[mf][nf][1] + b1);
            float2 v1 = make_float2(acc[mf][nf][2] + b0, acc[mf][nf][3] + b1);
            *(float2*)(C + (size_t)r * N + col)       = v0;
            *(float2*)(C + (size_t)(r + 8) * N + col) = v1;
        }
    }
}

/* ---- weight transpose + tf32 round + k-permute:
 * output row n, col (k-dim) stored at permuted position ---- */
__global__ void transpose_kernel(const float* __restrict__ S, float* __restrict__ D,
                                 int R, int Cc)
{
    __shared__ float t[32][33];
    const int bx = blockIdx.x * 32, by = blockIdx.y * 32;
    const int x = threadIdx.x, y = threadIdx.y;   /* 32 x 8 */
#pragma unroll
    for (int j = 0; j < 32; j += 8)
        t[y + j][x] = S[(size_t)(by + y + j) * Cc + bx + x];
    __syncthreads();
    /* col index = by + x ; permute within 32-block: by is 32-aligned */
    const int px = (x & 3) * 8 + (x >> 2);
#pragma unroll
    for (int j = 0; j < 32; j += 8)
        D[(size_t)(bx + y + j) * R + by + px] = roundtf(t[x][y + j]);
}

/* ---- x -> tf32-rounded, k-permuted copy ---- */
__global__ void round_copy_kernel(const float* __restrict__ S, float* __restrict__ D)
{
    const size_t base = ((size_t)blockIdx.x * 256 + threadIdx.x) * 4;
    float4 v = *(const float4*)(S + base);
    const size_t blk = base & ~(size_t)31;
    const int m = (int)((base & 31) >> 2);      /* k>>2 within block */
    D[blk + m +  0] = roundtf(v.x);             /* k&3 == 0 */
    D[blk + m +  8] = roundtf(v.y);
    D[blk + m + 16] = roundtf(v.z);
    D[blk + m + 24] = roundtf(v.w);
}

/* ---------------- softmaxes & small GEMMs ---------------- */

__global__ void q_softmax_kernel(float* __restrict__ qkv)
{
    const int b       = blockIdx.x / (DIMM / 32);
    const int colbase = (blockIdx.x % (DIMM / 32)) * 32;
    const int c = threadIdx.x & 31;
    const int r = threadIdx.x >> 5;   /* 0..31 */
    const int stride = QKVN;
    float* base = qkv + (size_t)b * SS * stride + colbase + c;

    __shared__ float red[32][33];

    float mx = -INFINITY;
    for (int s = r; s < SS; s += 32)
        mx = fmaxf(mx, base[(size_t)s * stride]);
    red[r][c] = mx;
    __syncthreads();
    if (r == 0) {
        float m = red[0][c];
#pragma unroll
        for (int i = 1; i < 32; i++) m = fmaxf(m, red[i][c]);
        red[0][c] = m;
    }
    __syncthreads();
    mx = red[0][c];
    __syncthreads();

    float sum = 0.f;
    for (int s = r; s < SS; s += 32)
        sum += __expf(base[(size_t)s * stride] - mx);
    red[r][c] = sum;
    __syncthreads();
    if (r == 0) {
        float t = 0.f;
#pragma unroll
        for (int i = 0; i < 32; i++) t += red[i][c];
        red[0][c] = t;
    }
    __syncthreads();
    const float inv = SCALE_F / red[0][c];

    for (int s = r; s < SS; s += 32) {
        size_t off = (size_t)s * stride;
        base[off] = __expf(base[off] - mx) * inv;
    }
}

__global__ void k_softmax_kernel(float* __restrict__ qkv)
{
    const int row  = blockIdx.x * 8 + (threadIdx.x >> 5);
    const int lane = threadIdx.x & 31;
    float* p = qkv + (size_t)(row / HH) * QKVN + DIMM + (row % HH) * HDD;

    float v0 = p[lane], v1 = p[lane + 32];
    float m = fmaxf(v0, v1);
#pragma unroll
    for (int o = 16; o > 0; o >>= 1)
        m = fmaxf(m, __shfl_xor_sync(0xFFFFFFFFu, m, o));
    float e0 = __expf(v0 - m), e1 = __expf(v1 - m);
    float s = e0 + e1;
#pragma unroll
    for (int o = 16; o > 0; o >>= 1)
        s += __shfl_xor_sync(0xFFFFFFFFu, s, o);
    float inv = 1.f / s;
    p[lane]      = e0 * inv;
    p[lane + 32] = e1 * inv;
}

__global__ void ktq_kernel(const float* __restrict__ qkv, float* __restrict__ Apart)
{
    const int bh = blockIdx.x / TSPLIT;
    const int ts = blockIdx.x % TSPLIT;
    const int b = bh / HH, h = bh % HH;
    const int TCHUNK = SS / TSPLIT;

    __shared__ __align__(16) float ks[32][64];
    __shared__ __align__(16) float qs[32][64];

    const int tid = threadIdx.x;
    const int tc = tid & 15;
    const int tr = tid >> 4;
    const int lr = tid >> 3;
    const int lc = tid & 7;

    float acc[4][4];
#pragma unroll
    for (int i = 0; i < 4; i++)
#pragma unroll
        for (int j = 0; j < 4; j++) acc[i][j] = 0.f;

    const float* base = qkv + ((size_t)b * SS + (size_t)ts * TCHUNK) * QKVN;

    for (int t0 = 0; t0 < TCHUNK; t0 += 32) {
        const float* qrow = base + (size_t)(t0 + lr) * QKVN + h * HDD;
        const float* krow = qrow + DIMM;
        *(float4*)&qs[lr][lc * 4]      = *(const float4*)(qrow + lc * 4);
        *(float4*)&qs[lr][lc * 4 + 32] = *(const float4*)(qrow + lc * 4 + 32);
        *(float4*)&ks[lr][lc * 4]      = *(const float4*)(krow + lc * 4);
        *(float4*)&ks[lr][lc * 4 + 32] = *(const float4*)(krow + lc * 4 + 32);
        __syncthreads();
#pragma unroll
        for (int kk = 0; kk < 32; kk++) {
            float kr[4], qr[4];
            *(float4*)kr = *(const float4*)&ks[kk][tr * 4];
            *(float4*)qr = *(const float4*)&qs[kk][tc * 4];
#pragma unroll
            for (int i = 0; i < 4; i++)
#pragma unroll
                for (int j = 0; j < 4; j++)
                    acc[i][j] += kr[i] * qr[j];
        }
        __syncthreads();
    }

    float* outp = Apart + ((size_t)ts * BB * HH + bh) * HDD * HDD;
#pragma unroll
    for (int i = 0; i < 4; i++) {
        float4 v = make_float4(acc[i][0], acc[i][1], acc[i][2], acc[i][3]);
        *(float4*)&outp[(tr * 4 + i) * HDD + tc * 4] = v;
    }
}

__global__ void a_reduce_kernel(const float* __restrict__ Apart, float* __restrict__ A)
{
    const int idx = blockIdx.x * 256 + threadIdx.x;
    const size_t stride = (size_t)BB * HH * HDD * HDD;
    float s = 0.f;
#pragma unroll
    for (int p = 0; p < TSPLIT; p++)
        s += Apart[(size_t)p * stride + idx];
    A[idx] = s;
}

/* vA: writes attn tf32-rounded AND k-permuted (attn feeds GEMM2's k-dim) */
__global__ void vA_kernel(const float* __restrict__ qkv, const float* __restrict__ Amat,
                          float* __restrict__ outp)
{
    const int stile = blockIdx.x % (SS / 64);
    const int bh    = blockIdx.x / (SS / 64);
    const int b = bh / HH, h = bh % HH;

    __shared__ __align__(16) float Am[64][64];
    __shared__ __align__(16) float vs[64][68];

    const int tid = threadIdx.x;
    const int tc = tid & 15;
    const int tr = tid >> 4;

    {
        const float4* Ab = (const float4*)(Amat + (size_t)bh * HDD * HDD);
        float4* Ad = (float4*)&Am[0][0];
#pragma unroll
        for (int i = 0; i < 4; i++) Ad[tid + i * 256] = Ab[tid + i * 256];
    }
    {
        const int lr = tid >> 2;
        const int lc = tid & 3;
        const float* vrow = qkv + ((size_t)b * SS + (size_t)stile * 64 + lr) * QKVN
                            + 2 * DIMM + h * HDD;
#pragma unroll
        for (int m = 0; m < 4; m++)
            *(float4*)&vs[lr][(lc + 4 * m) * 4] = *(const float4*)(vrow + (lc + 4 * m) * 4);
    }
    __syncthreads();

    float acc[4][4];
#pragma unroll
    for (int i = 0; i < 4; i++)
#pragma unroll
        for (int j = 0; j < 4; j++) acc[i][j] = 0.f;

#pragma unroll 8
    for (int d = 0; d < 64; d++) {
        float br[4];
        *(float4*)br = *(const float4*)&Am[d][tc * 4];
        float vr[4];
#pragma unroll
        for (int i = 0; i < 4; i++) vr[i] = vs[tr * 4 + i][d];
#pragma unroll
        for (int i = 0; i < 4; i++)
#pragma unroll
            for (int j = 0; j < 4; j++)
                acc[i][j] += vr[i] * br[j];
    }

    /* output col base c0 = h*64 + tc*4 (4-aligned); permute within 32-block */
    const int c0  = h * HDD + tc * 4;
    const int blk = c0 & ~31;
    const int m4  = (c0 & 31) >> 2;
#pragma unroll
    for (int i = 0; i < 4; i++) {
        size_t row = (size_t)b * SS + (size_t)stile * 64 + tr * 4 + i;
        float* orow = outp + row * DIMM + blk + m4;
        orow[0]  = roundtf(acc[i][0]);
        orow[8]  = roundtf(acc[i][1]);
        orow[16] = roundtf(acc[i][2]);
        orow[24] = roundtf(acc[i][3]);
    }
}

/* --------------------------------------------------------------- */
extern "C" void kernel_launch(void* const* d_in, const int* in_sizes, int n_in,
                              void* d_out, int out_size)
{
    (void)in_sizes; (void)n_in; (void)out_size;
    const float* x     = (const float*)d_in[0];
    const float* Wqkv  = (const float*)d_in[1];
    const float* bqkv  = (const float*)d_in[2];
    const float* Wproj = (const float*)d_in[3];
    const float* bproj = (const float*)d_in[4];
    float* out = (float*)d_out;

    float *qkv, *attn, *Apart, *Amat, *WqkvT, *WprojT, *xr;
    cudaGetSymbolAddress((void**)&qkv,    g_qkv);
    cudaGetSymbolAddress((void**)&attn,   g_attn);
    cudaGetSymbolAddress((void**)&Apart,  g_Apart);
    cudaGetSymbolAddress((void**)&Amat,   g_A);
    cudaGetSymbolAddress((void**)&WqkvT,  g_WqkvT);
    cudaGetSymbolAddress((void**)&WprojT, g_WprojT);
    cudaGetSymbolAddress((void**)&xr,     g_xr);

    cudaFuncSetAttribute(gemm_tc, cudaFuncAttributeMaxDynamicSharedMemorySize, SMEM_DYN_G);

    /* 0) pre-round + k-permute GEMM inputs */
    {
        dim3 blk(32, 8);
        transpose_kernel<<<dim3(QKVN / 32, DIMM / 32), blk>>>(Wqkv, WqkvT, DIMM, QKVN);
        transpose_kernel<<<dim3(DIMM / 32, DIMM / 32), blk>>>(Wproj, WprojT, DIMM, DIMM);
        round_copy_kernel<<<(size_t)BSR * DIMM / (256 * 4), 256>>>(x, xr);
    }
    /* 1) qkv = x @ Wqkv + bqkv  (tf32 mma.sync, float4 frag loads) */
    gemm_tc<<<dim3(QKVN / 128, BSR / 128), 256, SMEM_DYN_G>>>(xr, WqkvT, bqkv, qkv, QKVN);
    /* 2) softmaxes (in place) */
    q_softmax_kernel<<<BB * (DIMM / 32), 1024>>>(qkv);
    k_softmax_kernel<<<(BSR * HH) / 8, 256>>>(qkv);
    /* 3) A = K^T Q per (b,h) */
    ktq_kernel<<<BB * HH * TSPLIT, 256>>>(qkv, Apart);
    a_reduce_kernel<<<(BB * HH * HDD * HDD) / 256, 256>>>(Apart, Amat);
    /* 4) attn = V @ A per (b,h), attn pre-rounded + k-permuted */
    vA_kernel<<<BB * HH * (SS / 64), 256>>>(qkv, Amat, attn);
    /* 5) out = attn @ Wproj + bproj  (tf32 mma.sync) */
    gemm_tc<<<dim3(DIMM / 128, BSR / 128), 256, SMEM_DYN_G>>>(attn, WprojT, bproj, out, DIMM);
}

// round 6
// speedup vs baseline: 1.1157x; 1.1157x over previous
#include <cuda_runtime.h>
#include <cstdint>
#include <math.h>

#define BB   8
#define SS   4096
#define DIMM 1024
#define HH   16
#define HDD  64
#define BSR  (BB * SS)          /* 32768 rows */
#define QKVN (3 * DIMM)         /* 3072 */
#define TSPLIT 32
#define SCALE_F 0.125f          /* 64^-0.5 */
#define KDIM 1024               /* K of both big GEMMs */

/* -------- scratch (device globals: allocation-free rule) -------- */
__device__ float g_qkv[(size_t)BSR * QKVN];                       /* 402 MB */
__device__ float g_attn[(size_t)BSR * DIMM];                      /* 134 MB */
__device__ float g_Apart[(size_t)TSPLIT * BB * HH * HDD * HDD];   /* 67 MB  */
__device__ float g_A[(size_t)BB * HH * HDD * HDD];                /* 2 MB   */
__device__ float g_WqkvT[(size_t)QKVN * DIMM];                    /* 12 MB  */
__device__ float g_WprojT[(size_t)DIMM * DIMM];                   /* 4 MB   */
__device__ float g_xr[(size_t)BSR * DIMM];                        /* 134 MB */

__device__ __forceinline__ uint32_t f2tf32(float x) {
    uint32_t r;
    asm("cvt.rna.tf32.f32 %0, %1;" : "=r"(r) : "f"(x));
    return r;
}
__device__ __forceinline__ float roundtf(float x) {
    return __uint_as_float(f2tf32(x));
}

/* ================= tf32 mma.sync GEMM, ldmatrix fragments =================
 * Inputs pre-rounded to tf32 grid; hot loop = LDSM + HMMA only. */

#define BKK   32
#define ASTR  36                      /* padded row stride in floats */
#define STG_F (128 * ASTR)            /* floats per stage per matrix */
#define SMEM_DYN_G (4 * STG_F * 4)    /* 2 stages x (A+B) = 73728 B */
#define NCH   (KDIM / BKK)            /* 32 */

__device__ __forceinline__ uint32_t smem_u32(const void* p) {
    uint32_t a;
    asm("{ .reg .u64 t; cvta.to.shared.u64 t, %1; cvt.u32.u64 %0, t; }"
        : "=r"(a) : "l"(p));
    return a;
}
__device__ __forceinline__ void cp16(uint32_t dst, const void* src) {
    asm volatile("cp.async.cg.shared.global [%0], [%1], 16;"
                 :: "r"(dst), "l"(src) : "memory");
}
__device__ __forceinline__ void ldsm4(uint32_t* r, uint32_t addr) {
    asm volatile("ldmatrix.sync.aligned.m8n8.x4.shared.b16 {%0,%1,%2,%3}, [%4];"
                 : "=r"(r[0]), "=r"(r[1]), "=r"(r[2]), "=r"(r[3]) : "r"(addr));
}
__device__ __forceinline__ void mma_tf32(float* c, const uint32_t* a, const uint32_t* b) {
    asm volatile("mma.sync.aligned.m16n8k8.row.col.f32.tf32.tf32.f32 "
                 "{%0,%1,%2,%3}, {%4,%5,%6,%7}, {%8,%9}, {%0,%1,%2,%3};"
                 : "+f"(c[0]), "+f"(c[1]), "+f"(c[2]), "+f"(c[3])
                 : "r"(a[0]), "r"(a[1]), "r"(a[2]), "r"(a[3]),
                   "r"(b[0]), "r"(b[1]));
}

__global__ void __launch_bounds__(256, 2)
gemm_tc(const float* __restrict__ A, const float* __restrict__ BT,
        const float* __restrict__ bias, float* __restrict__ C, int N)
{
    extern __shared__ __align__(16) float sm[];
    const uint32_t uA = smem_u32(sm);
    const uint32_t uB = uA + 2 * STG_F * 4;

    const int tid  = threadIdx.x;
    const int lane = tid & 31;
    const int warp = tid >> 5;
    const int wm   = warp & 1;          /* warp row: 0..1 */
    const int wn   = warp >> 1;         /* warp col: 0..3 */
    const int g    = lane >> 2;         /* group 0..7 */
    const int tig  = lane & 3;          /* 0..3 */

    const int arow = tid >> 1;          /* 0..127 */
    const int seg  = (tid & 1) * 16;
    const float* Ag = A  + (size_t)(blockIdx.y * 128 + arow) * KDIM + seg;
    const float* Bg = BT + (size_t)(blockIdx.x * 128 + arow) * KDIM + seg;
    const uint32_t dstA = uA + (uint32_t)(arow * ASTR + seg) * 4;
    const uint32_t dstB = uB + (uint32_t)(arow * ASTR + seg) * 4;

    const int rb = wm * 64;
    const int cb = wn * 32;

    /* ldmatrix per-lane base addresses (bytes, within a stage) */
    /* A .x4: matrix j=lane>>3 -> rows (lane&15), k-half 4*(lane>>4) */
    uint32_t aoff[4];
#pragma unroll
    for (int mf = 0; mf < 4; mf++)
        aoff[mf] = (uint32_t)(((rb + mf * 16 + (lane & 15)) * ASTR
                               + 4 * (lane >> 4)) * 4);
    /* B .x4 (nf pair p): rows cb+p*16+(lane>>4)*8+(lane&7), k-half 4*((lane>>3)&1) */
    uint32_t boff[2];
#pragma unroll
    for (int p = 0; p < 2; p++)
        boff[p] = (uint32_t)(((cb + p * 16 + ((lane >> 4) << 3) + (lane & 7)) * ASTR
                              + 4 * ((lane >> 3) & 1)) * 4);

    float acc[4][4][4];
#pragma unroll
    for (int i = 0; i < 4; i++)
#pragma unroll
        for (int j = 0; j < 4; j++)
#pragma unroll
            for (int r = 0; r < 4; r++) acc[i][j][r] = 0.f;

#pragma unroll
    for (int i = 0; i < 4; i++) {
        cp16(dstA + i * 16, Ag + i * 4);
        cp16(dstB + i * 16, Bg + i * 4);
    }
    asm volatile("cp.async.commit_group;" ::: "memory");

    for (int c = 0; c < NCH; c++) {
        const int cur = c & 1;
        if (c + 1 < NCH) {
            const int nxt = (c + 1) & 1;
            const int k0 = (c + 1) * BKK;
#pragma unroll
            for (int i = 0; i < 4; i++) {
                cp16(dstA + (uint32_t)(nxt * STG_F * 4) + i * 16, Ag + k0 + i * 4);
                cp16(dstB + (uint32_t)(nxt * STG_F * 4) + i * 16, Bg + k0 + i * 4);
            }
            asm volatile("cp.async.commit_group;" ::: "memory");
            asm volatile("cp.async.wait_group 1;" ::: "memory");
        } else {
            asm volatile("cp.async.wait_group 0;" ::: "memory");
        }
        __syncthreads();

        const uint32_t stA = uA + (uint32_t)(cur * STG_F * 4);
        const uint32_t stB = uB + (uint32_t)(cur * STG_F * 4);
#pragma unroll
        for (int ks = 0; ks < 4; ks++) {
            uint32_t av[4][4], bv[2][4];
#pragma unroll
            for (int mf = 0; mf < 4; mf++)
                ldsm4(av[mf], stA + aoff[mf] + ks * 32);
#pragma unroll
            for (int p = 0; p < 2; p++)
                ldsm4(bv[p], stB + boff[p] + ks * 32);
#pragma unroll
            for (int mf = 0; mf < 4; mf++)
#pragma unroll
                for (int nf = 0; nf < 4; nf++)
                    mma_tf32(acc[mf][nf], av[mf], &bv[nf >> 1][(nf & 1) * 2]);
        }
        __syncthreads();
    }

    const int row0 = blockIdx.y * 128 + rb + g;
    const int col0 = blockIdx.x * 128 + cb + tig * 2;
#pragma unroll
    for (int nf = 0; nf < 4; nf++) {
        const int col = col0 + nf * 8;
        const float b0 = bias[col], b1 = bias[col + 1];
#pragma unroll
        for (int mf = 0; mf < 4; mf++) {
            const int r = row0 + mf * 16;
            float2 v0 = make_float2(acc[mf][nf][0] + b0, acc[mf][nf][1] + b1);
            float2 v1 = make_float2(acc[mf][nf][2] + b0, acc[mf][nf][3] + b1);
            *(float2*)(C + (size_t)r * N + col)       = v0;
            *(float2*)(C + (size_t)(r + 8) * N + col) = v1;
        }
    }
}

/* ---- weight transpose + tf32 round: D[c][r] = round(S[r][c]) ---- */
__global__ void transpose_kernel(const float* __restrict__ S, float* __restrict__ D,
                                 int R, int Cc)
{
    __shared__ float t[32][33];
    const int bx = blockIdx.x * 32, by = blockIdx.y * 32;
    const int x = threadIdx.x, y = threadIdx.y;   /* 32 x 8 */
#pragma unroll
    for (int j = 0; j < 32; j += 8)
        t[y + j][x] = S[(size_t)(by + y + j) * Cc + bx + x];
    __syncthreads();
#pragma unroll
    for (int j = 0; j < 32; j += 8)
        D[(size_t)(bx + y + j) * R + by + x] = roundtf(t[x][y + j]);
}

/* ---- x -> tf32-rounded copy ---- */
__global__ void round_copy_kernel(const float* __restrict__ S, float* __restrict__ D)
{
    const size_t i = ((size_t)blockIdx.x * 256 + threadIdx.x) * 4;
    float4 v = *(const float4*)(S + i);
    v.x = roundtf(v.x); v.y = roundtf(v.y);
    v.z = roundtf(v.z); v.w = roundtf(v.w);
    *(float4*)(D + i) = v;
}

/* ---------------- softmaxes & small GEMMs ---------------- */

__global__ void q_softmax_kernel(float* __restrict__ qkv)
{
    const int b       = blockIdx.x / (DIMM / 32);
    const int colbase = (blockIdx.x % (DIMM / 32)) * 32;
    const int c = threadIdx.x & 31;
    const int r = threadIdx.x >> 5;   /* 0..31 */
    const int stride = QKVN;
    float* base = qkv + (size_t)b * SS * stride + colbase + c;

    __shared__ float red[32][33];

    float mx = -INFINITY;
    for (int s = r; s < SS; s += 32)
        mx = fmaxf(mx, base[(size_t)s * stride]);
    red[r][c] = mx;
    __syncthreads();
    if (r == 0) {
        float m = red[0][c];
#pragma unroll
        for (int i = 1; i < 32; i++) m = fmaxf(m, red[i][c]);
        red[0][c] = m;
    }
    __syncthreads();
    mx = red[0][c];
    __syncthreads();

    float sum = 0.f;
    for (int s = r; s < SS; s += 32)
        sum += __expf(base[(size_t)s * stride] - mx);
    red[r][c] = sum;
    __syncthreads();
    if (r == 0) {
        float t = 0.f;
#pragma unroll
        for (int i = 0; i < 32; i++) t += red[i][c];
        red[0][c] = t;
    }
    __syncthreads();
    const float inv = SCALE_F / red[0][c];

    for (int s = r; s < SS; s += 32) {
        size_t off = (size_t)s * stride;
        base[off] = __expf(base[off] - mx) * inv;
    }
}

__global__ void k_softmax_kernel(float* __restrict__ qkv)
{
    const int row  = blockIdx.x * 8 + (threadIdx.x >> 5);
    const int lane = threadIdx.x & 31;
    float* p = qkv + (size_t)(row / HH) * QKVN + DIMM + (row % HH) * HDD;

    float v0 = p[lane], v1 = p[lane + 32];
    float m = fmaxf(v0, v1);
#pragma unroll
    for (int o = 16; o > 0; o >>= 1)
        m = fmaxf(m, __shfl_xor_sync(0xFFFFFFFFu, m, o));
    float e0 = __expf(v0 - m), e1 = __expf(v1 - m);
    float s = e0 + e1;
#pragma unroll
    for (int o = 16; o > 0; o >>= 1)
        s += __shfl_xor_sync(0xFFFFFFFFu, s, o);
    float inv = 1.f / s;
    p[lane]      = e0 * inv;
    p[lane + 32] = e1 * inv;
}

__global__ void ktq_kernel(const float* __restrict__ qkv, float* __restrict__ Apart)
{
    const int bh = blockIdx.x / TSPLIT;
    const int ts = blockIdx.x % TSPLIT;
    const int b = bh / HH, h = bh % HH;
    const int TCHUNK = SS / TSPLIT;

    __shared__ __align__(16) float ks[32][64];
    __shared__ __align__(16) float qs[32][64];

    const int tid = threadIdx.x;
    const int tc = tid & 15;
    const int tr = tid >> 4;
    const int lr = tid >> 3;
    const int lc = tid & 7;

    float acc[4][4];
#pragma unroll
    for (int i = 0; i < 4; i++)
#pragma unroll
        for (int j = 0; j < 4; j++) acc[i][j] = 0.f;

    const float* base = qkv + ((size_t)b * SS + (size_t)ts * TCHUNK) * QKVN;

    for (int t0 = 0; t0 < TCHUNK; t0 += 32) {
        const float* qrow = base + (size_t)(t0 + lr) * QKVN + h * HDD;
        const float* krow = qrow + DIMM;
        *(float4*)&qs[lr][lc * 4]      = *(const float4*)(qrow + lc * 4);
        *(float4*)&qs[lr][lc * 4 + 32] = *(const float4*)(qrow + lc * 4 + 32);
        *(float4*)&ks[lr][lc * 4]      = *(const float4*)(krow + lc * 4);
        *(float4*)&ks[lr][lc * 4 + 32] = *(const float4*)(krow + lc * 4 + 32);
        __syncthreads();
#pragma unroll
        for (int kk = 0; kk < 32; kk++) {
            float kr[4], qr[4];
            *(float4*)kr = *(const float4*)&ks[kk][tr * 4];
            *(float4*)qr = *(const float4*)&qs[kk][tc * 4];
#pragma unroll
            for (int i = 0; i < 4; i++)
#pragma unroll
                for (int j = 0; j < 4; j++)
                    acc[i][j] += kr[i] * qr[j];
        }
        __syncthreads();
    }

    float* outp = Apart + ((size_t)ts * BB * HH + bh) * HDD * HDD;
#pragma unroll
    for (int i = 0; i < 4; i++) {
        float4 v = make_float4(acc[i][0], acc[i][1], acc[i][2], acc[i][3]);
        *(float4*)&outp[(tr * 4 + i) * HDD + tc * 4] = v;
    }
}

__global__ void a_reduce_kernel(const float* __restrict__ Apart, float* __restrict__ A)
{
    const int idx = blockIdx.x * 256 + threadIdx.x;
    const size_t stride = (size_t)BB * HH * HDD * HDD;
    float s = 0.f;
#pragma unroll
    for (int p = 0; p < TSPLIT; p++)
        s += Apart[(size_t)p * stride + idx];
    A[idx] = s;
}

/* vA: writes attn PRE-ROUNDED to tf32 grid (attn is only GEMM2 input) */
__global__ void vA_kernel(const float* __restrict__ qkv, const float* __restrict__ Amat,
                          float* __restrict__ outp)
{
    const int stile = blockIdx.x % (SS / 64);
    const int bh    = blockIdx.x / (SS / 64);
    const int b = bh / HH, h = bh % HH;

    __shared__ __align__(16) float Am[64][64];
    __shared__ __align__(16) float vs[64][68];

    const int tid = threadIdx.x;
    const int tc = tid & 15;
    const int tr = tid >> 4;

    {
        const float4* Ab = (const float4*)(Amat + (size_t)bh * HDD * HDD);
        float4* Ad = (float4*)&Am[0][0];
#pragma unroll
        for (int i = 0; i < 4; i++) Ad[tid + i * 256] = Ab[tid + i * 256];
    }
    {
        const int lr = tid >> 2;
        const int lc = tid & 3;
        const float* vrow = qkv + ((size_t)b * SS + (size_t)stile * 64 + lr) * QKVN
                            + 2 * DIMM + h * HDD;
#pragma unroll
        for (int m = 0; m < 4; m++)
            *(float4*)&vs[lr][(lc + 4 * m) * 4] = *(const float4*)(vrow + (lc + 4 * m) * 4);
    }
    __syncthreads();

    float acc[4][4];
#pragma unroll
    for (int i = 0; i < 4; i++)
#pragma unroll
        for (int j = 0; j < 4; j++) acc[i][j] = 0.f;

#pragma unroll 8
    for (int d = 0; d < 64; d++) {
        float br[4];
        *(float4*)br = *(const float4*)&Am[d][tc * 4];
        float vr[4];
#pragma unroll
        for (int i = 0; i < 4; i++) vr[i] = vs[tr * 4 + i][d];
#pragma unroll
        for (int i = 0; i < 4; i++)
#pragma unroll
            for (int j = 0; j < 4; j++)
                acc[i][j] += vr[i] * br[j];
    }

#pragma unroll
    for (int i = 0; i < 4; i++) {
        size_t row = (size_t)b * SS + (size_t)stile * 64 + tr * 4 + i;
        float4 v = make_float4(roundtf(acc[i][0]), roundtf(acc[i][1]),
                               roundtf(acc[i][2]), roundtf(acc[i][3]));
        *(float4*)(outp + row * DIMM + h * HDD + tc * 4) = v;
    }
}

/* --------------------------------------------------------------- */
extern "C" void kernel_launch(void* const* d_in, const int* in_sizes, int n_in,
                              void* d_out, int out_size)
{
    (void)in_sizes; (void)n_in; (void)out_size;
    const float* x     = (const float*)d_in[0];
    const float* Wqkv  = (const float*)d_in[1];
    const float* bqkv  = (const float*)d_in[2];
    const float* Wproj = (const float*)d_in[3];
    const float* bproj = (const float*)d_in[4];
    float* out = (float*)d_out;

    float *qkv, *attn, *Apart, *Amat, *WqkvT, *WprojT, *xr;
    cudaGetSymbolAddress((void**)&qkv,    g_qkv);
    cudaGetSymbolAddress((void**)&attn,   g_attn);
    cudaGetSymbolAddress((void**)&Apart,  g_Apart);
    cudaGetSymbolAddress((void**)&Amat,   g_A);
    cudaGetSymbolAddress((void**)&WqkvT,  g_WqkvT);
    cudaGetSymbolAddress((void**)&WprojT, g_WprojT);
    cudaGetSymbolAddress((void**)&xr,     g_xr);

    cudaFuncSetAttribute(gemm_tc, cudaFuncAttributeMaxDynamicSharedMemorySize, SMEM_DYN_G);

    /* 0) pre-round GEMM inputs to tf32 grid */
    {
        dim3 blk(32, 8);
        transpose_kernel<<<dim3(QKVN / 32, DIMM / 32), blk>>>(Wqkv, WqkvT, DIMM, QKVN);
        transpose_kernel<<<dim3(DIMM / 32, DIMM / 32), blk>>>(Wproj, WprojT, DIMM, DIMM);
        round_copy_kernel<<<(size_t)BSR * DIMM / (256 * 4), 256>>>(x, xr);
    }
    /* 1) qkv = x @ Wqkv + bqkv  (tf32 mma.sync + ldmatrix) */
    gemm_tc<<<dim3(QKVN / 128, BSR / 128), 256, SMEM_DYN_G>>>(xr, WqkvT, bqkv, qkv, QKVN);
    /* 2) softmaxes (in place) */
    q_softmax_kernel<<<BB * (DIMM / 32), 1024>>>(qkv);
    k_softmax_kernel<<<(BSR * HH) / 8, 256>>>(qkv);
    /* 3) A = K^T Q per (b,h) */
    ktq_kernel<<<BB * HH * TSPLIT, 256>>>(qkv, Apart);
    a_reduce_kernel<<<(BB * HH * HDD * HDD) / 256, 256>>>(Apart, Amat);
    /* 4) attn = V @ A per (b,h), attn pre-rounded */
    vA_kernel<<<BB * HH * (SS / 64), 256>>>(qkv, Amat, attn);
    /* 5) out = attn @ Wproj + bproj  (tf32 mma.sync + ldmatrix) */
    gemm_tc<<<dim3(DIMM / 128, BSR / 128), 256, SMEM_DYN_G>>>(attn, WprojT, bproj, out, DIMM);
}

// round 7
// speedup vs baseline: 1.1800x; 1.0576x over previous
#include <cuda_runtime.h>
#include <cstdint>
#include <math.h>

#define BB   8
#define SS   4096
#define DIMM 1024
#define HH   16
#define HDD  64
#define BSR  (BB * SS)          /* 32768 rows */
#define QKVN (3 * DIMM)         /* 3072 */
#define TSPLIT 32
#define SCALE_F 0.125f          /* 64^-0.5 */
#define KDIM 1024               /* K of both big GEMMs */

/* -------- scratch (device globals: allocation-free rule) -------- */
__device__ float g_qkv[(size_t)BSR * QKVN];                       /* 402 MB */
__device__ float g_attn[(size_t)BSR * DIMM];                      /* 134 MB */
__device__ float g_Apart[(size_t)TSPLIT * BB * HH * HDD * HDD];   /* 67 MB  */
__device__ float g_A[(size_t)BB * HH * HDD * HDD];                /* 2 MB   */
__device__ float g_WqkvT[(size_t)QKVN * DIMM];                    /* 12 MB  */
__device__ float g_WprojT[(size_t)DIMM * DIMM];                   /* 4 MB   */
__device__ float g_xr[(size_t)BSR * DIMM];                        /* 134 MB */

__device__ __forceinline__ uint32_t f2tf32(float x) {
    uint32_t r;
    asm("cvt.rna.tf32.f32 %0, %1;" : "=r"(r) : "f"(x));
    return r;
}
__device__ __forceinline__ float roundtf(float x) {
    return __uint_as_float(f2tf32(x));
}

/* ========== tf32 mma.sync GEMM, ldmatrix fragments, 3-stage ring ==========
 * Inputs pre-rounded to tf32 grid; hot loop = LDSM + HMMA only.
 * Cutlass-style multistage: issue c+2 -> MMA c -> wait_group 1 -> sync. */

#define BKK   32
#define ASTR  36                      /* padded row stride in floats */
#define STG_F (128 * ASTR)            /* floats per matrix per stage (4608) */
#define STG_BYTES (2 * STG_F * 4)     /* A+B per stage = 36864 B */
#define NSTG  3
#define SMEM_DYN_G (NSTG * STG_BYTES) /* 110592 B */
#define NCH   (KDIM / BKK)            /* 32 */

__device__ __forceinline__ uint32_t smem_u32(const void* p) {
    uint32_t a;
    asm("{ .reg .u64 t; cvta.to.shared.u64 t, %1; cvt.u32.u64 %0, t; }"
        : "=r"(a) : "l"(p));
    return a;
}
__device__ __forceinline__ void cp16(uint32_t dst, const void* src) {
    asm volatile("cp.async.cg.shared.global [%0], [%1], 16;"
                 :: "r"(dst), "l"(src) : "memory");
}
__device__ __forceinline__ void ldsm4(uint32_t* r, uint32_t addr) {
    asm volatile("ldmatrix.sync.aligned.m8n8.x4.shared.b16 {%0,%1,%2,%3}, [%4];"
                 : "=r"(r[0]), "=r"(r[1]), "=r"(r[2]), "=r"(r[3]) : "r"(addr));
}
__device__ __forceinline__ void mma_tf32(float* c, const uint32_t* a, const uint32_t* b) {
    asm volatile("mma.sync.aligned.m16n8k8.row.col.f32.tf32.tf32.f32 "
                 "{%0,%1,%2,%3}, {%4,%5,%6,%7}, {%8,%9}, {%0,%1,%2,%3};"
                 : "+f"(c[0]), "+f"(c[1]), "+f"(c[2]), "+f"(c[3])
                 : "r"(a[0]), "r"(a[1]), "r"(a[2]), "r"(a[3]),
                   "r"(b[0]), "r"(b[1]));
}

__global__ void __launch_bounds__(256, 2)
gemm_tc(const float* __restrict__ A, const float* __restrict__ BT,
        const float* __restrict__ bias, float* __restrict__ C, int N)
{
    extern __shared__ __align__(16) float sm[];
    const uint32_t u0 = smem_u32(sm);

    const int tid  = threadIdx.x;
    const int lane = tid & 31;
    const int warp = tid >> 5;
    const int wm   = warp & 1;          /* warp row: 0..1 */
    const int wn   = warp >> 1;         /* warp col: 0..3 */
    const int g    = lane >> 2;         /* group 0..7 */
    const int tig  = lane & 3;          /* 0..3 */

    const int arow = tid >> 1;          /* 0..127 */
    const int seg  = (tid & 1) * 16;
    const float* Ag = A  + (size_t)(blockIdx.y * 128 + arow) * KDIM + seg;
    const float* Bg = BT + (size_t)(blockIdx.x * 128 + arow) * KDIM + seg;
    /* stage-0 destinations; add stage*STG_BYTES for others */
    const uint32_t dstA = u0 + (uint32_t)(arow * ASTR + seg) * 4;
    const uint32_t dstB = dstA + (uint32_t)(STG_F * 4);

    const int rb = wm * 64;
    const int cb = wn * 32;

    /* ldmatrix per-lane base byte offsets within a stage */
    uint32_t aoff[4];
#pragma unroll
    for (int mf = 0; mf < 4; mf++)
        aoff[mf] = (uint32_t)(((rb + mf * 16 + (lane & 15)) * ASTR
                               + 4 * (lane >> 4)) * 4);
    uint32_t boff[2];
#pragma unroll
    for (int p = 0; p < 2; p++)
        boff[p] = (uint32_t)(STG_F * 4)
                + (uint32_t)(((cb + p * 16 + ((lane >> 4) << 3) + (lane & 7)) * ASTR
                              + 4 * ((lane >> 3) & 1)) * 4);

    float acc[4][4][4];
#pragma unroll
    for (int i = 0; i < 4; i++)
#pragma unroll
        for (int j = 0; j < 4; j++)
#pragma unroll
            for (int r = 0; r < 4; r++) acc[i][j][r] = 0.f;

    /* prologue: chunks 0 and 1 into stages 0 and 1 */
#pragma unroll
    for (int s = 0; s < 2; s++) {
        const uint32_t sb = (uint32_t)(s * STG_BYTES);
        const int k0 = s * BKK;
#pragma unroll
        for (int i = 0; i < 4; i++) {
            cp16(dstA + sb + i * 16, Ag + k0 + i * 4);
            cp16(dstB + sb + i * 16, Bg + k0 + i * 4);
        }
        asm volatile("cp.async.commit_group;" ::: "memory");
    }
    asm volatile("cp.async.wait_group 1;" ::: "memory");
    __syncthreads();

    for (int c = 0; c < NCH; c++) {
        /* issue loads for chunk c+2 into stage (c+2)%3 (== stage holding
         * chunk c-1, fully consumed before last iteration's barrier) */
        if (c + 2 < NCH) {
            const uint32_t sb = (uint32_t)(((c + 2) % NSTG) * STG_BYTES);
            const int k0 = (c + 2) * BKK;
#pragma unroll
            for (int i = 0; i < 4; i++) {
                cp16(dstA + sb + i * 16, Ag + k0 + i * 4);
                cp16(dstB + sb + i * 16, Bg + k0 + i * 4);
            }
            asm volatile("cp.async.commit_group;" ::: "memory");
        }

        /* MMA on chunk c */
        const uint32_t st = u0 + (uint32_t)((c % NSTG) * STG_BYTES);
#pragma unroll
        for (int ks = 0; ks < 4; ks++) {
            uint32_t av[4][4], bv[2][4];
#pragma unroll
            for (int mf = 0; mf < 4; mf++)
                ldsm4(av[mf], st + aoff[mf] + ks * 32);
#pragma unroll
            for (int p = 0; p < 2; p++)
                ldsm4(bv[p], st + boff[p] + ks * 32);
#pragma unroll
            for (int mf = 0; mf < 4; mf++)
#pragma unroll
                for (int nf = 0; nf < 4; nf++)
                    mma_tf32(acc[mf][nf], av[mf], &bv[nf >> 1][(nf & 1) * 2]);
        }

        /* ensure chunk c+1 landed (pending <= 1), then barrier */
        if (c + 2 < NCH)
            asm volatile("cp.async.wait_group 1;" ::: "memory");
        else
            asm volatile("cp.async.wait_group 0;" ::: "memory");
        __syncthreads();
    }

    const int row0 = blockIdx.y * 128 + rb + g;
    const int col0 = blockIdx.x * 128 + cb + tig * 2;
#pragma unroll
    for (int nf = 0; nf < 4; nf++) {
        const int col = col0 + nf * 8;
        const float b0 = bias[col], b1 = bias[col + 1];
#pragma unroll
        for (int mf = 0; mf < 4; mf++) {
            const int r = row0 + mf * 16;
            float2 v0 = make_float2(acc[mf][nf][0] + b0, acc[mf][nf][1] + b1);
            float2 v1 = make_float2(acc[mf][nf][2] + b0, acc[mf][nf][3] + b1);
            *(float2*)(C + (size_t)r * N + col)       = v0;
            *(float2*)(C + (size_t)(r + 8) * N + col) = v1;
        }
    }
}

/* ---- weight transpose + tf32 round: D[c][r] = round(S[r][c]) ---- */
__global__ void transpose_kernel(const float* __restrict__ S, float* __restrict__ D,
                                 int R, int Cc)
{
    __shared__ float t[32][33];
    const int bx = blockIdx.x * 32, by = blockIdx.y * 32;
    const int x = threadIdx.x, y = threadIdx.y;   /* 32 x 8 */
#pragma unroll
    for (int j = 0; j < 32; j += 8)
        t[y + j][x] = S[(size_t)(by + y + j) * Cc + bx + x];
    __syncthreads();
#pragma unroll
    for (int j = 0; j < 32; j += 8)
        D[(size_t)(bx + y + j) * R + by + x] = roundtf(t[x][y + j]);
}

/* ---- x -> tf32-rounded copy ---- */
__global__ void round_copy_kernel(const float* __restrict__ S, float* __restrict__ D)
{
    const size_t i = ((size_t)blockIdx.x * 256 + threadIdx.x) * 4;
    float4 v = *(const float4*)(S + i);
    v.x = roundtf(v.x); v.y = roundtf(v.y);
    v.z = roundtf(v.z); v.w = roundtf(v.w);
    *(float4*)(D + i) = v;
}

/* ---------------- softmaxes & small GEMMs ---------------- */

/* 2-pass (no max subtraction — post-GEMM logits are O(10), exp is safe).
 * grid BB*(DIMM/32), block 1024 = 32 cols x 32 row-lanes */
__global__ void q_softmax_kernel(float* __restrict__ qkv)
{
    const int b       = blockIdx.x / (DIMM / 32);
    const int colbase = (blockIdx.x % (DIMM / 32)) * 32;
    const int c = threadIdx.x & 31;
    const int r = threadIdx.x >> 5;   /* 0..31 */
    const int stride = QKVN;
    float* base = qkv + (size_t)b * SS * stride + colbase + c;

    __shared__ float red[32][33];

    float sum = 0.f;
    for (int s = r; s < SS; s += 32)
        sum += __expf(base[(size_t)s * stride]);
    red[r][c] = sum;
    __syncthreads();
    if (r == 0) {
        float t = 0.f;
#pragma unroll
        for (int i = 0; i < 32; i++) t += red[i][c];
        red[0][c] = t;
    }
    __syncthreads();
    const float inv = SCALE_F / red[0][c];

    for (int s = r; s < SS; s += 32) {
        size_t off = (size_t)s * stride;
        base[off] = __expf(base[off]) * inv;
    }
}

/* no-max k softmax: 64 contiguous floats per (b,s,h) row */
__global__ void k_softmax_kernel(float* __restrict__ qkv)
{
    const int row  = blockIdx.x * 8 + (threadIdx.x >> 5);
    const int lane = threadIdx.x & 31;
    float* p = qkv + (size_t)(row / HH) * QKVN + DIMM + (row % HH) * HDD;

    float e0 = __expf(p[lane]), e1 = __expf(p[lane + 32]);
    float s = e0 + e1;
#pragma unroll
    for (int o = 16; o > 0; o >>= 1)
        s += __shfl_xor_sync(0xFFFFFFFFu, s, o);
    float inv = 1.f / s;
    p[lane]      = e0 * inv;
    p[lane + 32] = e1 * inv;
}

__global__ void ktq_kernel(const float* __restrict__ qkv, float* __restrict__ Apart)
{
    const int bh = blockIdx.x / TSPLIT;
    const int ts = blockIdx.x % TSPLIT;
    const int b = bh / HH, h = bh % HH;
    const int TCHUNK = SS / TSPLIT;

    __shared__ __align__(16) float ks[32][64];
    __shared__ __align__(16) float qs[32][64];

    const int tid = threadIdx.x;
    const int tc = tid & 15;
    const int tr = tid >> 4;
    const int lr = tid >> 3;
    const int lc = tid & 7;

    float acc[4][4];
#pragma unroll
    for (int i = 0; i < 4; i++)
#pragma unroll
        for (int j = 0; j < 4; j++) acc[i][j] = 0.f;

    const float* base = qkv + ((size_t)b * SS + (size_t)ts * TCHUNK) * QKVN;

    for (int t0 = 0; t0 < TCHUNK; t0 += 32) {
        const float* qrow = base + (size_t)(t0 + lr) * QKVN + h * HDD;
        const float* krow = qrow + DIMM;
        *(float4*)&qs[lr][lc * 4]      = *(const float4*)(qrow + lc * 4);
        *(float4*)&qs[lr][lc * 4 + 32] = *(const float4*)(qrow + lc * 4 + 32);
        *(float4*)&ks[lr][lc * 4]      = *(const float4*)(krow + lc * 4);
        *(float4*)&ks[lr][lc * 4 + 32] = *(const float4*)(krow + lc * 4 + 32);
        __syncthreads();
#pragma unroll
        for (int kk = 0; kk < 32; kk++) {
            float kr[4], qr[4];
            *(float4*)kr = *(const float4*)&ks[kk][tr * 4];
            *(float4*)qr = *(const float4*)&qs[kk][tc * 4];
#pragma unroll
            for (int i = 0; i < 4; i++)
#pragma unroll
                for (int j = 0; j < 4; j++)
                    acc[i][j] += kr[i] * qr[j];
        }
        __syncthreads();
    }

    float* outp = Apart + ((size_t)ts * BB * HH + bh) * HDD * HDD;
#pragma unroll
    for (int i = 0; i < 4; i++) {
        float4 v = make_float4(acc[i][0], acc[i][1], acc[i][2], acc[i][3]);
        *(float4*)&outp[(tr * 4 + i) * HDD + tc * 4] = v;
    }
}

__global__ void a_reduce_kernel(const float* __restrict__ Apart, float* __restrict__ A)
{
    const int idx = blockIdx.x * 256 + threadIdx.x;
    const size_t stride = (size_t)BB * HH * HDD * HDD;
    float s = 0.f;
#pragma unroll
    for (int p = 0; p < TSPLIT; p++)
        s += Apart[(size_t)p * stride + idx];
    A[idx] = s;
}

/* vA: writes attn PRE-ROUNDED to tf32 grid (attn is only GEMM2 input) */
__global__ void vA_kernel(const float* __restrict__ qkv, const float* __restrict__ Amat,
                          float* __restrict__ outp)
{
    const int stile = blockIdx.x % (SS / 64);
    const int bh    = blockIdx.x / (SS / 64);
    const int b = bh / HH, h = bh % HH;

    __shared__ __align__(16) float Am[64][64];
    __shared__ __align__(16) float vs[64][68];

    const int tid = threadIdx.x;
    const int tc = tid & 15;
    const int tr = tid >> 4;

    {
        const float4* Ab = (const float4*)(Amat + (size_t)bh * HDD * HDD);
        float4* Ad = (float4*)&Am[0][0];
#pragma unroll
        for (int i = 0; i < 4; i++) Ad[tid + i * 256] = Ab[tid + i * 256];
    }
    {
        const int lr = tid >> 2;
        const int lc = tid & 3;
        const float* vrow = qkv + ((size_t)b * SS + (size_t)stile * 64 + lr) * QKVN
                            + 2 * DIMM + h * HDD;
#pragma unroll
        for (int m = 0; m < 4; m++)
            *(float4*)&vs[lr][(lc + 4 * m) * 4] = *(const float4*)(vrow + (lc + 4 * m) * 4);
    }
    __syncthreads();

    float acc[4][4];
#pragma unroll
    for (int i = 0; i < 4; i++)
#pragma unroll
        for (int j = 0; j < 4; j++) acc[i][j] = 0.f;

#pragma unroll 8
    for (int d = 0; d < 64; d++) {
        float br[4];
        *(float4*)br = *(const float4*)&Am[d][tc * 4];
        float vr[4];
#pragma unroll
        for (int i = 0; i < 4; i++) vr[i] = vs[tr * 4 + i][d];
#pragma unroll
        for (int i = 0; i < 4; i++)
#pragma unroll
            for (int j = 0; j < 4; j++)
                acc[i][j] += vr[i] * br[j];
    }

#pragma unroll
    for (int i = 0; i < 4; i++) {
        size_t row = (size_t)b * SS + (size_t)stile * 64 + tr * 4 + i;
        float4 v = make_float4(roundtf(acc[i][0]), roundtf(acc[i][1]),
                               roundtf(acc[i][2]), roundtf(acc[i][3]));
        *(float4*)(outp + row * DIMM + h * HDD + tc * 4) = v;
    }
}

/* --------------------------------------------------------------- */
extern "C" void kernel_launch(void* const* d_in, const int* in_sizes, int n_in,
                              void* d_out, int out_size)
{
    (void)in_sizes; (void)n_in; (void)out_size;
    const float* x     = (const float*)d_in[0];
    const float* Wqkv  = (const float*)d_in[1];
    const float* bqkv  = (const float*)d_in[2];
    const float* Wproj = (const float*)d_in[3];
    const float* bproj = (const float*)d_in[4];
    float* out = (float*)d_out;

    float *qkv, *attn, *Apart, *Amat, *WqkvT, *WprojT, *xr;
    cudaGetSymbolAddress((void**)&qkv,    g_qkv);
    cudaGetSymbolAddress((void**)&attn,   g_attn);
    cudaGetSymbolAddress((void**)&Apart,  g_Apart);
    cudaGetSymbolAddress((void**)&Amat,   g_A);
    cudaGetSymbolAddress((void**)&WqkvT,  g_WqkvT);
    cudaGetSymbolAddress((void**)&WprojT, g_WprojT);
    cudaGetSymbolAddress((void**)&xr,     g_xr);

    cudaFuncSetAttribute(gemm_tc, cudaFuncAttributeMaxDynamicSharedMemorySize, SMEM_DYN_G);

    /* 0) pre-round GEMM inputs to tf32 grid */
    {
        dim3 blk(32, 8);
        transpose_kernel<<<dim3(QKVN / 32, DIMM / 32), blk>>>(Wqkv, WqkvT, DIMM, QKVN);
        transpose_kernel<<<dim3(DIMM / 32, DIMM / 32), blk>>>(Wproj, WprojT, DIMM, DIMM);
        round_copy_kernel<<<(size_t)BSR * DIMM / (256 * 4), 256>>>(x, xr);
    }
    /* 1) qkv = x @ Wqkv + bqkv  (tf32 mma.sync + ldmatrix, 3-stage) */
    gemm_tc<<<dim3(QKVN / 128, BSR / 128), 256, SMEM_DYN_G>>>(xr, WqkvT, bqkv, qkv, QKVN);
    /* 2) softmaxes (in place) */
    q_softmax_kernel<<<BB * (DIMM / 32), 1024>>>(qkv);
    k_softmax_kernel<<<(BSR * HH) / 8, 256>>>(qkv);
    /* 3) A = K^T Q per (b,h) */
    ktq_kernel<<<BB * HH * TSPLIT, 256>>>(qkv, Apart);
    a_reduce_kernel<<<(BB * HH * HDD * HDD) / 256, 256>>>(Apart, Amat);
    /* 4) attn = V @ A per (b,h), attn pre-rounded */
    vA_kernel<<<BB * HH * (SS / 64), 256>>>(qkv, Amat, attn);
    /* 5) out = attn @ Wproj + bproj  (tf32 mma.sync + ldmatrix, 3-stage) */
    gemm_tc<<<dim3(DIMM / 128, BSR / 128), 256, SMEM_DYN_G>>>(attn, WprojT, bproj, out, DIMM);
}

// round 8
// speedup vs baseline: 1.2099x; 1.0253x over previous
#include <cuda_runtime.h>
#include <cstdint>
#include <math.h>

#define BB   8
#define SS   4096
#define DIMM 1024
#define HH   16
#define HDD  64
#define BSR  (BB * SS)          /* 32768 rows */
#define QKVN (3 * DIMM)         /* 3072 */
#define TSPLIT 32
#define SCALE_F 0.125f          /* 64^-0.5 */
#define KDIM 1024               /* K of both big GEMMs */

/* -------- scratch (device globals: allocation-free rule) -------- */
__device__ float g_qkv[(size_t)BSR * QKVN];                       /* 402 MB */
__device__ float g_btilde[(size_t)BB * DIMM * DIMM];              /* 32 MB  */
__device__ float g_Apart[(size_t)TSPLIT * BB * HH * HDD * HDD];   /* 67 MB  */
__device__ float g_A[(size_t)BB * HH * HDD * HDD];                /* 2 MB   */
__device__ float g_WqkvT[(size_t)QKVN * DIMM];                    /* 12 MB  */
__device__ float g_WprojT[(size_t)DIMM * DIMM];                   /* 4 MB   */
__device__ float g_xr[(size_t)BSR * DIMM];                        /* 134 MB */

__device__ __forceinline__ uint32_t f2tf32(float x) {
    uint32_t r;
    asm("cvt.rna.tf32.f32 %0, %1;" : "=r"(r) : "f"(x));
    return r;
}
__device__ __forceinline__ float roundtf(float x) {
    return __uint_as_float(f2tf32(x));
}

/* ========== tf32 mma.sync GEMM, ldmatrix fragments, 3-stage ring ==========
 * A-rows strided by astr (lets GEMM2 read V straight out of qkv).
 * BT gets a per-batch offset (blockIdx.y>>5)*bstride (B~ per batch).
 * Output cols >= round_from are tf32-rounded in the epilogue. */

#define BKK   32
#define ASTR  36                      /* padded row stride in floats */
#define STG_F (128 * ASTR)            /* floats per matrix per stage (4608) */
#define STG_BYTES (2 * STG_F * 4)     /* A+B per stage = 36864 B */
#define NSTG  3
#define SMEM_DYN_G (NSTG * STG_BYTES) /* 110592 B */
#define NCH   (KDIM / BKK)            /* 32 */

__device__ __forceinline__ uint32_t smem_u32(const void* p) {
    uint32_t a;
    asm("{ .reg .u64 t; cvta.to.shared.u64 t, %1; cvt.u32.u64 %0, t; }"
        : "=r"(a) : "l"(p));
    return a;
}
__device__ __forceinline__ void cp16(uint32_t dst, const void* src) {
    asm volatile("cp.async.cg.shared.global [%0], [%1], 16;"
                 :: "r"(dst), "l"(src) : "memory");
}
__device__ __forceinline__ void ldsm4(uint32_t* r, uint32_t addr) {
    asm volatile("ldmatrix.sync.aligned.m8n8.x4.shared.b16 {%0,%1,%2,%3}, [%4];"
                 : "=r"(r[0]), "=r"(r[1]), "=r"(r[2]), "=r"(r[3]) : "r"(addr));
}
__device__ __forceinline__ void mma_tf32(float* c, const uint32_t* a, const uint32_t* b) {
    asm volatile("mma.sync.aligned.m16n8k8.row.col.f32.tf32.tf32.f32 "
                 "{%0,%1,%2,%3}, {%4,%5,%6,%7}, {%8,%9}, {%0,%1,%2,%3};"
                 : "+f"(c[0]), "+f"(c[1]), "+f"(c[2]), "+f"(c[3])
                 : "r"(a[0]), "r"(a[1]), "r"(a[2]), "r"(a[3]),
                   "r"(b[0]), "r"(b[1]));
}

__global__ void __launch_bounds__(256, 2)
gemm_tc(const float* __restrict__ A, int astr,
        const float* __restrict__ BT, int bstride,
        const float* __restrict__ bias, float* __restrict__ C, int N,
        int round_from)
{
    extern __shared__ __align__(16) float sm[];
    const uint32_t u0 = smem_u32(sm);

    const int tid  = threadIdx.x;
    const int lane = tid & 31;
    const int warp = tid >> 5;
    const int wm   = warp & 1;          /* warp row: 0..1 */
    const int wn   = warp >> 1;         /* warp col: 0..3 */
    const int g    = lane >> 2;         /* group 0..7 */
    const int tig  = lane & 3;          /* 0..3 */

    const int arow = tid >> 1;          /* 0..127 */
    const int seg  = (tid & 1) * 16;
    const float* Ag = A + (size_t)(blockIdx.y * 128 + arow) * astr + seg;
    const float* Bg = BT + (size_t)(blockIdx.y >> 5) * (size_t)bstride
                         + (size_t)(blockIdx.x * 128 + arow) * KDIM + seg;
    /* stage-0 destinations; add stage*STG_BYTES for others */
    const uint32_t dstA = u0 + (uint32_t)(arow * ASTR + seg) * 4;
    const uint32_t dstB = dstA + (uint32_t)(STG_F * 4);

    const int rb = wm * 64;
    const int cb = wn * 32;

    /* ldmatrix per-lane base byte offsets within a stage */
    uint32_t aoff[4];
#pragma unroll
    for (int mf = 0; mf < 4; mf++)
        aoff[mf] = (uint32_t)(((rb + mf * 16 + (lane & 15)) * ASTR
                               + 4 * (lane >> 4)) * 4);
    uint32_t boff[2];
#pragma unroll
    for (int p = 0; p < 2; p++)
        boff[p] = (uint32_t)(STG_F * 4)
                + (uint32_t)(((cb + p * 16 + ((lane >> 4) << 3) + (lane & 7)) * ASTR
                              + 4 * ((lane >> 3) & 1)) * 4);

    float acc[4][4][4];
#pragma unroll
    for (int i = 0; i < 4; i++)
#pragma unroll
        for (int j = 0; j < 4; j++)
#pragma unroll
            for (int r = 0; r < 4; r++) acc[i][j][r] = 0.f;

    /* prologue: chunks 0 and 1 into stages 0 and 1 */
#pragma unroll
    for (int s = 0; s < 2; s++) {
        const uint32_t sb = (uint32_t)(s * STG_BYTES);
        const int k0 = s * BKK;
#pragma unroll
        for (int i = 0; i < 4; i++) {
            cp16(dstA + sb + i * 16, Ag + k0 + i * 4);
            cp16(dstB + sb + i * 16, Bg + k0 + i * 4);
        }
        asm volatile("cp.async.commit_group;" ::: "memory");
    }
    asm volatile("cp.async.wait_group 1;" ::: "memory");
    __syncthreads();

    for (int c = 0; c < NCH; c++) {
        if (c + 2 < NCH) {
            const uint32_t sb = (uint32_t)(((c + 2) % NSTG) * STG_BYTES);
            const int k0 = (c + 2) * BKK;
#pragma unroll
            for (int i = 0; i < 4; i++) {
                cp16(dstA + sb + i * 16, Ag + k0 + i * 4);
                cp16(dstB + sb + i * 16, Bg + k0 + i * 4);
            }
            asm volatile("cp.async.commit_group;" ::: "memory");
        }

        const uint32_t st = u0 + (uint32_t)((c % NSTG) * STG_BYTES);
#pragma unroll
        for (int ks = 0; ks < 4; ks++) {
            uint32_t av[4][4], bv[2][4];
#pragma unroll
            for (int mf = 0; mf < 4; mf++)
                ldsm4(av[mf], st + aoff[mf] + ks * 32);
#pragma unroll
            for (int p = 0; p < 2; p++)
                ldsm4(bv[p], st + boff[p] + ks * 32);
#pragma unroll
            for (int mf = 0; mf < 4; mf++)
#pragma unroll
                for (int nf = 0; nf < 4; nf++)
                    mma_tf32(acc[mf][nf], av[mf], &bv[nf >> 1][(nf & 1) * 2]);
        }

        if (c + 2 < NCH)
            asm volatile("cp.async.wait_group 1;" ::: "memory");
        else
            asm volatile("cp.async.wait_group 0;" ::: "memory");
        __syncthreads();
    }

    const int row0 = blockIdx.y * 128 + rb + g;
    const int col0 = blockIdx.x * 128 + cb + tig * 2;
#pragma unroll
    for (int nf = 0; nf < 4; nf++) {
        const int col = col0 + nf * 8;
        const float b0 = bias[col], b1 = bias[col + 1];
        const bool rnd = (col >= round_from);
#pragma unroll
        for (int mf = 0; mf < 4; mf++) {
            const int r = row0 + mf * 16;
            float2 v0 = make_float2(acc[mf][nf][0] + b0, acc[mf][nf][1] + b1);
            float2 v1 = make_float2(acc[mf][nf][2] + b0, acc[mf][nf][3] + b1);
            if (rnd) {
                v0.x = roundtf(v0.x); v0.y = roundtf(v0.y);
                v1.x = roundtf(v1.x); v1.y = roundtf(v1.y);
            }
            *(float2*)(C + (size_t)r * N + col)       = v0;
            *(float2*)(C + (size_t)(r + 8) * N + col) = v1;
        }
    }
}

/* ---- weight transpose + tf32 round: D[c][r] = round(S[r][c]) ---- */
__global__ void transpose_kernel(const float* __restrict__ S, float* __restrict__ D,
                                 int R, int Cc)
{
    __shared__ float t[32][33];
    const int bx = blockIdx.x * 32, by = blockIdx.y * 32;
    const int x = threadIdx.x, y = threadIdx.y;   /* 32 x 8 */
#pragma unroll
    for (int j = 0; j < 32; j += 8)
        t[y + j][x] = S[(size_t)(by + y + j) * Cc + bx + x];
    __syncthreads();
#pragma unroll
    for (int j = 0; j < 32; j += 8)
        D[(size_t)(bx + y + j) * R + by + x] = roundtf(t[x][y + j]);
}

/* ---- x -> tf32-rounded copy ---- */
__global__ void round_copy_kernel(const float* __restrict__ S, float* __restrict__ D)
{
    const size_t i = ((size_t)blockIdx.x * 256 + threadIdx.x) * 4;
    float4 v = *(const float4*)(S + i);
    v.x = roundtf(v.x); v.y = roundtf(v.y);
    v.z = roundtf(v.z); v.w = roundtf(v.w);
    *(float4*)(D + i) = v;
}

/* ---------------- softmaxes & small kernels ---------------- */

/* 2-pass no-max q softmax; grid BB*(DIMM/32), block 1024 */
__global__ void q_softmax_kernel(float* __restrict__ qkv)
{
    const int b       = blockIdx.x / (DIMM / 32);
    const int colbase = (blockIdx.x % (DIMM / 32)) * 32;
    const int c = threadIdx.x & 31;
    const int r = threadIdx.x >> 5;   /* 0..31 */
    const int stride = QKVN;
    float* base = qkv + (size_t)b * SS * stride + colbase + c;

    __shared__ float red[32][33];

    float sum = 0.f;
    for (int s = r; s < SS; s += 32)
        sum += __expf(base[(size_t)s * stride]);
    red[r][c] = sum;
    __syncthreads();
    if (r == 0) {
        float t = 0.f;
#pragma unroll
        for (int i = 0; i < 32; i++) t += red[i][c];
        red[0][c] = t;
    }
    __syncthreads();
    const float inv = SCALE_F / red[0][c];

    for (int s = r; s < SS; s += 32) {
        size_t off = (size_t)s * stride;
        base[off] = __expf(base[off]) * inv;
    }
}

/* no-max k softmax: 64 contiguous floats per (b,s,h) row */
__global__ void k_softmax_kernel(float* __restrict__ qkv)
{
    const int row  = blockIdx.x * 8 + (threadIdx.x >> 5);
    const int lane = threadIdx.x & 31;
    float* p = qkv + (size_t)(row / HH) * QKVN + DIMM + (row % HH) * HDD;

    float e0 = __expf(p[lane]), e1 = __expf(p[lane + 32]);
    float s = e0 + e1;
#pragma unroll
    for (int o = 16; o > 0; o >>= 1)
        s += __shfl_xor_sync(0xFFFFFFFFu, s, o);
    float inv = 1.f / s;
    p[lane]      = e0 * inv;
    p[lane + 32] = e1 * inv;
}

__global__ void ktq_kernel(const float* __restrict__ qkv, float* __restrict__ Apart)
{
    const int bh = blockIdx.x / TSPLIT;
    const int ts = blockIdx.x % TSPLIT;
    const int b = bh / HH, h = bh % HH;
    const int TCHUNK = SS / TSPLIT;

    __shared__ __align__(16) float ks[32][64];
    __shared__ __align__(16) float qs[32][64];

    const int tid = threadIdx.x;
    const int tc = tid & 15;
    const int tr = tid >> 4;
    const int lr = tid >> 3;
    const int lc = tid & 7;

    float acc[4][4];
#pragma unroll
    for (int i = 0; i < 4; i++)
#pragma unroll
        for (int j = 0; j < 4; j++) acc[i][j] = 0.f;

    const float* base = qkv + ((size_t)b * SS + (size_t)ts * TCHUNK) * QKVN;

    for (int t0 = 0; t0 < TCHUNK; t0 += 32) {
        const float* qrow = base + (size_t)(t0 + lr) * QKVN + h * HDD;
        const float* krow = qrow + DIMM;
        *(float4*)&qs[lr][lc * 4]      = *(const float4*)(qrow + lc * 4);
        *(float4*)&qs[lr][lc * 4 + 32] = *(const float4*)(qrow + lc * 4 + 32);
        *(float4*)&ks[lr][lc * 4]      = *(const float4*)(krow + lc * 4);
        *(float4*)&ks[lr][lc * 4 + 32] = *(const float4*)(krow + lc * 4 + 32);
        __syncthreads();
#pragma unroll
        for (int kk = 0; kk < 32; kk++) {
            float kr[4], qr[4];
            *(float4*)kr = *(const float4*)&ks[kk][tr * 4];
            *(float4*)qr = *(const float4*)&qs[kk][tc * 4];
#pragma unroll
            for (int i = 0; i < 4; i++)
#pragma unroll
                for (int j = 0; j < 4; j++)
                    acc[i][j] += kr[i] * qr[j];
        }
        __syncthreads();
    }

    float* outp = Apart + ((size_t)ts * BB * HH + bh) * HDD * HDD;
#pragma unroll
    for (int i = 0; i < 4; i++) {
        float4 v = make_float4(acc[i][0], acc[i][1], acc[i][2], acc[i][3]);
        *(float4*)&outp[(tr * 4 + i) * HDD + tc * 4] = v;
    }
}

__global__ void a_reduce_kernel(const float* __restrict__ Apart, float* __restrict__ A)
{
    const int idx = blockIdx.x * 256 + threadIdx.x;
    const size_t stride = (size_t)BB * HH * HDD * HDD;
    float s = 0.f;
#pragma unroll
    for (int p = 0; p < TSPLIT; p++)
        s += Apart[(size_t)p * stride + idx];
    A[idx] = s;
}

/* ---- B~[b][j][h*64+d] = round(sum_e WprojT[j][h*64+e] * A[b,h,d,e]) ----
 * grid (16 j-tiles, 128 bh), block 256 (4x4 per thread), vA-style. */
__global__ void wA_kernel(const float* __restrict__ WprojT,
                          const float* __restrict__ Amat,
                          float* __restrict__ btilde)
{
    const int jt = blockIdx.x;         /* 0..15 */
    const int bh = blockIdx.y;         /* 0..127 */
    const int b = bh >> 4, h = bh & 15;

    __shared__ __align__(16) float Xsm[64][68];   /* X[e][d] = A[d][e] */
    __shared__ __align__(16) float Wsm[64][68];   /* W[local j][e]     */

    const int tid = threadIdx.x;
    const int tc = tid & 15;   /* d group */
    const int tr = tid >> 4;   /* j group */

    /* load A block transposed */
    {
        const float* Ab = Amat + (size_t)bh * (HDD * HDD);
#pragma unroll
        for (int i = 0; i < 16; i++) {
            int idx = i * 256 + tid;
            Xsm[idx & 63][idx >> 6] = Ab[idx];
        }
    }
    /* load W tile: rows j = jt*64 + lr, cols e = h*64.. */
    {
        const int lr = tid >> 2;
        const int lc = tid & 3;
        const float* wrow = WprojT + (size_t)(jt * 64 + lr) * KDIM + h * HDD;
#pragma unroll
        for (int m = 0; m < 4; m++)
            *(float4*)&Wsm[lr][(lc + 4 * m) * 4] = *(const float4*)(wrow + (lc + 4 * m) * 4);
    }
    __syncthreads();

    float acc[4][4];
#pragma unroll
    for (int i = 0; i < 4; i++)
#pragma unroll
        for (int j = 0; j < 4; j++) acc[i][j] = 0.f;

#pragma unroll 8
    for (int e = 0; e < 64; e++) {
        float br[4];
        *(float4*)br = *(const float4*)&Xsm[e][tc * 4];
        float wr[4];
#pragma unroll
        for (int i = 0; i < 4; i++) wr[i] = Wsm[tr * 4 + i][e];
#pragma unroll
        for (int i = 0; i < 4; i++)
#pragma unroll
            for (int j = 0; j < 4; j++)
                acc[i][j] += wr[i] * br[j];
    }

    /* store: row j = jt*64 + tr*4+i, col = h*64 + tc*4 .. +3 */
#pragma unroll
    for (int i = 0; i < 4; i++) {
        const size_t row = (size_t)b * DIMM + jt * 64 + tr * 4 + i;
        float4 v = make_float4(roundtf(acc[i][0]), roundtf(acc[i][1]),
                               roundtf(acc[i][2]), roundtf(acc[i][3]));
        *(float4*)(btilde + row * DIMM + h * HDD + tc * 4) = v;
    }
}

/* --------------------------------------------------------------- */
extern "C" void kernel_launch(void* const* d_in, const int* in_sizes, int n_in,
                              void* d_out, int out_size)
{
    (void)in_sizes; (void)n_in; (void)out_size;
    const float* x     = (const float*)d_in[0];
    const float* Wqkv  = (const float*)d_in[1];
    const float* bqkv  = (const float*)d_in[2];
    const float* Wproj = (const float*)d_in[3];
    const float* bproj = (const float*)d_in[4];
    float* out = (float*)d_out;

    float *qkv, *btilde, *Apart, *Amat, *WqkvT, *WprojT, *xr;
    cudaGetSymbolAddress((void**)&qkv,    g_qkv);
    cudaGetSymbolAddress((void**)&btilde, g_btilde);
    cudaGetSymbolAddress((void**)&Apart,  g_Apart);
    cudaGetSymbolAddress((void**)&Amat,   g_A);
    cudaGetSymbolAddress((void**)&WqkvT,  g_WqkvT);
    cudaGetSymbolAddress((void**)&WprojT, g_WprojT);
    cudaGetSymbolAddress((void**)&xr,     g_xr);

    cudaFuncSetAttribute(gemm_tc, cudaFuncAttributeMaxDynamicSharedMemorySize, SMEM_DYN_G);

    /* 0) pre-round GEMM inputs to tf32 grid */
    {
        dim3 blk(32, 8);
        transpose_kernel<<<dim3(QKVN / 32, DIMM / 32), blk>>>(Wqkv, WqkvT, DIMM, QKVN);
        transpose_kernel<<<dim3(DIMM / 32, DIMM / 32), blk>>>(Wproj, WprojT, DIMM, DIMM);
        round_copy_kernel<<<(size_t)BSR * DIMM / (256 * 4), 256>>>(x, xr);
    }
    /* 1) qkv = x @ Wqkv + bqkv ; V columns (>=2048) written tf32-rounded */
    gemm_tc<<<dim3(QKVN / 128, BSR / 128), 256, SMEM_DYN_G>>>(
        xr, KDIM, WqkvT, 0, bqkv, qkv, QKVN, 2 * DIMM);
    /* 2) softmaxes (in place on q, k) */
    q_softmax_kernel<<<BB * (DIMM / 32), 1024>>>(qkv);
    k_softmax_kernel<<<(BSR * HH) / 8, 256>>>(qkv);
    /* 3) A = K^T Q per (b,h) */
    ktq_kernel<<<BB * HH * TSPLIT, 256>>>(qkv, Apart);
    a_reduce_kernel<<<(BB * HH * HDD * HDD) / 256, 256>>>(Apart, Amat);
    /* 4) B~ = A (x) Wproj  (per-batch folded weights, tf32-rounded) */
    wA_kernel<<<dim3(16, BB * HH), 256>>>(WprojT, Amat, btilde);
    /* 5) out = V @ B~ + bproj  (V read strided from qkv; B~ per batch) */
    gemm_tc<<<dim3(DIMM / 128, BSR / 128), 256, SMEM_DYN_G>>>(
        qkv + 2 * DIMM, QKVN, btilde, DIMM * DIMM, bproj, out, DIMM, 1 << 30);
}

// round 9
// speedup vs baseline: 1.2624x; 1.0434x over previous
#include <cuda_runtime.h>
#include <cstdint>
#include <math.h>

#define BB   8
#define SS   4096
#define DIMM 1024
#define HH   16
#define HDD  64
#define BSR  (BB * SS)          /* 32768 rows */
#define QKVN (3 * DIMM)         /* 3072 */
#define TSPLIT 16
#define SCALE_F 0.125f          /* 64^-0.5 */
#define KDIM 1024               /* K of both big GEMMs */

/* -------- scratch (device globals: allocation-free rule) -------- */
__device__ float g_qkv[(size_t)BSR * QKVN];                       /* 402 MB */
__device__ float g_btilde[(size_t)BB * DIMM * DIMM];              /* 32 MB  */
__device__ float g_Apart[(size_t)TSPLIT * BB * HH * HDD * HDD];   /* 33 MB  */
__device__ float g_A[(size_t)BB * HH * HDD * HDD];                /* 2 MB   */
__device__ float g_WqkvT[(size_t)QKVN * DIMM];                    /* 12 MB  */
__device__ float g_WprojT[(size_t)DIMM * DIMM];                   /* 4 MB   */

__device__ __forceinline__ uint32_t f2tf32(float x) {
    uint32_t r;
    asm("cvt.rna.tf32.f32 %0, %1;" : "=r"(r) : "f"(x));
    return r;
}
__device__ __forceinline__ float roundtf(float x) {
    return __uint_as_float(f2tf32(x));
}

/* ===== tf32 mma.sync GEMM: 512 thr, tile 128x128, warp tile 32x32,
 * 6-stage cp.async ring, peeled tail, ldmatrix fragments.
 * RA=1: A operand is raw fp32, rounded to tf32 in-kernel (LDG+cvt+STS).
 * A-rows strided astr; BT per-batch offset (blockIdx.y>>5)*bstride;
 * output cols >= round_from tf32-rounded. ===== */

#define BKK   32
#define ASTR  36                      /* padded row stride in floats */
#define STG_F (128 * ASTR)            /* floats per matrix per stage */
#define STG_BYTES (2 * STG_F * 4)     /* A+B per stage = 36864 B */
#define NSTG  6
#define SMEM_DYN_G (NSTG * STG_BYTES) /* 221184 B */
#define NCH   (KDIM / BKK)            /* 32 */

__device__ __forceinline__ uint32_t smem_u32(const void* p) {
    uint32_t a;
    asm("{ .reg .u64 t; cvta.to.shared.u64 t, %1; cvt.u32.u64 %0, t; }"
        : "=r"(a) : "l"(p));
    return a;
}
__device__ __forceinline__ void cp16(uint32_t dst, const void* src) {
    asm volatile("cp.async.cg.shared.global [%0], [%1], 16;"
                 :: "r"(dst), "l"(src) : "memory");
}
__device__ __forceinline__ void sts16(uint32_t dst, float4 v) {
    asm volatile("st.shared.v4.b32 [%0], {%1,%2,%3,%4};"
                 :: "r"(dst), "f"(v.x), "f"(v.y), "f"(v.z), "f"(v.w) : "memory");
}
__device__ __forceinline__ void ldsm4(uint32_t* r, uint32_t addr) {
    asm volatile("ldmatrix.sync.aligned.m8n8.x4.shared.b16 {%0,%1,%2,%3}, [%4];"
                 : "=r"(r[0]), "=r"(r[1]), "=r"(r[2]), "=r"(r[3]) : "r"(addr));
}
__device__ __forceinline__ void mma_tf32(float* c, const uint32_t* a, const uint32_t* b) {
    asm volatile("mma.sync.aligned.m16n8k8.row.col.f32.tf32.tf32.f32 "
                 "{%0,%1,%2,%3}, {%4,%5,%6,%7}, {%8,%9}, {%0,%1,%2,%3};"
                 : "+f"(c[0]), "+f"(c[1]), "+f"(c[2]), "+f"(c[3])
                 : "r"(a[0]), "r"(a[1]), "r"(a[2]), "r"(a[3]),
                   "r"(b[0]), "r"(b[1]));
}
__device__ __forceinline__ float4 roundtf4(float4 v) {
    v.x = roundtf(v.x); v.y = roundtf(v.y);
    v.z = roundtf(v.z); v.w = roundtf(v.w);
    return v;
}

template<int RA>
__global__ void __launch_bounds__(512, 1)
gemm_tc(const float* __restrict__ A, int astr,
        const float* __restrict__ BT, int bstride,
        const float* __restrict__ bias, float* __restrict__ C, int N,
        int round_from)
{
    extern __shared__ __align__(16) float sm[];
    const uint32_t u0 = smem_u32(sm);

    const int tid  = threadIdx.x;
    const int lane = tid & 31;
    const int warp = tid >> 5;          /* 0..15 */
    const int wm   = warp & 3;          /* warp row: 0..3 */
    const int wn   = warp >> 2;         /* warp col: 0..3 */
    const int g    = lane >> 2;
    const int tig  = lane & 3;

    /* loader: 4 threads per 128B row, each 2x16B (slots q, q+4) */
    const int lrow = tid >> 2;          /* 0..127 */
    const int lq   = tid & 3;
    const float* Ag = A + (size_t)(blockIdx.y * 128 + lrow) * astr + lq * 4;
    const float* Bg = BT + (size_t)(blockIdx.y >> 5) * (size_t)bstride
                         + (size_t)(blockIdx.x * 128 + lrow) * KDIM + lq * 4;
    const uint32_t dstA = u0 + (uint32_t)(lrow * ASTR + lq * 4) * 4;
    const uint32_t dstB = dstA + (uint32_t)(STG_F * 4);

    const int rb = wm * 32;
    const int cb = wn * 32;

    uint32_t aoff[2];
#pragma unroll
    for (int mf = 0; mf < 2; mf++)
        aoff[mf] = (uint32_t)(((rb + mf * 16 + (lane & 15)) * ASTR
                               + 4 * (lane >> 4)) * 4);
    uint32_t boff[2];
#pragma unroll
    for (int p = 0; p < 2; p++)
        boff[p] = (uint32_t)(STG_F * 4)
                + (uint32_t)(((cb + p * 16 + ((lane >> 4) << 3) + (lane & 7)) * ASTR
                              + 4 * ((lane >> 3) & 1)) * 4);

    float acc[2][4][4];
#pragma unroll
    for (int i = 0; i < 2; i++)
#pragma unroll
        for (int j = 0; j < 4; j++)
#pragma unroll
            for (int r = 0; r < 4; r++) acc[i][j][r] = 0.f;

    /* prologue: chunks 0..4 into stages 0..4 */
#pragma unroll
    for (int s = 0; s < NSTG - 1; s++) {
        const uint32_t sb = (uint32_t)(s * STG_BYTES);
        const int k0 = s * BKK;
        if (RA) {
            float4 v0 = *(const float4*)(Ag + k0);
            float4 v1 = *(const float4*)(Ag + k0 + 16);
            sts16(dstA + sb, roundtf4(v0));
            sts16(dstA + sb + 64, roundtf4(v1));
        } else {
            cp16(dstA + sb, Ag + k0);
            cp16(dstA + sb + 64, Ag + k0 + 16);
        }
        cp16(dstB + sb, Bg + k0);
        cp16(dstB + sb + 64, Bg + k0 + 16);
        asm volatile("cp.async.commit_group;" ::: "memory");
    }
    asm volatile("cp.async.wait_group 4;" ::: "memory");
    __syncthreads();

    /* main loop: issue c+5, MMA c, wait(c+1), sync */
    for (int c = 0; c < NCH - (NSTG - 1); c++) {
        const uint32_t sb = (uint32_t)(((c + NSTG - 1) % NSTG) * STG_BYTES);
        const int k0n = (c + NSTG - 1) * BKK;
        float4 pa0, pa1;
        if (RA) {
            pa0 = *(const float4*)(Ag + k0n);
            pa1 = *(const float4*)(Ag + k0n + 16);
        } else {
            cp16(dstA + sb, Ag + k0n);
            cp16(dstA + sb + 64, Ag + k0n + 16);
        }
        cp16(dstB + sb, Bg + k0n);
        cp16(dstB + sb + 64, Bg + k0n + 16);
        asm volatile("cp.async.commit_group;" ::: "memory");

        const uint32_t st = u0 + (uint32_t)((c % NSTG) * STG_BYTES);
#pragma unroll
        for (int ks = 0; ks < 4; ks++) {
            uint32_t av[2][4], bv[2][4];
#pragma unroll
            for (int mf = 0; mf < 2; mf++)
                ldsm4(av[mf], st + aoff[mf] + ks * 32);
#pragma unroll
            for (int p = 0; p < 2; p++)
                ldsm4(bv[p], st + boff[p] + ks * 32);
#pragma unroll
            for (int mf = 0; mf < 2; mf++)
#pragma unroll
                for (int nf = 0; nf < 4; nf++)
                    mma_tf32(acc[mf][nf], av[mf], &bv[nf >> 1][(nf & 1) * 2]);
        }

        if (RA) {
            sts16(dstA + sb, roundtf4(pa0));
            sts16(dstA + sb + 64, roundtf4(pa1));
        }
        asm volatile("cp.async.wait_group 4;" ::: "memory");
        __syncthreads();
    }

    /* tail: everything resident; 5 chunks with no waits/barriers */
    asm volatile("cp.async.wait_group 0;" ::: "memory");
    __syncthreads();
#pragma unroll
    for (int c = NCH - (NSTG - 1); c < NCH; c++) {
        const uint32_t st = u0 + (uint32_t)((c % NSTG) * STG_BYTES);
#pragma unroll
        for (int ks = 0; ks < 4; ks++) {
            uint32_t av[2][4], bv[2][4];
#pragma unroll
            for (int mf = 0; mf < 2; mf++)
                ldsm4(av[mf], st + aoff[mf] + ks * 32);
#pragma unroll
            for (int p = 0; p < 2; p++)
                ldsm4(bv[p], st + boff[p] + ks * 32);
#pragma unroll
            for (int mf = 0; mf < 2; mf++)
#pragma unroll
                for (int nf = 0; nf < 4; nf++)
                    mma_tf32(acc[mf][nf], av[mf], &bv[nf >> 1][(nf & 1) * 2]);
        }
    }

    const int row0 = blockIdx.y * 128 + rb + g;
    const int col0 = blockIdx.x * 128 + cb + tig * 2;
#pragma unroll
    for (int nf = 0; nf < 4; nf++) {
        const int col = col0 + nf * 8;
        const float b0 = bias[col], b1 = bias[col + 1];
        const bool rnd = (col >= round_from);
#pragma unroll
        for (int mf = 0; mf < 2; mf++) {
            const int r = row0 + mf * 16;
            float2 v0 = make_float2(acc[mf][nf][0] + b0, acc[mf][nf][1] + b1);
            float2 v1 = make_float2(acc[mf][nf][2] + b0, acc[mf][nf][3] + b1);
            if (rnd) {
                v0.x = roundtf(v0.x); v0.y = roundtf(v0.y);
                v1.x = roundtf(v1.x); v1.y = roundtf(v1.y);
            }
            *(float2*)(C + (size_t)r * N + col)       = v0;
            *(float2*)(C + (size_t)(r + 8) * N + col) = v1;
        }
    }
}

/* ---- weight transpose + tf32 round: D[c][r] = round(S[r][c]) ---- */
__global__ void transpose_kernel(const float* __restrict__ S, float* __restrict__ D,
                                 int R, int Cc)
{
    __shared__ float t[32][33];
    const int bx = blockIdx.x * 32, by = blockIdx.y * 32;
    const int x = threadIdx.x, y = threadIdx.y;   /* 32 x 8 */
#pragma unroll
    for (int j = 0; j < 32; j += 8)
        t[y + j][x] = S[(size_t)(by + y + j) * Cc + bx + x];
    __syncthreads();
#pragma unroll
    for (int j = 0; j < 32; j += 8)
        D[(size_t)(bx + y + j) * R + by + x] = roundtf(t[x][y + j]);
}

/* ---------------- softmaxes & small kernels ---------------- */

/* 2-pass no-max q softmax; grid BB*(DIMM/32), block 1024 */
__global__ void q_softmax_kernel(float* __restrict__ qkv)
{
    const int b       = blockIdx.x / (DIMM / 32);
    const int colbase = (blockIdx.x % (DIMM / 32)) * 32;
    const int c = threadIdx.x & 31;
    const int r = threadIdx.x >> 5;   /* 0..31 */
    const int stride = QKVN;
    float* base = qkv + (size_t)b * SS * stride + colbase + c;

    __shared__ float red[32][33];

    float sum = 0.f;
    for (int s = r; s < SS; s += 32)
        sum += __expf(base[(size_t)s * stride]);
    red[r][c] = sum;
    __syncthreads();
    if (r == 0) {
        float t = 0.f;
#pragma unroll
        for (int i = 0; i < 32; i++) t += red[i][c];
        red[0][c] = t;
    }
    __syncthreads();
    const float inv = SCALE_F / red[0][c];

    for (int s = r; s < SS; s += 32) {
        size_t off = (size_t)s * stride;
        base[off] = __expf(base[off]) * inv;
    }
}

/* no-max k softmax: 64 contiguous floats per (b,s,h) row */
__global__ void k_softmax_kernel(float* __restrict__ qkv)
{
    const int row  = blockIdx.x * 8 + (threadIdx.x >> 5);
    const int lane = threadIdx.x & 31;
    float* p = qkv + (size_t)(row / HH) * QKVN + DIMM + (row % HH) * HDD;

    float e0 = __expf(p[lane]), e1 = __expf(p[lane + 32]);
    float s = e0 + e1;
#pragma unroll
    for (int o = 16; o > 0; o >>= 1)
        s += __shfl_xor_sync(0xFFFFFFFFu, s, o);
    float inv = 1.f / s;
    p[lane]      = e0 * inv;
    p[lane + 32] = e1 * inv;
}

__global__ void ktq_kernel(const float* __restrict__ qkv, float* __restrict__ Apart)
{
    const int bh = blockIdx.x / TSPLIT;
    const int ts = blockIdx.x % TSPLIT;
    const int b = bh / HH, h = bh % HH;
    const int TCHUNK = SS / TSPLIT;   /* 256 */

    __shared__ __align__(16) float ks[32][64];
    __shared__ __align__(16) float qs[32][64];

    const int tid = threadIdx.x;
    const int tc = tid & 15;
    const int tr = tid >> 4;
    const int lr = tid >> 3;
    const int lc = tid & 7;

    float acc[4][4];
#pragma unroll
    for (int i = 0; i < 4; i++)
#pragma unroll
        for (int j = 0; j < 4; j++) acc[i][j] = 0.f;

    const float* base = qkv + ((size_t)b * SS + (size_t)ts * TCHUNK) * QKVN;

    for (int t0 = 0; t0 < TCHUNK; t0 += 32) {
        const float* qrow = base + (size_t)(t0 + lr) * QKVN + h * HDD;
        const float* krow = qrow + DIMM;
        *(float4*)&qs[lr][lc * 4]      = *(const float4*)(qrow + lc * 4);
        *(float4*)&qs[lr][lc * 4 + 32] = *(const float4*)(qrow + lc * 4 + 32);
        *(float4*)&ks[lr][lc * 4]      = *(const float4*)(krow + lc * 4);
        *(float4*)&ks[lr][lc * 4 + 32] = *(const float4*)(krow + lc * 4 + 32);
        __syncthreads();
#pragma unroll
        for (int kk = 0; kk < 32; kk++) {
            float kr[4], qr[4];
            *(float4*)kr = *(const float4*)&ks[kk][tr * 4];
            *(float4*)qr = *(const float4*)&qs[kk][tc * 4];
#pragma unroll
            for (int i = 0; i < 4; i++)
#pragma unroll
                for (int j = 0; j < 4; j++)
                    acc[i][j] += kr[i] * qr[j];
        }
        __syncthreads();
    }

    float* outp = Apart + ((size_t)ts * BB * HH + bh) * HDD * HDD;
#pragma unroll
    for (int i = 0; i < 4; i++) {
        float4 v = make_float4(acc[i][0], acc[i][1], acc[i][2], acc[i][3]);
        *(float4*)&outp[(tr * 4 + i) * HDD + tc * 4] = v;
    }
}

__global__ void a_reduce_kernel(const float* __restrict__ Apart, float* __restrict__ A)
{
    const int idx = blockIdx.x * 256 + threadIdx.x;
    const size_t stride = (size_t)BB * HH * HDD * HDD;
    float s = 0.f;
#pragma unroll
    for (int p = 0; p < TSPLIT; p++)
        s += Apart[(size_t)p * stride + idx];
    A[idx] = s;
}

/* ---- B~[b][j][h*64+d] = round(sum_e WprojT[j][h*64+e] * A[b,h,d,e]) ---- */
__global__ void wA_kernel(const float* __restrict__ WprojT,
                          const float* __restrict__ Amat,
                          float* __restrict__ btilde)
{
    const int jt = blockIdx.x;         /* 0..15 */
    const int bh = blockIdx.y;         /* 0..127 */
    const int b = bh >> 4, h = bh & 15;

    __shared__ __align__(16) float Xsm[64][68];   /* X[e][d] = A[d][e] */
    __shared__ __align__(16) float Wsm[64][68];   /* W[local j][e]     */

    const int tid = threadIdx.x;
    const int tc = tid & 15;   /* d group */
    const int tr = tid >> 4;   /* j group */

    {
        const float* Ab = Amat + (size_t)bh * (HDD * HDD);
#pragma unroll
        for (int i = 0; i < 16; i++) {
            int idx = i * 256 + tid;
            Xsm[idx & 63][idx >> 6] = Ab[idx];
        }
    }
    {
        const int lr = tid >> 2;
        const int lc = tid & 3;
        const float* wrow = WprojT + (size_t)(jt * 64 + lr) * KDIM + h * HDD;
#pragma unroll
        for (int m = 0; m < 4; m++)
            *(float4*)&Wsm[lr][(lc + 4 * m) * 4] = *(const float4*)(wrow + (lc + 4 * m) * 4);
    }
    __syncthreads();

    float acc[4][4];
#pragma unroll
    for (int i = 0; i < 4; i++)
#pragma unroll
        for (int j = 0; j < 4; j++) acc[i][j] = 0.f;

#pragma unroll 8
    for (int e = 0; e < 64; e++) {
        float br[4];
        *(float4*)br = *(const float4*)&Xsm[e][tc * 4];
        float wr[4];
#pragma unroll
        for (int i = 0; i < 4; i++) wr[i] = Wsm[tr * 4 + i][e];
#pragma unroll
        for (int i = 0; i < 4; i++)
#pragma unroll
            for (int j = 0; j < 4; j++)
                acc[i][j] += wr[i] * br[j];
    }

#pragma unroll
    for (int i = 0; i < 4; i++) {
        const size_t row = (size_t)b * DIMM + jt * 64 + tr * 4 + i;
        float4 v = make_float4(roundtf(acc[i][0]), roundtf(acc[i][1]),
                               roundtf(acc[i][2]), roundtf(acc[i][3]));
        *(float4*)(btilde + row * DIMM + h * HDD + tc * 4) = v;
    }
}

/* --------------------------------------------------------------- */
extern "C" void kernel_launch(void* const* d_in, const int* in_sizes, int n_in,
                              void* d_out, int out_size)
{
    (void)in_sizes; (void)n_in; (void)out_size;
    const float* x     = (const float*)d_in[0];
    const float* Wqkv  = (const float*)d_in[1];
    const float* bqkv  = (const float*)d_in[2];
    const float* Wproj = (const float*)d_in[3];
    const float* bproj = (const float*)d_in[4];
    float* out = (float*)d_out;

    float *qkv, *btilde, *Apart, *Amat, *WqkvT, *WprojT;
    cudaGetSymbolAddress((void**)&qkv,    g_qkv);
    cudaGetSymbolAddress((void**)&btilde, g_btilde);
    cudaGetSymbolAddress((void**)&Apart,  g_Apart);
    cudaGetSymbolAddress((void**)&Amat,   g_A);
    cudaGetSymbolAddress((void**)&WqkvT,  g_WqkvT);
    cudaGetSymbolAddress((void**)&WprojT, g_WprojT);

    cudaFuncSetAttribute((const void*)gemm_tc<1>,
                         cudaFuncAttributeMaxDynamicSharedMemorySize, SMEM_DYN_G);
    cudaFuncSetAttribute((const void*)gemm_tc<0>,
                         cudaFuncAttributeMaxDynamicSharedMemorySize, SMEM_DYN_G);

    /* 0) pre-round weights (x rounded inside GEMM1) */
    {
        dim3 blk(32, 8);
        transpose_kernel<<<dim3(QKVN / 32, DIMM / 32), blk>>>(Wqkv, WqkvT, DIMM, QKVN);
        transpose_kernel<<<dim3(DIMM / 32, DIMM / 32), blk>>>(Wproj, WprojT, DIMM, DIMM);
    }
    /* 1) qkv = x @ Wqkv + bqkv ; x rounded in-kernel; V cols (>=2048) rounded */
    gemm_tc<1><<<dim3(QKVN / 128, BSR / 128), 512, SMEM_DYN_G>>>(
        x, KDIM, WqkvT, 0, bqkv, qkv, QKVN, 2 * DIMM);
    /* 2) softmaxes (in place on q, k) */
    q_softmax_kernel<<<BB * (DIMM / 32), 1024>>>(qkv);
    k_softmax_kernel<<<(BSR * HH) / 8, 256>>>(qkv);
    /* 3) A = K^T Q per (b,h) */
    ktq_kernel<<<BB * HH * TSPLIT, 256>>>(qkv, Apart);
    a_reduce_kernel<<<(BB * HH * HDD * HDD) / 256, 256>>>(Apart, Amat);
    /* 4) B~ = A (x) Wproj  (per-batch folded weights, tf32-rounded) */
    wA_kernel<<<dim3(16, BB * HH), 256>>>(WprojT, Amat, btilde);
    /* 5) out = V @ B~ + bproj  (V read strided from qkv; B~ per batch) */
    gemm_tc<0><<<dim3(DIMM / 128, BSR / 128), 512, SMEM_DYN_G>>>(
        qkv + 2 * DIMM, QKVN, btilde, DIMM * DIMM, bproj, out, DIMM, 1 << 30);
}

// round 10
// speedup vs baseline: 1.2702x; 1.0062x over previous
#include <cuda_runtime.h>
#include <cstdint>
#include <math.h>

#define BB   8
#define SS   4096
#define DIMM 1024
#define HH   16
#define HDD  64
#define BSR  (BB * SS)          /* 32768 rows */
#define QKVN (3 * DIMM)         /* 3072 */
#define TSPLIT 16
#define SCALE_F 0.125f          /* 64^-0.5 */
#define KDIM 1024               /* K of both big GEMMs */

/* -------- scratch (device globals: allocation-free rule) -------- */
__device__ float g_qkv[(size_t)BSR * QKVN];                       /* 402 MB */
__device__ float g_btilde[(size_t)BB * DIMM * DIMM];              /* 32 MB  */
__device__ float g_Apart[(size_t)TSPLIT * BB * HH * HDD * HDD];   /* 33 MB  */
__device__ float g_A[(size_t)BB * HH * HDD * HDD];                /* 2 MB   */
__device__ float g_WqkvT[(size_t)QKVN * DIMM];                    /* 12 MB  */
__device__ float g_WprojT[(size_t)DIMM * DIMM];                   /* 4 MB   */

__device__ __forceinline__ uint32_t f2tf32(float x) {
    uint32_t r;
    asm("cvt.rna.tf32.f32 %0, %1;" : "=r"(r) : "f"(x));
    return r;
}
__device__ __forceinline__ float roundtf(float x) {
    return __uint_as_float(f2tf32(x));
}

/* ===== tf32 mma.sync GEMM: 512 thr, tile 128x128, warp tile 32x32,
 * 6-stage cp.async ring, peeled tail, ldmatrix fragments with
 * REGISTER DOUBLE-BUFFERING (prefetch ks+1 during ks's HMMAs). ===== */

#define BKK   32
#define ASTR  36                      /* padded row stride in floats */
#define STG_F (128 * ASTR)            /* floats per matrix per stage */
#define STG_BYTES (2 * STG_F * 4)     /* A+B per stage = 36864 B */
#define NSTG  6
#define SMEM_DYN_G (NSTG * STG_BYTES) /* 221184 B */
#define NCH   (KDIM / BKK)            /* 32 */

__device__ __forceinline__ uint32_t smem_u32(const void* p) {
    uint32_t a;
    asm("{ .reg .u64 t; cvta.to.shared.u64 t, %1; cvt.u32.u64 %0, t; }"
        : "=r"(a) : "l"(p));
    return a;
}
__device__ __forceinline__ void cp16(uint32_t dst, const void* src) {
    asm volatile("cp.async.cg.shared.global [%0], [%1], 16;"
                 :: "r"(dst), "l"(src) : "memory");
}
__device__ __forceinline__ void sts16(uint32_t dst, float4 v) {
    asm volatile("st.shared.v4.b32 [%0], {%1,%2,%3,%4};"
                 :: "r"(dst), "f"(v.x), "f"(v.y), "f"(v.z), "f"(v.w) : "memory");
}
__device__ __forceinline__ void ldsm4(uint32_t* r, uint32_t addr) {
    asm volatile("ldmatrix.sync.aligned.m8n8.x4.shared.b16 {%0,%1,%2,%3}, [%4];"
                 : "=r"(r[0]), "=r"(r[1]), "=r"(r[2]), "=r"(r[3]) : "r"(addr));
}
__device__ __forceinline__ void mma_tf32(float* c, const uint32_t* a, const uint32_t* b) {
    asm volatile("mma.sync.aligned.m16n8k8.row.col.f32.tf32.tf32.f32 "
                 "{%0,%1,%2,%3}, {%4,%5,%6,%7}, {%8,%9}, {%0,%1,%2,%3};"
                 : "+f"(c[0]), "+f"(c[1]), "+f"(c[2]), "+f"(c[3])
                 : "r"(a[0]), "r"(a[1]), "r"(a[2]), "r"(a[3]),
                   "r"(b[0]), "r"(b[1]));
}
__device__ __forceinline__ float4 roundtf4(float4 v) {
    v.x = roundtf(v.x); v.y = roundtf(v.y);
    v.z = roundtf(v.z); v.w = roundtf(v.w);
    return v;
}

/* one 32-K chunk of MMAs with register double-buffered fragments */
__device__ __forceinline__ void chunk_mma(uint32_t st, const uint32_t* aoff,
                                          const uint32_t* boff,
                                          float acc[2][4][4])
{
    uint32_t av[2][2][4], bv[2][2][4];
#pragma unroll
    for (int mf = 0; mf < 2; mf++) ldsm4(av[0][mf], st + aoff[mf]);
#pragma unroll
    for (int p = 0; p < 2; p++)    ldsm4(bv[0][p], st + boff[p]);
#pragma unroll
    for (int ks = 0; ks < 4; ks++) {
        const int cur = ks & 1, nxt = cur ^ 1;
        if (ks < 3) {
#pragma unroll
            for (int mf = 0; mf < 2; mf++)
                ldsm4(av[nxt][mf], st + aoff[mf] + (ks + 1) * 32);
#pragma unroll
            for (int p = 0; p < 2; p++)
                ldsm4(bv[nxt][p], st + boff[p] + (ks + 1) * 32);
        }
#pragma unroll
        for (int mf = 0; mf < 2; mf++)
#pragma unroll
            for (int nf = 0; nf < 4; nf++)
                mma_tf32(acc[mf][nf], av[cur][mf], &bv[cur][nf >> 1][(nf & 1) * 2]);
    }
}

template<int RA>
__global__ void __launch_bounds__(512, 1)
gemm_tc(const float* __restrict__ A, int astr,
        const float* __restrict__ BT, int bstride,
        const float* __restrict__ bias, float* __restrict__ C, int N,
        int round_from)
{
    extern __shared__ __align__(16) float sm[];
    const uint32_t u0 = smem_u32(sm);

    const int tid  = threadIdx.x;
    const int lane = tid & 31;
    const int warp = tid >> 5;          /* 0..15 */
    const int wm   = warp & 3;          /* warp row: 0..3 */
    const int wn   = warp >> 2;         /* warp col: 0..3 */
    const int g    = lane >> 2;
    const int tig  = lane & 3;

    /* loader: 4 threads per 128B row, each 2x16B (slots q, q+4) */
    const int lrow = tid >> 2;          /* 0..127 */
    const int lq   = tid & 3;
    const float* Ag = A + (size_t)(blockIdx.y * 128 + lrow) * astr + lq * 4;
    const float* Bg = BT + (size_t)(blockIdx.y >> 5) * (size_t)bstride
                         + (size_t)(blockIdx.x * 128 + lrow) * KDIM + lq * 4;
    const uint32_t dstA = u0 + (uint32_t)(lrow * ASTR + lq * 4) * 4;
    const uint32_t dstB = dstA + (uint32_t)(STG_F * 4);

    const int rb = wm * 32;
    const int cb = wn * 32;

    uint32_t aoff[2];
#pragma unroll
    for (int mf = 0; mf < 2; mf++)
        aoff[mf] = (uint32_t)(((rb + mf * 16 + (lane & 15)) * ASTR
                               + 4 * (lane >> 4)) * 4);
    uint32_t boff[2];
#pragma unroll
    for (int p = 0; p < 2; p++)
        boff[p] = (uint32_t)(STG_F * 4)
                + (uint32_t)(((cb + p * 16 + ((lane >> 4) << 3) + (lane & 7)) * ASTR
                              + 4 * ((lane >> 3) & 1)) * 4);

    float acc[2][4][4];
#pragma unroll
    for (int i = 0; i < 2; i++)
#pragma unroll
        for (int j = 0; j < 4; j++)
#pragma unroll
            for (int r = 0; r < 4; r++) acc[i][j][r] = 0.f;

    /* prologue: chunks 0..4 into stages 0..4 */
#pragma unroll
    for (int s = 0; s < NSTG - 1; s++) {
        const uint32_t sb = (uint32_t)(s * STG_BYTES);
        const int k0 = s * BKK;
        if (RA) {
            float4 v0 = *(const float4*)(Ag + k0);
            float4 v1 = *(const float4*)(Ag + k0 + 16);
            sts16(dstA + sb, roundtf4(v0));
            sts16(dstA + sb + 64, roundtf4(v1));
        } else {
            cp16(dstA + sb, Ag + k0);
            cp16(dstA + sb + 64, Ag + k0 + 16);
        }
        cp16(dstB + sb, Bg + k0);
        cp16(dstB + sb + 64, Bg + k0 + 16);
        asm volatile("cp.async.commit_group;" ::: "memory");
    }
    asm volatile("cp.async.wait_group 4;" ::: "memory");
    __syncthreads();

    /* main loop: issue c+5, MMA c, wait(c+1), sync */
    for (int c = 0; c < NCH - (NSTG - 1); c++) {
        const uint32_t sb = (uint32_t)(((c + NSTG - 1) % NSTG) * STG_BYTES);
        const int k0n = (c + NSTG - 1) * BKK;
        float4 pa0, pa1;
        if (RA) {
            pa0 = *(const float4*)(Ag + k0n);
            pa1 = *(const float4*)(Ag + k0n + 16);
        } else {
            cp16(dstA + sb, Ag + k0n);
            cp16(dstA + sb + 64, Ag + k0n + 16);
        }
        cp16(dstB + sb, Bg + k0n);
        cp16(dstB + sb + 64, Bg + k0n + 16);
        asm volatile("cp.async.commit_group;" ::: "memory");

        const uint32_t st = u0 + (uint32_t)((c % NSTG) * STG_BYTES);
        chunk_mma(st, aoff, boff, acc);

        if (RA) {
            sts16(dstA + sb, roundtf4(pa0));
            sts16(dstA + sb + 64, roundtf4(pa1));
        }
        asm volatile("cp.async.wait_group 4;" ::: "memory");
        __syncthreads();
    }

    /* tail: everything resident; 5 chunks with no waits/barriers */
    asm volatile("cp.async.wait_group 0;" ::: "memory");
    __syncthreads();
#pragma unroll
    for (int c = NCH - (NSTG - 1); c < NCH; c++) {
        const uint32_t st = u0 + (uint32_t)((c % NSTG) * STG_BYTES);
        chunk_mma(st, aoff, boff, acc);
    }

    const int row0 = blockIdx.y * 128 + rb + g;
    const int col0 = blockIdx.x * 128 + cb + tig * 2;
#pragma unroll
    for (int nf = 0; nf < 4; nf++) {
        const int col = col0 + nf * 8;
        const float b0 = bias[col], b1 = bias[col + 1];
        const bool rnd = (col >= round_from);
#pragma unroll
        for (int mf = 0; mf < 2; mf++) {
            const int r = row0 + mf * 16;
            float2 v0 = make_float2(acc[mf][nf][0] + b0, acc[mf][nf][1] + b1);
            float2 v1 = make_float2(acc[mf][nf][2] + b0, acc[mf][nf][3] + b1);
            if (rnd) {
                v0.x = roundtf(v0.x); v0.y = roundtf(v0.y);
                v1.x = roundtf(v1.x); v1.y = roundtf(v1.y);
            }
            *(float2*)(C + (size_t)r * N + col)       = v0;
            *(float2*)(C + (size_t)(r + 8) * N + col) = v1;
        }
    }
}

/* ---- weight transpose + tf32 round: D[c][r] = round(S[r][c]) ---- */
__global__ void transpose_kernel(const float* __restrict__ S, float* __restrict__ D,
                                 int R, int Cc)
{
    __shared__ float t[32][33];
    const int bx = blockIdx.x * 32, by = blockIdx.y * 32;
    const int x = threadIdx.x, y = threadIdx.y;   /* 32 x 8 */
#pragma unroll
    for (int j = 0; j < 32; j += 8)
        t[y + j][x] = S[(size_t)(by + y + j) * Cc + bx + x];
    __syncthreads();
#pragma unroll
    for (int j = 0; j < 32; j += 8)
        D[(size_t)(bx + y + j) * R + by + x] = roundtf(t[x][y + j]);
}

/* ---------------- softmaxes & small kernels ---------------- */

/* 2-pass no-max q softmax; grid BB*(DIMM/32), block 1024 */
__global__ void q_softmax_kernel(float* __restrict__ qkv)
{
    const int b       = blockIdx.x / (DIMM / 32);
    const int colbase = (blockIdx.x % (DIMM / 32)) * 32;
    const int c = threadIdx.x & 31;
    const int r = threadIdx.x >> 5;   /* 0..31 */
    const int stride = QKVN;
    float* base = qkv + (size_t)b * SS * stride + colbase + c;

    __shared__ float red[32][33];

    float sum = 0.f;
    for (int s = r; s < SS; s += 32)
        sum += __expf(base[(size_t)s * stride]);
    red[r][c] = sum;
    __syncthreads();
    if (r == 0) {
        float t = 0.f;
#pragma unroll
        for (int i = 0; i < 32; i++) t += red[i][c];
        red[0][c] = t;
    }
    __syncthreads();
    const float inv = SCALE_F / red[0][c];

    for (int s = r; s < SS; s += 32) {
        size_t off = (size_t)s * stride;
        base[off] = __expf(base[off]) * inv;
    }
}

/* no-max k softmax: 64 contiguous floats per (b,s,h) row */
__global__ void k_softmax_kernel(float* __restrict__ qkv)
{
    const int row  = blockIdx.x * 8 + (threadIdx.x >> 5);
    const int lane = threadIdx.x & 31;
    float* p = qkv + (size_t)(row / HH) * QKVN + DIMM + (row % HH) * HDD;

    float e0 = __expf(p[lane]), e1 = __expf(p[lane + 32]);
    float s = e0 + e1;
#pragma unroll
    for (int o = 16; o > 0; o >>= 1)
        s += __shfl_xor_sync(0xFFFFFFFFu, s, o);
    float inv = 1.f / s;
    p[lane]      = e0 * inv;
    p[lane + 32] = e1 * inv;
}

__global__ void ktq_kernel(const float* __restrict__ qkv, float* __restrict__ Apart)
{
    const int bh = blockIdx.x / TSPLIT;
    const int ts = blockIdx.x % TSPLIT;
    const int b = bh / HH, h = bh % HH;
    const int TCHUNK = SS / TSPLIT;   /* 256 */

    __shared__ __align__(16) float ks[32][64];
    __shared__ __align__(16) float qs[32][64];

    const int tid = threadIdx.x;
    const int tc = tid & 15;
    const int tr = tid >> 4;
    const int lr = tid >> 3;
    const int lc = tid & 7;

    float acc[4][4];
#pragma unroll
    for (int i = 0; i < 4; i++)
#pragma unroll
        for (int j = 0; j < 4; j++) acc[i][j] = 0.f;

    const float* base = qkv + ((size_t)b * SS + (size_t)ts * TCHUNK) * QKVN;

    for (int t0 = 0; t0 < TCHUNK; t0 += 32) {
        const float* qrow = base + (size_t)(t0 + lr) * QKVN + h * HDD;
        const float* krow = qrow + DIMM;
        *(float4*)&qs[lr][lc * 4]      = *(const float4*)(qrow + lc * 4);
        *(float4*)&qs[lr][lc * 4 + 32] = *(const float4*)(qrow + lc * 4 + 32);
        *(float4*)&ks[lr][lc * 4]      = *(const float4*)(krow + lc * 4);
        *(float4*)&ks[lr][lc * 4 + 32] = *(const float4*)(krow + lc * 4 + 32);
        __syncthreads();
#pragma unroll
        for (int kk = 0; kk < 32; kk++) {
            float kr[4], qr[4];
            *(float4*)kr = *(const float4*)&ks[kk][tr * 4];
            *(float4*)qr = *(const float4*)&qs[kk][tc * 4];
#pragma unroll
            for (int i = 0; i < 4; i++)
#pragma unroll
                for (int j = 0; j < 4; j++)
                    acc[i][j] += kr[i] * qr[j];
        }
        __syncthreads();
    }

    float* outp = Apart + ((size_t)ts * BB * HH + bh) * HDD * HDD;
#pragma unroll
    for (int i = 0; i < 4; i++) {
        float4 v = make_float4(acc[i][0], acc[i][1], acc[i][2], acc[i][3]);
        *(float4*)&outp[(tr * 4 + i) * HDD + tc * 4] = v;
    }
}

__global__ void a_reduce_kernel(const float* __restrict__ Apart, float* __restrict__ A)
{
    const int idx = blockIdx.x * 256 + threadIdx.x;
    const size_t stride = (size_t)BB * HH * HDD * HDD;
    float s = 0.f;
#pragma unroll
    for (int p = 0; p < TSPLIT; p++)
        s += Apart[(size_t)p * stride + idx];
    A[idx] = s;
}

/* ---- B~[b][j][h*64+d] = round(sum_e WprojT[j][h*64+e] * A[b,h,d,e]) ---- */
__global__ void wA_kernel(const float* __restrict__ WprojT,
                          const float* __restrict__ Amat,
                          float* __restrict__ btilde)
{
    const int jt = blockIdx.x;         /* 0..15 */
    const int bh = blockIdx.y;         /* 0..127 */
    const int b = bh >> 4, h = bh & 15;

    __shared__ __align__(16) float Xsm[64][68];   /* X[e][d] = A[d][e] */
    __shared__ __align__(16) float Wsm[64][68];   /* W[local j][e]     */

    const int tid = threadIdx.x;
    const int tc = tid & 15;   /* d group */
    const int tr = tid >> 4;   /* j group */

    {
        const float* Ab = Amat + (size_t)bh * (HDD * HDD);
#pragma unroll
        for (int i = 0; i < 16; i++) {
            int idx = i * 256 + tid;
            Xsm[idx & 63][idx >> 6] = Ab[idx];
        }
    }
    {
        const int lr = tid >> 2;
        const int lc = tid & 3;
        const float* wrow = WprojT + (size_t)(jt * 64 + lr) * KDIM + h * HDD;
#pragma unroll
        for (int m = 0; m < 4; m++)
            *(float4*)&Wsm[lr][(lc + 4 * m) * 4] = *(const float4*)(wrow + (lc + 4 * m) * 4);
    }
    __syncthreads();

    float acc[4][4];
#pragma unroll
    for (int i = 0; i < 4; i++)
#pragma unroll
        for (int j = 0; j < 4; j++) acc[i][j] = 0.f;

#pragma unroll 8
    for (int e = 0; e < 64; e++) {
        float br[4];
        *(float4*)br = *(const float4*)&Xsm[e][tc * 4];
        float wr[4];
#pragma unroll
        for (int i = 0; i < 4; i++) wr[i] = Wsm[tr * 4 + i][e];
#pragma unroll
        for (int i = 0; i < 4; i++)
#pragma unroll
            for (int j = 0; j < 4; j++)
                acc[i][j] += wr[i] * br[j];
    }

#pragma unroll
    for (int i = 0; i < 4; i++) {
        const size_t row = (size_t)b * DIMM + jt * 64 + tr * 4 + i;
        float4 v = make_float4(roundtf(acc[i][0]), roundtf(acc[i][1]),
                               roundtf(acc[i][2]), roundtf(acc[i][3]));
        *(float4*)(btilde + row * DIMM + h * HDD + tc * 4) = v;
    }
}

/* --------------------------------------------------------------- */
extern "C" void kernel_launch(void* const* d_in, const int* in_sizes, int n_in,
                              void* d_out, int out_size)
{
    (void)in_sizes; (void)n_in; (void)out_size;
    const float* x     = (const float*)d_in[0];
    const float* Wqkv  = (const float*)d_in[1];
    const float* bqkv  = (const float*)d_in[2];
    const float* Wproj = (const float*)d_in[3];
    const float* bproj = (const float*)d_in[4];
    float* out = (float*)d_out;

    float *qkv, *btilde, *Apart, *Amat, *WqkvT, *WprojT;
    cudaGetSymbolAddress((void**)&qkv,    g_qkv);
    cudaGetSymbolAddress((void**)&btilde, g_btilde);
    cudaGetSymbolAddress((void**)&Apart,  g_Apart);
    cudaGetSymbolAddress((void**)&Amat,   g_A);
    cudaGetSymbolAddress((void**)&WqkvT,  g_WqkvT);
    cudaGetSymbolAddress((void**)&WprojT, g_WprojT);

    cudaFuncSetAttribute((const void*)gemm_tc<1>,
                         cudaFuncAttributeMaxDynamicSharedMemorySize, SMEM_DYN_G);
    cudaFuncSetAttribute((const void*)gemm_tc<0>,
                         cudaFuncAttributeMaxDynamicSharedMemorySize, SMEM_DYN_G);

    /* 0) pre-round weights (x rounded inside GEMM1) */
    {
        dim3 blk(32, 8);
        transpose_kernel<<<dim3(QKVN / 32, DIMM / 32), blk>>>(Wqkv, WqkvT, DIMM, QKVN);
        transpose_kernel<<<dim3(DIMM / 32, DIMM / 32), blk>>>(Wproj, WprojT, DIMM, DIMM);
    }
    /* 1) qkv = x @ Wqkv + bqkv ; x rounded in-kernel; V cols (>=2048) rounded */
    gemm_tc<1><<<dim3(QKVN / 128, BSR / 128), 512, SMEM_DYN_G>>>(
        x, KDIM, WqkvT, 0, bqkv, qkv, QKVN, 2 * DIMM);
    /* 2) softmaxes (in place on q, k) */
    q_softmax_kernel<<<BB * (DIMM / 32), 1024>>>(qkv);
    k_softmax_kernel<<<(BSR * HH) / 8, 256>>>(qkv);
    /* 3) A = K^T Q per (b,h) */
    ktq_kernel<<<BB * HH * TSPLIT, 256>>>(qkv, Apart);
    a_reduce_kernel<<<(BB * HH * HDD * HDD) / 256, 256>>>(Apart, Amat);
    /* 4) B~ = A (x) Wproj  (per-batch folded weights, tf32-rounded) */
    wA_kernel<<<dim3(16, BB * HH), 256>>>(WprojT, Amat, btilde);
    /* 5) out = V @ B~ + bproj  (V read strided from qkv; B~ per batch) */
    gemm_tc<0><<<dim3(DIMM / 128, BSR / 128), 512, SMEM_DYN_G>>>(
        qkv + 2 * DIMM, QKVN, btilde, DIMM * DIMM, bproj, out, DIMM, 1 << 30);
}

// round 11
// speedup vs baseline: 2.0691x; 1.6289x over previous
#include <cuda_runtime.h>
#include <cuda_fp16.h>
#include <cstdint>
#include <math.h>

#define BB   8
#define SS   4096
#define DIMM 1024
#define HH   16
#define HDD  64
#define BSR  (BB * SS)          /* 32768 rows */
#define QKSTR 2048              /* qkv buffer now holds q,k only */
#define TSPLIT 16
#define SCALE_F 0.125f          /* 64^-0.5 */
#define KDIM 1024               /* K of both big GEMMs */

/* -------- scratch (device globals: allocation-free rule) -------- */
__device__ float  g_qkv[(size_t)BSR * QKSTR];                      /* 268 MB */
__device__ __half g_vh[(size_t)BSR * DIMM];                        /* 67 MB  */
__device__ __half g_btilde[(size_t)BB * DIMM * DIMM];              /* 16 MB  */
__device__ float  g_Apart[(size_t)TSPLIT * BB * HH * HDD * HDD];   /* 33 MB  */
__device__ float  g_A[(size_t)BB * HH * HDD * HDD];                /* 2 MB   */
__device__ __half g_WqkvT[(size_t)3 * DIMM * DIMM];                /* 6 MB   */
__device__ __half g_WprojT[(size_t)DIMM * DIMM];                   /* 2 MB   */

/* ===== fp16 mma.sync GEMM: 512 thr, tile 128x128, warp tile 32x32,
 * m16n8k16.f32.f16.f16.f32, 8-stage cp.async ring, peeled tail.
 * MODE 1: A operand fp32 (x) converted to fp16 in-kernel; epilogue
 *         splits q,k (fp32 -> C) from V (fp16 -> vh).
 * MODE 0: A operand fp16 (vh); plain fp32 epilogue. ===== */

#define BROW  80                      /* smem row stride bytes (32 halfs + pad) */
#define A_STG 10240                   /* 128 rows * 80 B */
#define STG_BYTES 20480               /* A + B per stage */
#define NSTG  8
#define SMEM_DYN_G (NSTG * STG_BYTES) /* 163840 B */
#define NCH   (KDIM / 32)             /* 32 chunks of K=32 */

__device__ __forceinline__ uint32_t smem_u32(const void* p) {
    uint32_t a;
    asm("{ .reg .u64 t; cvta.to.shared.u64 t, %1; cvt.u32.u64 %0, t; }"
        : "=r"(a) : "l"(p));
    return a;
}
__device__ __forceinline__ void cp16(uint32_t dst, const void* src) {
    asm volatile("cp.async.cg.shared.global [%0], [%1], 16;"
                 :: "r"(dst), "l"(src) : "memory");
}
__device__ __forceinline__ uint32_t pack2(float lo, float hi) {
    uint32_t r;
    asm("cvt.rn.f16x2.f32 %0, %1, %2;" : "=r"(r) : "f"(hi), "f"(lo));
    return r;
}
__device__ __forceinline__ void sts16u(uint32_t dst, uint32_t a, uint32_t b,
                                       uint32_t c, uint32_t d) {
    asm volatile("st.shared.v4.b32 [%0], {%1,%2,%3,%4};"
                 :: "r"(dst), "r"(a), "r"(b), "r"(c), "r"(d) : "memory");
}
__device__ __forceinline__ void ldsm4(uint32_t* r, uint32_t addr) {
    asm volatile("ldmatrix.sync.aligned.m8n8.x4.shared.b16 {%0,%1,%2,%3}, [%4];"
                 : "=r"(r[0]), "=r"(r[1]), "=r"(r[2]), "=r"(r[3]) : "r"(addr));
}
__device__ __forceinline__ void mma_f16(float* c, const uint32_t* a, const uint32_t* b) {
    asm volatile("mma.sync.aligned.m16n8k16.row.col.f32.f16.f16.f32 "
                 "{%0,%1,%2,%3}, {%4,%5,%6,%7}, {%8,%9}, {%0,%1,%2,%3};"
                 : "+f"(c[0]), "+f"(c[1]), "+f"(c[2]), "+f"(c[3])
                 : "r"(a[0]), "r"(a[1]), "r"(a[2]), "r"(a[3]),
                   "r"(b[0]), "r"(b[1]));
}

/* one 32-K chunk = 2 k16 steps; 4 ldsm + 8 mma per step */
__device__ __forceinline__ void chunk_mma(uint32_t st, const uint32_t* aoff,
                                          const uint32_t* boff,
                                          float acc[2][4][4])
{
#pragma unroll
    for (int ks = 0; ks < 2; ks++) {
        uint32_t av[2][4], bv[2][4];
#pragma unroll
        for (int mf = 0; mf < 2; mf++)
            ldsm4(av[mf], st + aoff[mf] + ks * 32);
#pragma unroll
        for (int p = 0; p < 2; p++)
            ldsm4(bv[p], st + boff[p] + ks * 32);
#pragma unroll
        for (int mf = 0; mf < 2; mf++)
#pragma unroll
            for (int nf = 0; nf < 4; nf++)
                mma_f16(acc[mf][nf], av[mf], &bv[nf >> 1][(nf & 1) * 2]);
    }
}

template<int MODE>
__global__ void __launch_bounds__(512, 1)
gemm_fp16(const void* __restrict__ Ain, int astr,
          const __half* __restrict__ BT, int bstride,
          const float* __restrict__ bias, float* __restrict__ C, int cstr,
          __half* __restrict__ vh)
{
    extern __shared__ __align__(16) char sm[];
    const uint32_t u0 = smem_u32(sm);

    const int tid  = threadIdx.x;
    const int lane = tid & 31;
    const int warp = tid >> 5;          /* 0..15 */
    const int wm   = warp & 3;
    const int wn   = warp >> 2;
    const int g    = lane >> 2;
    const int tig  = lane & 3;

    /* loader: 4 threads per row, 16B (8 halfs / 8 floats-worth) each */
    const int lrow = tid >> 2;          /* 0..127 */
    const int lq   = tid & 3;
    const float*  Ag32 = (const float*)Ain + (size_t)(blockIdx.y * 128 + lrow) * astr + lq * 8;
    const __half* Agh  = (const __half*)Ain + (size_t)(blockIdx.y * 128 + lrow) * astr + lq * 8;
    const __half* Bg   = BT + (size_t)(blockIdx.y >> 5) * (size_t)bstride
                            + (size_t)(blockIdx.x * 128 + lrow) * KDIM + lq * 8;
    const uint32_t dstA = u0 + (uint32_t)(lrow * BROW + lq * 16);
    const uint32_t dstB = dstA + A_STG;

    const int rb = wm * 32;
    const int cb = wn * 32;

    uint32_t aoff[2];
#pragma unroll
    for (int mf = 0; mf < 2; mf++)
        aoff[mf] = (uint32_t)((rb + mf * 16 + (lane & 15)) * BROW + 16 * (lane >> 4));
    uint32_t boff[2];
#pragma unroll
    for (int p = 0; p < 2; p++)
        boff[p] = (uint32_t)(A_STG + (cb + p * 16 + ((lane >> 4) << 3) + (lane & 7)) * BROW
                             + 16 * ((lane >> 3) & 1));

    float acc[2][4][4];
#pragma unroll
    for (int i = 0; i < 2; i++)
#pragma unroll
        for (int j = 0; j < 4; j++)
#pragma unroll
            for (int r = 0; r < 4; r++) acc[i][j][r] = 0.f;

    /* prologue: chunks 0..NSTG-2 */
#pragma unroll
    for (int s = 0; s < NSTG - 1; s++) {
        const uint32_t sb = (uint32_t)(s * STG_BYTES);
        const int k0 = s * 32;
        if (MODE == 1) {
            float4 v0 = *(const float4*)(Ag32 + k0);
            float4 v1 = *(const float4*)(Ag32 + k0 + 4);
            sts16u(dstA + sb, pack2(v0.x, v0.y), pack2(v0.z, v0.w),
                   pack2(v1.x, v1.y), pack2(v1.z, v1.w));
        } else {
            cp16(dstA + sb, Agh + k0);
        }
        cp16(dstB + sb, Bg + k0);
        asm volatile("cp.async.commit_group;" ::: "memory");
    }
    asm volatile("cp.async.wait_group 6;" ::: "memory");
    __syncthreads();

    /* main loop: LDG A(c+7) -> cp B(c+7) -> MMA c -> STS A -> wait -> sync */
    for (int c = 0; c < NCH - (NSTG - 1); c++) {
        const uint32_t sb = (uint32_t)(((c + NSTG - 1) % NSTG) * STG_BYTES);
        const int k0n = (c + NSTG - 1) * 32;
        float4 pa0, pa1;
        if (MODE == 1) {
            pa0 = *(const float4*)(Ag32 + k0n);
            pa1 = *(const float4*)(Ag32 + k0n + 4);
        } else {
            cp16(dstA + sb, Agh + k0n);
        }
        cp16(dstB + sb, Bg + k0n);
        asm volatile("cp.async.commit_group;" ::: "memory");

        const uint32_t st = u0 + (uint32_t)((c % NSTG) * STG_BYTES);
        chunk_mma(st, aoff, boff, acc);

        if (MODE == 1)
            sts16u(dstA + sb, pack2(pa0.x, pa0.y), pack2(pa0.z, pa0.w),
                   pack2(pa1.x, pa1.y), pack2(pa1.z, pa1.w));
        asm volatile("cp.async.wait_group 6;" ::: "memory");
        __syncthreads();
    }

    /* tail: all resident */
    asm volatile("cp.async.wait_group 0;" ::: "memory");
    __syncthreads();
#pragma unroll
    for (int c = NCH - (NSTG - 1); c < NCH; c++) {
        const uint32_t st = u0 + (uint32_t)((c % NSTG) * STG_BYTES);
        chunk_mma(st, aoff, boff, acc);
    }

    /* epilogue */
    const int row0 = blockIdx.y * 128 + rb + g;
    const int col0 = blockIdx.x * 128 + cb + tig * 2;
    const bool is_v = (MODE == 1) && (blockIdx.x >= 16);
#pragma unroll
    for (int nf = 0; nf < 4; nf++) {
        const int col = col0 + nf * 8;
        const float b0 = bias[col], b1 = bias[col + 1];
#pragma unroll
        for (int mf = 0; mf < 2; mf++) {
            const int r = row0 + mf * 16;
            float2 v0 = make_float2(acc[mf][nf][0] + b0, acc[mf][nf][1] + b1);
            float2 v1 = make_float2(acc[mf][nf][2] + b0, acc[mf][nf][3] + b1);
            if (is_v) {
                *(__half2*)(vh + (size_t)r * DIMM + (col - 2048)) =
                    __float22half2_rn(v0);
                *(__half2*)(vh + (size_t)(r + 8) * DIMM + (col - 2048)) =
                    __float22half2_rn(v1);
            } else {
                *(float2*)(C + (size_t)r * cstr + col)       = v0;
                *(float2*)(C + (size_t)(r + 8) * cstr + col) = v1;
            }
        }
    }
}

/* ---- weight transpose -> fp16: D[c][r] = half(S[r][c]) ---- */
__global__ void transpose_h_kernel(const float* __restrict__ S, __half* __restrict__ D,
                                   int R, int Cc)
{
    __shared__ float t[32][33];
    const int bx = blockIdx.x * 32, by = blockIdx.y * 32;
    const int x = threadIdx.x, y = threadIdx.y;   /* 32 x 8 */
#pragma unroll
    for (int j = 0; j < 32; j += 8)
        t[y + j][x] = S[(size_t)(by + y + j) * Cc + bx + x];
    __syncthreads();
#pragma unroll
    for (int j = 0; j < 32; j += 8)
        D[(size_t)(bx + y + j) * R + by + x] = __float2half_rn(t[x][y + j]);
}

/* ---------------- softmaxes & small kernels (fp32, qkv stride 2048) ---- */

__global__ void q_softmax_kernel(float* __restrict__ qkv)
{
    const int b       = blockIdx.x / (DIMM / 32);
    const int colbase = (blockIdx.x % (DIMM / 32)) * 32;
    const int c = threadIdx.x & 31;
    const int r = threadIdx.x >> 5;   /* 0..31 */
    float* base = qkv + (size_t)b * SS * QKSTR + colbase + c;

    __shared__ float red[32][33];

    float sum = 0.f;
    for (int s = r; s < SS; s += 32)
        sum += __expf(base[(size_t)s * QKSTR]);
    red[r][c] = sum;
    __syncthreads();
    if (r == 0) {
        float t = 0.f;
#pragma unroll
        for (int i = 0; i < 32; i++) t += red[i][c];
        red[0][c] = t;
    }
    __syncthreads();
    const float inv = SCALE_F / red[0][c];

    for (int s = r; s < SS; s += 32) {
        size_t off = (size_t)s * QKSTR;
        base[off] = __expf(base[off]) * inv;
    }
}

__global__ void k_softmax_kernel(float* __restrict__ qkv)
{
    const int row  = blockIdx.x * 8 + (threadIdx.x >> 5);
    const int lane = threadIdx.x & 31;
    float* p = qkv + (size_t)(row / HH) * QKSTR + DIMM + (row % HH) * HDD;

    float e0 = __expf(p[lane]), e1 = __expf(p[lane + 32]);
    float s = e0 + e1;
#pragma unroll
    for (int o = 16; o > 0; o >>= 1)
        s += __shfl_xor_sync(0xFFFFFFFFu, s, o);
    float inv = 1.f / s;
    p[lane]      = e0 * inv;
    p[lane + 32] = e1 * inv;
}

__global__ void ktq_kernel(const float* __restrict__ qkv, float* __restrict__ Apart)
{
    const int bh = blockIdx.x / TSPLIT;
    const int ts = blockIdx.x % TSPLIT;
    const int b = bh / HH, h = bh % HH;
    const int TCHUNK = SS / TSPLIT;   /* 256 */

    __shared__ __align__(16) float ks[32][64];
    __shared__ __align__(16) float qs[32][64];

    const int tid = threadIdx.x;
    const int tc = tid & 15;
    const int tr = tid >> 4;
    const int lr = tid >> 3;
    const int lc = tid & 7;

    float acc[4][4];
#pragma unroll
    for (int i = 0; i < 4; i++)
#pragma unroll
        for (int j = 0; j < 4; j++) acc[i][j] = 0.f;

    const float* base = qkv + ((size_t)b * SS + (size_t)ts * TCHUNK) * QKSTR;

    for (int t0 = 0; t0 < TCHUNK; t0 += 32) {
        const float* qrow = base + (size_t)(t0 + lr) * QKSTR + h * HDD;
        const float* krow = qrow + DIMM;
        *(float4*)&qs[lr][lc * 4]      = *(const float4*)(qrow + lc * 4);
        *(float4*)&qs[lr][lc * 4 + 32] = *(const float4*)(qrow + lc * 4 + 32);
        *(float4*)&ks[lr][lc * 4]      = *(const float4*)(krow + lc * 4);
        *(float4*)&ks[lr][lc * 4 + 32] = *(const float4*)(krow + lc * 4 + 32);
        __syncthreads();
#pragma unroll
        for (int kk = 0; kk < 32; kk++) {
            float kr[4], qr[4];
            *(float4*)kr = *(const float4*)&ks[kk][tr * 4];
            *(float4*)qr = *(const float4*)&qs[kk][tc * 4];
#pragma unroll
            for (int i = 0; i < 4; i++)
#pragma unroll
                for (int j = 0; j < 4; j++)
                    acc[i][j] += kr[i] * qr[j];
        }
        __syncthreads();
    }

    float* outp = Apart + ((size_t)ts * BB * HH + bh) * HDD * HDD;
#pragma unroll
    for (int i = 0; i < 4; i++) {
        float4 v = make_float4(acc[i][0], acc[i][1], acc[i][2], acc[i][3]);
        *(float4*)&outp[(tr * 4 + i) * HDD + tc * 4] = v;
    }
}

__global__ void a_reduce_kernel(const float* __restrict__ Apart, float* __restrict__ A)
{
    const int idx = blockIdx.x * 256 + threadIdx.x;
    const size_t stride = (size_t)BB * HH * HDD * HDD;
    float s = 0.f;
#pragma unroll
    for (int p = 0; p < TSPLIT; p++)
        s += Apart[(size_t)p * stride + idx];
    A[idx] = s;
}

/* ---- B~[b][j][h*64+d] = half(sum_e WprojT[j][h*64+e] * A[b,h,d,e]) ---- */
__global__ void wA_kernel(const __half* __restrict__ WprojT,
                          const float* __restrict__ Amat,
                          __half* __restrict__ btilde)
{
    const int jt = blockIdx.x;         /* 0..15 */
    const int bh = blockIdx.y;         /* 0..127 */
    const int b = bh >> 4, h = bh & 15;

    __shared__ __align__(16) float Xsm[64][68];   /* X[e][d] = A[d][e] */
    __shared__ __align__(16) float Wsm[64][68];   /* W[local j][e]     */

    const int tid = threadIdx.x;
    const int tc = tid & 15;   /* d group */
    const int tr = tid >> 4;   /* j group */

    {
        const float* Ab = Amat + (size_t)bh * (HDD * HDD);
#pragma unroll
        for (int i = 0; i < 16; i++) {
            int idx = i * 256 + tid;
            Xsm[idx & 63][idx >> 6] = Ab[idx];
        }
    }
    {
        const int lr = tid >> 2;
        const int lc = tid & 3;
        const __half* wrow = WprojT + (size_t)(jt * 64 + lr) * KDIM + h * HDD;
#pragma unroll
        for (int m = 0; m < 4; m++) {
            const int cc = (lc + 4 * m) * 4;
            __half2 a = *(const __half2*)(wrow + cc);
            __half2 bb = *(const __half2*)(wrow + cc + 2);
            Wsm[lr][cc + 0] = __low2float(a);
            Wsm[lr][cc + 1] = __high2float(a);
            Wsm[lr][cc + 2] = __low2float(bb);
            Wsm[lr][cc + 3] = __high2float(bb);
        }
    }
    __syncthreads();

    float acc[4][4];
#pragma unroll
    for (int i = 0; i < 4; i++)
#pragma unroll
        for (int j = 0; j < 4; j++) acc[i][j] = 0.f;

#pragma unroll 8
    for (int e = 0; e < 64; e++) {
        float br[4];
        *(float4*)br = *(const float4*)&Xsm[e][tc * 4];
        float wr[4];
#pragma unroll
        for (int i = 0; i < 4; i++) wr[i] = Wsm[tr * 4 + i][e];
#pragma unroll
        for (int i = 0; i < 4; i++)
#pragma unroll
            for (int j = 0; j < 4; j++)
                acc[i][j] += wr[i] * br[j];
    }

#pragma unroll
    for (int i = 0; i < 4; i++) {
        const size_t row = (size_t)b * DIMM + jt * 64 + tr * 4 + i;
        __half* orow = btilde + row * DIMM + h * HDD + tc * 4;
        *(__half2*)(orow)     = __float22half2_rn(make_float2(acc[i][0], acc[i][1]));
        *(__half2*)(orow + 2) = __float22half2_rn(make_float2(acc[i][2], acc[i][3]));
    }
}

/* --------------------------------------------------------------- */
extern "C" void kernel_launch(void* const* d_in, const int* in_sizes, int n_in,
                              void* d_out, int out_size)
{
    (void)in_sizes; (void)n_in; (void)out_size;
    const float* x     = (const float*)d_in[0];
    const float* Wqkv  = (const float*)d_in[1];
    const float* bqkv  = (const float*)d_in[2];
    const float* Wproj = (const float*)d_in[3];
    const float* bproj = (const float*)d_in[4];
    float* out = (float*)d_out;

    float *qkv, *Apart, *Amat;
    __half *vh, *btilde, *WqkvT, *WprojT;
    cudaGetSymbolAddress((void**)&qkv,    g_qkv);
    cudaGetSymbolAddress((void**)&vh,     g_vh);
    cudaGetSymbolAddress((void**)&btilde, g_btilde);
    cudaGetSymbolAddress((void**)&Apart,  g_Apart);
    cudaGetSymbolAddress((void**)&Amat,   g_A);
    cudaGetSymbolAddress((void**)&WqkvT,  g_WqkvT);
    cudaGetSymbolAddress((void**)&WprojT, g_WprojT);

    cudaFuncSetAttribute((const void*)gemm_fp16<1>,
                         cudaFuncAttributeMaxDynamicSharedMemorySize, SMEM_DYN_G);
    cudaFuncSetAttribute((const void*)gemm_fp16<0>,
                         cudaFuncAttributeMaxDynamicSharedMemorySize, SMEM_DYN_G);

    /* 0) weights -> transposed fp16 */
    {
        dim3 blk(32, 8);
        transpose_h_kernel<<<dim3(3 * DIMM / 32, DIMM / 32), blk>>>(Wqkv, WqkvT, DIMM, 3 * DIMM);
        transpose_h_kernel<<<dim3(DIMM / 32, DIMM / 32), blk>>>(Wproj, WprojT, DIMM, DIMM);
    }
    /* 1) qkv: q,k fp32 -> g_qkv (stride 2048); V fp16 -> g_vh */
    gemm_fp16<1><<<dim3(3 * DIMM / 128, BSR / 128), 512, SMEM_DYN_G>>>(
        x, KDIM, WqkvT, 0, bqkv, qkv, QKSTR, vh);
    /* 2) softmaxes (in place on q, k) */
    q_softmax_kernel<<<BB * (DIMM / 32), 1024>>>(qkv);
    k_softmax_kernel<<<(BSR * HH) / 8, 256>>>(qkv);
    /* 3) A = K^T Q per (b,h) */
    ktq_kernel<<<BB * HH * TSPLIT, 256>>>(qkv, Apart);
    a_reduce_kernel<<<(BB * HH * HDD * HDD) / 256, 256>>>(Apart, Amat);
    /* 4) B~ = A (x) Wproj  (fp16) */
    wA_kernel<<<dim3(16, BB * HH), 256>>>(WprojT, Amat, btilde);
    /* 5) out = V @ B~ + bproj  (pure fp16 operands) */
    gemm_fp16<0><<<dim3(DIMM / 128, BSR / 128), 512, SMEM_DYN_G>>>(
        vh, DIMM, btilde, DIMM * DIMM, bproj, out, DIMM, nullptr);
}

// round 12
// speedup vs baseline: 2.1779x; 1.0526x over previous
#include <cuda_runtime.h>
#include <cuda_fp16.h>
#include <cstdint>
#include <math.h>

#define BB   8
#define SS   4096
#define DIMM 1024
#define HH   16
#define HDD  64
#define BSR  (BB * SS)          /* 32768 rows */
#define QKVH 3072               /* fp16 qkv row stride */
#define TSPLIT 16
#define SCALE_F 0.125f          /* 64^-0.5 */
#define KDIM 1024               /* K of both big GEMMs */

/* -------- scratch (device globals: allocation-free rule) -------- */
__device__ __half g_qkvh[(size_t)BSR * QKVH];                      /* 201 MB */
__device__ float  g_qinv[(size_t)BB * DIMM];                       /* 32 KB  */
__device__ __half g_btilde[(size_t)BB * DIMM * DIMM];              /* 16 MB  */
__device__ float  g_Apart[(size_t)TSPLIT * BB * HH * HDD * HDD];   /* 33 MB  */
__device__ float  g_A[(size_t)BB * HH * HDD * HDD];                /* 2 MB   */
__device__ __half g_WqkvT[(size_t)3 * DIMM * DIMM];                /* 6 MB   */
__device__ __half g_WprojT[(size_t)DIMM * DIMM];                   /* 2 MB   */

/* ===== fp16 mma.sync GEMM: 512 thr, tile 128x128, warp tile 32x32,
 * m16n8k16.f32.f16.f16.f32, 8-stage cp.async ring, peeled tail.
 * MODE 1: A fp32 (x) converted fp16 in-kernel; epilogue writes fp16 qkvh.
 * MODE 0: A fp16; fp32 epilogue to C. ===== */

#define BROW  80                      /* smem row stride bytes (32 halfs + pad) */
#define A_STG 10240                   /* 128 rows * 80 B */
#define STG_BYTES 20480               /* A + B per stage */
#define NSTG  8
#define SMEM_DYN_G (NSTG * STG_BYTES) /* 163840 B */
#define NCH   (KDIM / 32)             /* 32 chunks of K=32 */

__device__ __forceinline__ uint32_t smem_u32(const void* p) {
    uint32_t a;
    asm("{ .reg .u64 t; cvta.to.shared.u64 t, %1; cvt.u32.u64 %0, t; }"
        : "=r"(a) : "l"(p));
    return a;
}
__device__ __forceinline__ void cp16(uint32_t dst, const void* src) {
    asm volatile("cp.async.cg.shared.global [%0], [%1], 16;"
                 :: "r"(dst), "l"(src) : "memory");
}
__device__ __forceinline__ uint32_t pack2(float lo, float hi) {
    uint32_t r;
    asm("cvt.rn.f16x2.f32 %0, %1, %2;" : "=r"(r) : "f"(hi), "f"(lo));
    return r;
}
__device__ __forceinline__ void sts16u(uint32_t dst, uint32_t a, uint32_t b,
                                       uint32_t c, uint32_t d) {
    asm volatile("st.shared.v4.b32 [%0], {%1,%2,%3,%4};"
                 :: "r"(dst), "r"(a), "r"(b), "r"(c), "r"(d) : "memory");
}
__device__ __forceinline__ void ldsm4(uint32_t* r, uint32_t addr) {
    asm volatile("ldmatrix.sync.aligned.m8n8.x4.shared.b16 {%0,%1,%2,%3}, [%4];"
                 : "=r"(r[0]), "=r"(r[1]), "=r"(r[2]), "=r"(r[3]) : "r"(addr));
}
__device__ __forceinline__ void mma_f16(float* c, const uint32_t* a, const uint32_t* b) {
    asm volatile("mma.sync.aligned.m16n8k16.row.col.f32.f16.f16.f32 "
                 "{%0,%1,%2,%3}, {%4,%5,%6,%7}, {%8,%9}, {%0,%1,%2,%3};"
                 : "+f"(c[0]), "+f"(c[1]), "+f"(c[2]), "+f"(c[3])
                 : "r"(a[0]), "r"(a[1]), "r"(a[2]), "r"(a[3]),
                   "r"(b[0]), "r"(b[1]));
}

__device__ __forceinline__ void chunk_mma(uint32_t st, const uint32_t* aoff,
                                          const uint32_t* boff,
                                          float acc[2][4][4])
{
#pragma unroll
    for (int ks = 0; ks < 2; ks++) {
        uint32_t av[2][4], bv[2][4];
#pragma unroll
        for (int mf = 0; mf < 2; mf++)
            ldsm4(av[mf], st + aoff[mf] + ks * 32);
#pragma unroll
        for (int p = 0; p < 2; p++)
            ldsm4(bv[p], st + boff[p] + ks * 32);
#pragma unroll
        for (int mf = 0; mf < 2; mf++)
#pragma unroll
            for (int nf = 0; nf < 4; nf++)
                mma_f16(acc[mf][nf], av[mf], &bv[nf >> 1][(nf & 1) * 2]);
    }
}

template<int MODE>
__global__ void __launch_bounds__(512, 1)
gemm_fp16(const void* __restrict__ Ain, int astr,
          const __half* __restrict__ BT, int bstride,
          const float* __restrict__ bias, float* __restrict__ C, int cstr,
          __half* __restrict__ hout)
{
    extern __shared__ __align__(16) char sm[];
    const uint32_t u0 = smem_u32(sm);

    const int tid  = threadIdx.x;
    const int lane = tid & 31;
    const int warp = tid >> 5;
    const int wm   = warp & 3;
    const int wn   = warp >> 2;
    const int g    = lane >> 2;
    const int tig  = lane & 3;

    const int lrow = tid >> 2;
    const int lq   = tid & 3;
    const float*  Ag32 = (const float*)Ain + (size_t)(blockIdx.y * 128 + lrow) * astr + lq * 8;
    const __half* Agh  = (const __half*)Ain + (size_t)(blockIdx.y * 128 + lrow) * astr + lq * 8;
    const __half* Bg   = BT + (size_t)(blockIdx.y >> 5) * (size_t)bstride
                            + (size_t)(blockIdx.x * 128 + lrow) * KDIM + lq * 8;
    const uint32_t dstA = u0 + (uint32_t)(lrow * BROW + lq * 16);
    const uint32_t dstB = dstA + A_STG;

    const int rb = wm * 32;
    const int cb = wn * 32;

    uint32_t aoff[2];
#pragma unroll
    for (int mf = 0; mf < 2; mf++)
        aoff[mf] = (uint32_t)((rb + mf * 16 + (lane & 15)) * BROW + 16 * (lane >> 4));
    uint32_t boff[2];
#pragma unroll
    for (int p = 0; p < 2; p++)
        boff[p] = (uint32_t)(A_STG + (cb + p * 16 + ((lane >> 4) << 3) + (lane & 7)) * BROW
                             + 16 * ((lane >> 3) & 1));

    float acc[2][4][4];
#pragma unroll
    for (int i = 0; i < 2; i++)
#pragma unroll
        for (int j = 0; j < 4; j++)
#pragma unroll
            for (int r = 0; r < 4; r++) acc[i][j][r] = 0.f;

#pragma unroll
    for (int s = 0; s < NSTG - 1; s++) {
        const uint32_t sb = (uint32_t)(s * STG_BYTES);
        const int k0 = s * 32;
        if (MODE == 1) {
            float4 v0 = *(const float4*)(Ag32 + k0);
            float4 v1 = *(const float4*)(Ag32 + k0 + 4);
            sts16u(dstA + sb, pack2(v0.x, v0.y), pack2(v0.z, v0.w),
                   pack2(v1.x, v1.y), pack2(v1.z, v1.w));
        } else {
            cp16(dstA + sb, Agh + k0);
        }
        cp16(dstB + sb, Bg + k0);
        asm volatile("cp.async.commit_group;" ::: "memory");
    }
    asm volatile("cp.async.wait_group 6;" ::: "memory");
    __syncthreads();

    for (int c = 0; c < NCH - (NSTG - 1); c++) {
        const uint32_t sb = (uint32_t)(((c + NSTG - 1) % NSTG) * STG_BYTES);
        const int k0n = (c + NSTG - 1) * 32;
        float4 pa0, pa1;
        if (MODE == 1) {
            pa0 = *(const float4*)(Ag32 + k0n);
            pa1 = *(const float4*)(Ag32 + k0n + 4);
        } else {
            cp16(dstA + sb, Agh + k0n);
        }
        cp16(dstB + sb, Bg + k0n);
        asm volatile("cp.async.commit_group;" ::: "memory");

        const uint32_t st = u0 + (uint32_t)((c % NSTG) * STG_BYTES);
        chunk_mma(st, aoff, boff, acc);

        if (MODE == 1)
            sts16u(dstA + sb, pack2(pa0.x, pa0.y), pack2(pa0.z, pa0.w),
                   pack2(pa1.x, pa1.y), pack2(pa1.z, pa1.w));
        asm volatile("cp.async.wait_group 6;" ::: "memory");
        __syncthreads();
    }

    asm volatile("cp.async.wait_group 0;" ::: "memory");
    __syncthreads();
#pragma unroll
    for (int c = NCH - (NSTG - 1); c < NCH; c++) {
        const uint32_t st = u0 + (uint32_t)((c % NSTG) * STG_BYTES);
        chunk_mma(st, aoff, boff, acc);
    }

    const int row0 = blockIdx.y * 128 + rb + g;
    const int col0 = blockIdx.x * 128 + cb + tig * 2;
#pragma unroll
    for (int nf = 0; nf < 4; nf++) {
        const int col = col0 + nf * 8;
        const float b0 = bias[col], b1 = bias[col + 1];
#pragma unroll
        for (int mf = 0; mf < 2; mf++) {
            const int r = row0 + mf * 16;
            float2 v0 = make_float2(acc[mf][nf][0] + b0, acc[mf][nf][1] + b1);
            float2 v1 = make_float2(acc[mf][nf][2] + b0, acc[mf][nf][3] + b1);
            if (MODE == 1) {
                *(__half2*)(hout + (size_t)r * QKVH + col)       = __float22half2_rn(v0);
                *(__half2*)(hout + (size_t)(r + 8) * QKVH + col) = __float22half2_rn(v1);
            } else {
                *(float2*)(C + (size_t)r * cstr + col)       = v0;
                *(float2*)(C + (size_t)(r + 8) * cstr + col) = v1;
            }
        }
    }
}

/* ---- weight transpose -> fp16: D[c][r] = half(S[r][c]) ---- */
__global__ void transpose_h_kernel(const float* __restrict__ S, __half* __restrict__ D,
                                   int R, int Cc)
{
    __shared__ float t[32][33];
    const int bx = blockIdx.x * 32, by = blockIdx.y * 32;
    const int x = threadIdx.x, y = threadIdx.y;
#pragma unroll
    for (int j = 0; j < 32; j += 8)
        t[y + j][x] = S[(size_t)(by + y + j) * Cc + bx + x];
    __syncthreads();
#pragma unroll
    for (int j = 0; j < 32; j += 8)
        D[(size_t)(bx + y + j) * R + by + x] = __float2half_rn(t[x][y + j]);
}

/* ---- q column sums: qinv[b][col] = SCALE / sum_s exp(q) ---- */
__global__ void q_sum_kernel(const __half* __restrict__ qkvh, float* __restrict__ qinv)
{
    const int b       = blockIdx.x / (DIMM / 32);
    const int colbase = (blockIdx.x % (DIMM / 32)) * 32;
    const int c = threadIdx.x & 31;
    const int r = threadIdx.x >> 5;   /* 0..31 */
    const __half* base = qkvh + (size_t)b * SS * QKVH + colbase + c;

    __shared__ float red[32][33];

    float sum = 0.f;
    for (int s = r; s < SS; s += 32)
        sum += __expf(__half2float(base[(size_t)s * QKVH]));
    red[r][c] = sum;
    __syncthreads();
    if (r == 0) {
        float t = 0.f;
#pragma unroll
        for (int i = 0; i < 32; i++) t += red[i][c];
        qinv[b * DIMM + colbase + c] = SCALE_F / t;
    }
}

/* ---- ktq with fused q-normalize + k row-softmax (fp16 inputs) ---- */
__global__ void ktq_kernel(const __half* __restrict__ qkvh,
                           const float* __restrict__ qinv,
                           float* __restrict__ Apart)
{
    const int bh = blockIdx.x / TSPLIT;
    const int ts = blockIdx.x % TSPLIT;
    const int b = bh / HH, h = bh % HH;
    const int TCHUNK = SS / TSPLIT;   /* 256 */

    __shared__ __align__(16) float ks[32][64];
    __shared__ __align__(16) float qs[32][64];
    __shared__ float inv_sm[64];

    const int tid = threadIdx.x;
    const int tc = tid & 15;
    const int tr = tid >> 4;
    const int lr = tid >> 3;   /* 0..31 row */
    const int lc = tid & 7;    /* 8 halfs each */

    if (tid < 64) inv_sm[tid] = qinv[b * DIMM + h * HDD + tid];
    __syncthreads();

    float acc[4][4];
#pragma unroll
    for (int i = 0; i < 4; i++)
#pragma unroll
        for (int j = 0; j < 4; j++) acc[i][j] = 0.f;

    const __half* base = qkvh + ((size_t)b * SS + (size_t)ts * TCHUNK) * QKVH;

    for (int t0 = 0; t0 < TCHUNK; t0 += 32) {
        const __half* qrow = base + (size_t)(t0 + lr) * QKVH + h * HDD;
        const __half* krow = qrow + DIMM;
        /* q: exp * col-inv */
        {
            const __half2* qp = (const __half2*)(qrow + lc * 8);
#pragma unroll
            for (int j = 0; j < 4; j++) {
                float2 f = __half22float2(qp[j]);
                qs[lr][lc * 8 + 2 * j]     = __expf(f.x) * inv_sm[lc * 8 + 2 * j];
                qs[lr][lc * 8 + 2 * j + 1] = __expf(f.y) * inv_sm[lc * 8 + 2 * j + 1];
            }
        }
        /* k: row softmax over 64 (8 lanes x 8 values) */
        {
            const __half2* kp = (const __half2*)(krow + lc * 8);
            float e[8];
            float s = 0.f;
#pragma unroll
            for (int j = 0; j < 4; j++) {
                float2 f = __half22float2(kp[j]);
                e[2 * j]     = __expf(f.x);
                e[2 * j + 1] = __expf(f.y);
                s += e[2 * j] + e[2 * j + 1];
            }
#pragma unroll
            for (int o = 4; o > 0; o >>= 1)
                s += __shfl_xor_sync(0xFFFFFFFFu, s, o);
            const float rinv = 1.f / s;
#pragma unroll
            for (int j = 0; j < 8; j++)
                ks[lr][lc * 8 + j] = e[j] * rinv;
        }
        __syncthreads();
#pragma unroll
        for (int kk = 0; kk < 32; kk++) {
            float kr[4], qr[4];
            *(float4*)kr = *(const float4*)&ks[kk][tr * 4];
            *(float4*)qr = *(const float4*)&qs[kk][tc * 4];
#pragma unroll
            for (int i = 0; i < 4; i++)
#pragma unroll
                for (int j = 0; j < 4; j++)
                    acc[i][j] += kr[i] * qr[j];
        }
        __syncthreads();
    }

    float* outp = Apart + ((size_t)ts * BB * HH + bh) * HDD * HDD;
#pragma unroll
    for (int i = 0; i < 4; i++) {
        float4 v = make_float4(acc[i][0], acc[i][1], acc[i][2], acc[i][3]);
        *(float4*)&outp[(tr * 4 + i) * HDD + tc * 4] = v;
    }
}

__global__ void a_reduce_kernel(const float* __restrict__ Apart, float* __restrict__ A)
{
    const int idx = blockIdx.x * 256 + threadIdx.x;
    const size_t stride = (size_t)BB * HH * HDD * HDD;
    float s = 0.f;
#pragma unroll
    for (int p = 0; p < TSPLIT; p++)
        s += Apart[(size_t)p * stride + idx];
    A[idx] = s;
}

/* ---- B~[b][j][h*64+d] = half(sum_e WprojT[j][h*64+e] * A[b,h,d,e]) ---- */
__global__ void wA_kernel(const __half* __restrict__ WprojT,
                          const float* __restrict__ Amat,
                          __half* __restrict__ btilde)
{
    const int jt = blockIdx.x;
    const int bh = blockIdx.y;
    const int b = bh >> 4, h = bh & 15;

    __shared__ __align__(16) float Xsm[64][68];
    __shared__ __align__(16) float Wsm[64][68];

    const int tid = threadIdx.x;
    const int tc = tid & 15;
    const int tr = tid >> 4;

    {
        const float* Ab = Amat + (size_t)bh * (HDD * HDD);
#pragma unroll
        for (int i = 0; i < 16; i++) {
            int idx = i * 256 + tid;
            Xsm[idx & 63][idx >> 6] = Ab[idx];
        }
    }
    {
        const int lr = tid >> 2;
        const int lc = tid & 3;
        const __half* wrow = WprojT + (size_t)(jt * 64 + lr) * KDIM + h * HDD;
#pragma unroll
        for (int m = 0; m < 4; m++) {
            const int cc = (lc + 4 * m) * 4;
            __half2 a = *(const __half2*)(wrow + cc);
            __half2 bb = *(const __half2*)(wrow + cc + 2);
            Wsm[lr][cc + 0] = __low2float(a);
            Wsm[lr][cc + 1] = __high2float(a);
            Wsm[lr][cc + 2] = __low2float(bb);
            Wsm[lr][cc + 3] = __high2float(bb);
        }
    }
    __syncthreads();

    float acc[4][4];
#pragma unroll
    for (int i = 0; i < 4; i++)
#pragma unroll
        for (int j = 0; j < 4; j++) acc[i][j] = 0.f;

#pragma unroll 8
    for (int e = 0; e < 64; e++) {
        float br[4];
        *(float4*)br = *(const float4*)&Xsm[e][tc * 4];
        float wr[4];
#pragma unroll
        for (int i = 0; i < 4; i++) wr[i] = Wsm[tr * 4 + i][e];
#pragma unroll
        for (int i = 0; i < 4; i++)
#pragma unroll
            for (int j = 0; j < 4; j++)
                acc[i][j] += wr[i] * br[j];
    }

#pragma unroll
    for (int i = 0; i < 4; i++) {
        const size_t row = (size_t)b * DIMM + jt * 64 + tr * 4 + i;
        __half* orow = btilde + row * DIMM + h * HDD + tc * 4;
        *(__half2*)(orow)     = __float22half2_rn(make_float2(acc[i][0], acc[i][1]));
        *(__half2*)(orow + 2) = __float22half2_rn(make_float2(acc[i][2], acc[i][3]));
    }
}

/* --------------------------------------------------------------- */
extern "C" void kernel_launch(void* const* d_in, const int* in_sizes, int n_in,
                              void* d_out, int out_size)
{
    (void)in_sizes; (void)n_in; (void)out_size;
    const float* x     = (const float*)d_in[0];
    const float* Wqkv  = (const float*)d_in[1];
    const float* bqkv  = (const float*)d_in[2];
    const float* Wproj = (const float*)d_in[3];
    const float* bproj = (const float*)d_in[4];
    float* out = (float*)d_out;

    float *Apart, *Amat, *qinv;
    __half *qkvh, *btilde, *WqkvT, *WprojT;
    cudaGetSymbolAddress((void**)&qkvh,   g_qkvh);
    cudaGetSymbolAddress((void**)&qinv,   g_qinv);
    cudaGetSymbolAddress((void**)&btilde, g_btilde);
    cudaGetSymbolAddress((void**)&Apart,  g_Apart);
    cudaGetSymbolAddress((void**)&Amat,   g_A);
    cudaGetSymbolAddress((void**)&WqkvT,  g_WqkvT);
    cudaGetSymbolAddress((void**)&WprojT, g_WprojT);

    cudaFuncSetAttribute((const void*)gemm_fp16<1>,
                         cudaFuncAttributeMaxDynamicSharedMemorySize, SMEM_DYN_G);
    cudaFuncSetAttribute((const void*)gemm_fp16<0>,
                         cudaFuncAttributeMaxDynamicSharedMemorySize, SMEM_DYN_G);

    /* 0) weights -> transposed fp16 */
    {
        dim3 blk(32, 8);
        transpose_h_kernel<<<dim3(3 * DIMM / 32, DIMM / 32), blk>>>(Wqkv, WqkvT, DIMM, 3 * DIMM);
        transpose_h_kernel<<<dim3(DIMM / 32, DIMM / 32), blk>>>(Wproj, WprojT, DIMM, DIMM);
    }
    /* 1) qkvh = fp16(x @ Wqkv + bqkv), one buffer stride 3072 */
    gemm_fp16<1><<<dim3(3 * DIMM / 128, BSR / 128), 512, SMEM_DYN_G>>>(
        x, KDIM, WqkvT, 0, bqkv, nullptr, 0, qkvh);
    /* 2) q column-sum only (normalization applied inside ktq) */
    q_sum_kernel<<<BB * (DIMM / 32), 1024>>>(qkvh, qinv);
    /* 3) A = K^T Q with fused q-normalize + k row-softmax */
    ktq_kernel<<<BB * HH * TSPLIT, 256>>>(qkvh, qinv, Apart);
    a_reduce_kernel<<<(BB * HH * HDD * HDD) / 256, 256>>>(Apart, Amat);
    /* 4) B~ = A (x) Wproj  (fp16) */
    wA_kernel<<<dim3(16, BB * HH), 256>>>(WprojT, Amat, btilde);
    /* 5) out = V @ B~ + bproj  (V = qkvh cols 2048.., stride 3072) */
    gemm_fp16<0><<<dim3(DIMM / 128, BSR / 128), 512, SMEM_DYN_G>>>(
        (const void*)(qkvh + 2048), QKVH, btilde, DIMM * DIMM, bproj, out, DIMM, nullptr);
}

// round 13
// speedup vs baseline: 2.2450x; 1.0308x over previous
#include <cuda_runtime.h>
#include <cuda_fp16.h>
#include <cstdint>
#include <math.h>

#define BB   8
#define SS   4096
#define DIMM 1024
#define HH   16
#define HDD  64
#define BSR  (BB * SS)          /* 32768 rows */
#define QKVH 3072               /* fp16 qkv row stride */
#define TSPLIT 16
#define SCALE_F 0.125f          /* 64^-0.5 */
#define KDIM 1024               /* K of both big GEMMs */

/* -------- scratch (device globals: allocation-free rule) -------- */
__device__ __half g_qkvh[(size_t)BSR * QKVH];                      /* 201 MB */
__device__ float  g_qinv[(size_t)BB * DIMM];                       /* 32 KB  */
__device__ __half g_btilde[(size_t)BB * DIMM * DIMM];              /* 16 MB  */
__device__ float  g_Apart[(size_t)TSPLIT * BB * HH * HDD * HDD];   /* 33 MB  */
__device__ float  g_A[(size_t)BB * HH * HDD * HDD];                /* 2 MB   */
__device__ __half g_WqkvT[(size_t)3 * DIMM * DIMM];                /* 6 MB   */
__device__ __half g_WprojT[(size_t)DIMM * DIMM];                   /* 2 MB   */

/* ===== fp16 mma.sync GEMM (unchanged from R12) ===== */

#define BROW  80
#define A_STG 10240
#define STG_BYTES 20480
#define NSTG  8
#define SMEM_DYN_G (NSTG * STG_BYTES)
#define NCH   (KDIM / 32)

__device__ __forceinline__ uint32_t smem_u32(const void* p) {
    uint32_t a;
    asm("{ .reg .u64 t; cvta.to.shared.u64 t, %1; cvt.u32.u64 %0, t; }"
        : "=r"(a) : "l"(p));
    return a;
}
__device__ __forceinline__ void cp16(uint32_t dst, const void* src) {
    asm volatile("cp.async.cg.shared.global [%0], [%1], 16;"
                 :: "r"(dst), "l"(src) : "memory");
}
__device__ __forceinline__ uint32_t pack2(float lo, float hi) {
    uint32_t r;
    asm("cvt.rn.f16x2.f32 %0, %1, %2;" : "=r"(r) : "f"(hi), "f"(lo));
    return r;
}
__device__ __forceinline__ void sts16u(uint32_t dst, uint32_t a, uint32_t b,
                                       uint32_t c, uint32_t d) {
    asm volatile("st.shared.v4.b32 [%0], {%1,%2,%3,%4};"
                 :: "r"(dst), "r"(a), "r"(b), "r"(c), "r"(d) : "memory");
}
__device__ __forceinline__ void ldsm4(uint32_t* r, uint32_t addr) {
    asm volatile("ldmatrix.sync.aligned.m8n8.x4.shared.b16 {%0,%1,%2,%3}, [%4];"
                 : "=r"(r[0]), "=r"(r[1]), "=r"(r[2]), "=r"(r[3]) : "r"(addr));
}
__device__ __forceinline__ void mma_f16(float* c, const uint32_t* a, const uint32_t* b) {
    asm volatile("mma.sync.aligned.m16n8k16.row.col.f32.f16.f16.f32 "
                 "{%0,%1,%2,%3}, {%4,%5,%6,%7}, {%8,%9}, {%0,%1,%2,%3};"
                 : "+f"(c[0]), "+f"(c[1]), "+f"(c[2]), "+f"(c[3])
                 : "r"(a[0]), "r"(a[1]), "r"(a[2]), "r"(a[3]),
                   "r"(b[0]), "r"(b[1]));
}

__device__ __forceinline__ void chunk_mma(uint32_t st, const uint32_t* aoff,
                                          const uint32_t* boff,
                                          float acc[2][4][4])
{
#pragma unroll
    for (int ks = 0; ks < 2; ks++) {
        uint32_t av[2][4], bv[2][4];
#pragma unroll
        for (int mf = 0; mf < 2; mf++)
            ldsm4(av[mf], st + aoff[mf] + ks * 32);
#pragma unroll
        for (int p = 0; p < 2; p++)
            ldsm4(bv[p], st + boff[p] + ks * 32);
#pragma unroll
        for (int mf = 0; mf < 2; mf++)
#pragma unroll
            for (int nf = 0; nf < 4; nf++)
                mma_f16(acc[mf][nf], av[mf], &bv[nf >> 1][(nf & 1) * 2]);
    }
}

template<int MODE>
__global__ void __launch_bounds__(512, 1)
gemm_fp16(const void* __restrict__ Ain, int astr,
          const __half* __restrict__ BT, int bstride,
          const float* __restrict__ bias, float* __restrict__ C, int cstr,
          __half* __restrict__ hout)
{
    extern __shared__ __align__(16) char sm[];
    const uint32_t u0 = smem_u32(sm);

    const int tid  = threadIdx.x;
    const int lane = tid & 31;
    const int warp = tid >> 5;
    const int wm   = warp & 3;
    const int wn   = warp >> 2;
    const int g    = lane >> 2;
    const int tig  = lane & 3;

    const int lrow = tid >> 2;
    const int lq   = tid & 3;
    const float*  Ag32 = (const float*)Ain + (size_t)(blockIdx.y * 128 + lrow) * astr + lq * 8;
    const __half* Agh  = (const __half*)Ain + (size_t)(blockIdx.y * 128 + lrow) * astr + lq * 8;
    const __half* Bg   = BT + (size_t)(blockIdx.y >> 5) * (size_t)bstride
                            + (size_t)(blockIdx.x * 128 + lrow) * KDIM + lq * 8;
    const uint32_t dstA = u0 + (uint32_t)(lrow * BROW + lq * 16);
    const uint32_t dstB = dstA + A_STG;

    const int rb = wm * 32;
    const int cb = wn * 32;

    uint32_t aoff[2];
#pragma unroll
    for (int mf = 0; mf < 2; mf++)
        aoff[mf] = (uint32_t)((rb + mf * 16 + (lane & 15)) * BROW + 16 * (lane >> 4));
    uint32_t boff[2];
#pragma unroll
    for (int p = 0; p < 2; p++)
        boff[p] = (uint32_t)(A_STG + (cb + p * 16 + ((lane >> 4) << 3) + (lane & 7)) * BROW
                             + 16 * ((lane >> 3) & 1));

    float acc[2][4][4];
#pragma unroll
    for (int i = 0; i < 2; i++)
#pragma unroll
        for (int j = 0; j < 4; j++)
#pragma unroll
            for (int r = 0; r < 4; r++) acc[i][j][r] = 0.f;

#pragma unroll
    for (int s = 0; s < NSTG - 1; s++) {
        const uint32_t sb = (uint32_t)(s * STG_BYTES);
        const int k0 = s * 32;
        if (MODE == 1) {
            float4 v0 = *(const float4*)(Ag32 + k0);
            float4 v1 = *(const float4*)(Ag32 + k0 + 4);
            sts16u(dstA + sb, pack2(v0.x, v0.y), pack2(v0.z, v0.w),
                   pack2(v1.x, v1.y), pack2(v1.z, v1.w));
        } else {
            cp16(dstA + sb, Agh + k0);
        }
        cp16(dstB + sb, Bg + k0);
        asm volatile("cp.async.commit_group;" ::: "memory");
    }
    asm volatile("cp.async.wait_group 6;" ::: "memory");
    __syncthreads();

    for (int c = 0; c < NCH - (NSTG - 1); c++) {
        const uint32_t sb = (uint32_t)(((c + NSTG - 1) % NSTG) * STG_BYTES);
        const int k0n = (c + NSTG - 1) * 32;
        float4 pa0, pa1;
        if (MODE == 1) {
            pa0 = *(const float4*)(Ag32 + k0n);
            pa1 = *(const float4*)(Ag32 + k0n + 4);
        } else {
            cp16(dstA + sb, Agh + k0n);
        }
        cp16(dstB + sb, Bg + k0n);
        asm volatile("cp.async.commit_group;" ::: "memory");

        const uint32_t st = u0 + (uint32_t)((c % NSTG) * STG_BYTES);
        chunk_mma(st, aoff, boff, acc);

        if (MODE == 1)
            sts16u(dstA + sb, pack2(pa0.x, pa0.y), pack2(pa0.z, pa0.w),
                   pack2(pa1.x, pa1.y), pack2(pa1.z, pa1.w));
        asm volatile("cp.async.wait_group 6;" ::: "memory");
        __syncthreads();
    }

    asm volatile("cp.async.wait_group 0;" ::: "memory");
    __syncthreads();
#pragma unroll
    for (int c = NCH - (NSTG - 1); c < NCH; c++) {
        const uint32_t st = u0 + (uint32_t)((c % NSTG) * STG_BYTES);
        chunk_mma(st, aoff, boff, acc);
    }

    const int row0 = blockIdx.y * 128 + rb + g;
    const int col0 = blockIdx.x * 128 + cb + tig * 2;
#pragma unroll
    for (int nf = 0; nf < 4; nf++) {
        const int col = col0 + nf * 8;
        const float b0 = bias[col], b1 = bias[col + 1];
#pragma unroll
        for (int mf = 0; mf < 2; mf++) {
            const int r = row0 + mf * 16;
            float2 v0 = make_float2(acc[mf][nf][0] + b0, acc[mf][nf][1] + b1);
            float2 v1 = make_float2(acc[mf][nf][2] + b0, acc[mf][nf][3] + b1);
            if (MODE == 1) {
                *(__half2*)(hout + (size_t)r * QKVH + col)       = __float22half2_rn(v0);
                *(__half2*)(hout + (size_t)(r + 8) * QKVH + col) = __float22half2_rn(v1);
            } else {
                *(float2*)(C + (size_t)r * cstr + col)       = v0;
                *(float2*)(C + (size_t)(r + 8) * cstr + col) = v1;
            }
        }
    }
}

/* ---- weight transpose -> fp16 ---- */
__global__ void transpose_h_kernel(const float* __restrict__ S, __half* __restrict__ D,
                                   int R, int Cc)
{
    __shared__ float t[32][33];
    const int bx = blockIdx.x * 32, by = blockIdx.y * 32;
    const int x = threadIdx.x, y = threadIdx.y;
#pragma unroll
    for (int j = 0; j < 32; j += 8)
        t[y + j][x] = S[(size_t)(by + y + j) * Cc + bx + x];
    __syncthreads();
#pragma unroll
    for (int j = 0; j < 32; j += 8)
        D[(size_t)(bx + y + j) * R + by + x] = __float2half_rn(t[x][y + j]);
}

/* ---- q column sums ---- */
__global__ void q_sum_kernel(const __half* __restrict__ qkvh, float* __restrict__ qinv)
{
    const int b       = blockIdx.x / (DIMM / 32);
    const int colbase = (blockIdx.x % (DIMM / 32)) * 32;
    const int c = threadIdx.x & 31;
    const int r = threadIdx.x >> 5;
    const __half* base = qkvh + (size_t)b * SS * QKVH + colbase + c;

    __shared__ float red[32][33];

    float sum = 0.f;
    for (int s = r; s < SS; s += 32)
        sum += __expf(__half2float(base[(size_t)s * QKVH]));
    red[r][c] = sum;
    __syncthreads();
    if (r == 0) {
        float t = 0.f;
#pragma unroll
        for (int i = 0; i < 32; i++) t += red[i][c];
        qinv[b * DIMM + colbase + c] = SCALE_F / t;
    }
}

/* ---- ktq on tensor cores: A[d][e] = sum_t k'[t,d] * q'[t,e]
 * staging applies exp/normalize and writes TRANSPOSED fp16 tiles;
 * mma uses the proven row-major ldmatrix recipe on [d][t] layout.
 * 256 thr = 8 warps (2x4 of 32x16); t chunks of 64. ---- */
#define KTSTR 72   /* half stride of transposed tiles (16B-aligned rows) */
__global__ void __launch_bounds__(256, 4)
ktq_kernel(const __half* __restrict__ qkvh,
           const float* __restrict__ qinv,
           float* __restrict__ Apart)
{
    const int bh = blockIdx.x / TSPLIT;
    const int ts = blockIdx.x % TSPLIT;
    const int b = bh / HH, h = bh % HH;
    const int TCHUNK = SS / TSPLIT;   /* 256 */

    __shared__ __align__(16) __half ksT[64][KTSTR];
    __shared__ __align__(16) __half qsT[64][KTSTR];
    __shared__ float inv_sm[64];

    const int tid  = threadIdx.x;
    const int lane = tid & 31;
    const int warp = tid >> 5;
    const int wm   = warp & 1;          /* rb = wm*32 (d) */
    const int wn   = warp >> 1;         /* cb = wn*16 (e) */
    const int rb   = wm * 32;
    const int cb   = wn * 16;

    const uint32_t ubk = smem_u32(&ksT[0][0]);
    const uint32_t ubq = smem_u32(&qsT[0][0]);
    uint32_t aoff[2];
#pragma unroll
    for (int mf = 0; mf < 2; mf++)
        aoff[mf] = ubk + (uint32_t)(((rb + mf * 16 + (lane & 15)) * KTSTR
                                     + 8 * (lane >> 4)) * 2);
    const uint32_t boff = ubq + (uint32_t)(((cb + ((lane >> 4) << 3) + (lane & 7)) * KTSTR
                                            + 8 * ((lane >> 3) & 1)) * 2);

    if (tid < 64) inv_sm[tid] = qinv[b * DIMM + h * HDD + tid];
    __syncthreads();

    float acc[2][2][4];
#pragma unroll
    for (int i = 0; i < 2; i++)
#pragma unroll
        for (int j = 0; j < 2; j++)
#pragma unroll
            for (int r = 0; r < 4; r++) acc[i][j][r] = 0.f;

    const int t4  = tid >> 2;   /* 0..63 local t */
    const int c16 = tid & 3;    /* 16 d/e values each */

    for (int t0 = 0; t0 < TCHUNK; t0 += 64) {
        const __half2* qrow = (const __half2*)(qkvh
            + ((size_t)b * SS + (size_t)ts * TCHUNK + t0 + t4) * QKVH + h * HDD + c16 * 16);
        const __half2* krow = (const __half2*)((const __half*)qrow + DIMM);
        /* q: exp * col-inv, store transposed */
#pragma unroll
        for (int m = 0; m < 8; m++) {
            float2 f = __half22float2(qrow[m]);
            const int d0 = c16 * 16 + 2 * m;
            qsT[d0][t4]     = __float2half_rn(__expf(f.x) * inv_sm[d0]);
            qsT[d0 + 1][t4] = __float2half_rn(__expf(f.y) * inv_sm[d0 + 1]);
        }
        /* k: row softmax over 64 (4 lanes x 16), store transposed */
        {
            float e[16];
            float s = 0.f;
#pragma unroll
            for (int m = 0; m < 8; m++) {
                float2 f = __half22float2(krow[m]);
                e[2 * m]     = __expf(f.x);
                e[2 * m + 1] = __expf(f.y);
                s += e[2 * m] + e[2 * m + 1];
            }
            s += __shfl_xor_sync(0xFFFFFFFFu, s, 1);
            s += __shfl_xor_sync(0xFFFFFFFFu, s, 2);
            const float rinv = 1.f / s;
#pragma unroll
            for (int j = 0; j < 16; j++)
                ksT[c16 * 16 + j][t4] = __float2half_rn(e[j] * rinv);
        }
        __syncthreads();

#pragma unroll
        for (int ks = 0; ks < 4; ks++) {
            uint32_t av[2][4], bv[4];
            ldsm4(av[0], aoff[0] + ks * 32);
            ldsm4(av[1], aoff[1] + ks * 32);
            ldsm4(bv, boff + ks * 32);
#pragma unroll
            for (int mf = 0; mf < 2; mf++)
#pragma unroll
                for (int nf = 0; nf < 2; nf++)
                    mma_f16(acc[mf][nf], av[mf], &bv[nf * 2]);
        }
        __syncthreads();
    }

    const int g   = lane >> 2;
    const int tig = lane & 3;
    float* outp = Apart + ((size_t)ts * BB * HH + bh) * (HDD * HDD);
#pragma unroll
    for (int nf = 0; nf < 2; nf++) {
        const int col = cb + tig * 2 + nf * 8;
#pragma unroll
        for (int mf = 0; mf < 2; mf++) {
            const int r = rb + g + mf * 16;
            *(float2*)&outp[r * HDD + col] =
                make_float2(acc[mf][nf][0], acc[mf][nf][1]);
            *(float2*)&outp[(r + 8) * HDD + col] =
                make_float2(acc[mf][nf][2], acc[mf][nf][3]);
        }
    }
}

__global__ void a_reduce_kernel(const float* __restrict__ Apart, float* __restrict__ A)
{
    const int idx = blockIdx.x * 256 + threadIdx.x;
    const size_t stride = (size_t)BB * HH * HDD * HDD;
    float s = 0.f;
#pragma unroll
    for (int p = 0; p < TSPLIT; p++)
        s += Apart[(size_t)p * stride + idx];
    A[idx] = s;
}

/* ---- B~[b][j][h*64+d] = half(sum_e WprojT[j][h*64+e] * A[b,h,d,e]) ---- */
__global__ void wA_kernel(const __half* __restrict__ WprojT,
                          const float* __restrict__ Amat,
                          __half* __restrict__ btilde)
{
    const int jt = blockIdx.x;
    const int bh = blockIdx.y;
    const int b = bh >> 4, h = bh & 15;

    __shared__ __align__(16) float Xsm[64][68];
    __shared__ __align__(16) float Wsm[64][68];

    const int tid = threadIdx.x;
    const int tc = tid & 15;
    const int tr = tid >> 4;

    {
        const float* Ab = Amat + (size_t)bh * (HDD * HDD);
#pragma unroll
        for (int i = 0; i < 16; i++) {
            int idx = i * 256 + tid;
            Xsm[idx & 63][idx >> 6] = Ab[idx];
        }
    }
    {
        const int lr = tid >> 2;
        const int lc = tid & 3;
        const __half* wrow = WprojT + (size_t)(jt * 64 + lr) * KDIM + h * HDD;
#pragma unroll
        for (int m = 0; m < 4; m++) {
            const int cc = (lc + 4 * m) * 4;
            __half2 a = *(const __half2*)(wrow + cc);
            __half2 bb = *(const __half2*)(wrow + cc + 2);
            Wsm[lr][cc + 0] = __low2float(a);
            Wsm[lr][cc + 1] = __high2float(a);
            Wsm[lr][cc + 2] = __low2float(bb);
            Wsm[lr][cc + 3] = __high2float(bb);
        }
    }
    __syncthreads();

    float acc[4][4];
#pragma unroll
    for (int i = 0; i < 4; i++)
#pragma unroll
        for (int j = 0; j < 4; j++) acc[i][j] = 0.f;

#pragma unroll 8
    for (int e = 0; e < 64; e++) {
        float br[4];
        *(float4*)br = *(const float4*)&Xsm[e][tc * 4];
        float wr[4];
#pragma unroll
        for (int i = 0; i < 4; i++) wr[i] = Wsm[tr * 4 + i][e];
#pragma unroll
        for (int i = 0; i < 4; i++)
#pragma unroll
            for (int j = 0; j < 4; j++)
                acc[i][j] += wr[i] * br[j];
    }

#pragma unroll
    for (int i = 0; i < 4; i++) {
        const size_t row = (size_t)b * DIMM + jt * 64 + tr * 4 + i;
        __half* orow = btilde + row * DIMM + h * HDD + tc * 4;
        *(__half2*)(orow)     = __float22half2_rn(make_float2(acc[i][0], acc[i][1]));
        *(__half2*)(orow + 2) = __float22half2_rn(make_float2(acc[i][2], acc[i][3]));
    }
}

/* --------------------------------------------------------------- */
extern "C" void kernel_launch(void* const* d_in, const int* in_sizes, int n_in,
                              void* d_out, int out_size)
{
    (void)in_sizes; (void)n_in; (void)out_size;
    const float* x     = (const float*)d_in[0];
    const float* Wqkv  = (const float*)d_in[1];
    const float* bqkv  = (const float*)d_in[2];
    const float* Wproj = (const float*)d_in[3];
    const float* bproj = (const float*)d_in[4];
    float* out = (float*)d_out;

    float *Apart, *Amat, *qinv;
    __half *qkvh, *btilde, *WqkvT, *WprojT;
    cudaGetSymbolAddress((void**)&qkvh,   g_qkvh);
    cudaGetSymbolAddress((void**)&qinv,   g_qinv);
    cudaGetSymbolAddress((void**)&btilde, g_btilde);
    cudaGetSymbolAddress((void**)&Apart,  g_Apart);
    cudaGetSymbolAddress((void**)&Amat,   g_A);
    cudaGetSymbolAddress((void**)&WqkvT,  g_WqkvT);
    cudaGetSymbolAddress((void**)&WprojT, g_WprojT);

    cudaFuncSetAttribute((const void*)gemm_fp16<1>,
                         cudaFuncAttributeMaxDynamicSharedMemorySize, SMEM_DYN_G);
    cudaFuncSetAttribute((const void*)gemm_fp16<0>,
                         cudaFuncAttributeMaxDynamicSharedMemorySize, SMEM_DYN_G);

    /* 0) weights -> transposed fp16 */
    {
        dim3 blk(32, 8);
        transpose_h_kernel<<<dim3(3 * DIMM / 32, DIMM / 32), blk>>>(Wqkv, WqkvT, DIMM, 3 * DIMM);
        transpose_h_kernel<<<dim3(DIMM / 32, DIMM / 32), blk>>>(Wproj, WprojT, DIMM, DIMM);
    }
    /* 1) qkvh = fp16(x @ Wqkv + bqkv) */
    gemm_fp16<1><<<dim3(3 * DIMM / 128, BSR / 128), 512, SMEM_DYN_G>>>(
        x, KDIM, WqkvT, 0, bqkv, nullptr, 0, qkvh);
    /* 2) q column-sums */
    q_sum_kernel<<<BB * (DIMM / 32), 1024>>>(qkvh, qinv);
    /* 3) A = K^T Q on tensor cores (fused softmaxes) */
    ktq_kernel<<<BB * HH * TSPLIT, 256>>>(qkvh, qinv, Apart);
    a_reduce_kernel<<<(BB * HH * HDD * HDD) / 256, 256>>>(Apart, Amat);
    /* 4) B~ = A (x) Wproj  (fp16) */
    wA_kernel<<<dim3(16, BB * HH), 256>>>(WprojT, Amat, btilde);
    /* 5) out = V @ B~ + bproj */
    gemm_fp16<0><<<dim3(DIMM / 128, BSR / 128), 512, SMEM_DYN_G>>>(
        (const void*)(qkvh + 2048), QKVH, btilde, DIMM * DIMM, bproj, out, DIMM, nullptr);
}

// round 14
// speedup vs baseline: 2.3117x; 1.0297x over previous
#include <cuda_runtime.h>
#include <cuda_fp16.h>
#include <cstdint>
#include <math.h>

#define BB   8
#define SS   4096
#define DIMM 1024
#define HH   16
#define HDD  64
#define BSR  (BB * SS)          /* 32768 rows */
#define QKVH 3072               /* fp16 qkv row stride */
#define TSPLIT 8
#define SCALE_F 0.125f          /* 64^-0.5 */
#define KDIM 1024               /* K of both big GEMMs */

/* -------- scratch (device globals: allocation-free rule) -------- */
__device__ __half g_qkvh[(size_t)BSR * QKVH];                      /* 201 MB */
__device__ float  g_qsum[(size_t)BB * DIMM];                       /* 32 KB  */
__device__ __half g_btilde[(size_t)BB * DIMM * DIMM];              /* 16 MB  */
__device__ float  g_Apart[(size_t)TSPLIT * BB * HH * HDD * HDD];   /* 16 MB  */
__device__ float  g_A[(size_t)BB * HH * HDD * HDD];                /* 2 MB   */
__device__ __half g_WqkvT[(size_t)3 * DIMM * DIMM];                /* 6 MB   */
__device__ __half g_WprojT[(size_t)DIMM * DIMM];                   /* 2 MB   */

/* ===== fp16 mma.sync GEMM: 512 thr, tile 128x128, warp tile 32x32,
 * m16n8k16.f32.f16.f16.f32, 8-stage cp.async ring, peeled tail.
 * MODE 1: A fp32 (x) converted fp16 in-kernel; fp16 epilogue to qkvh,
 *         PLUS fused exp-column-sums for the q blocks (atomicAdd qsum).
 * MODE 0: A fp16; fp32 epilogue to C. ===== */

#define BROW  80
#define A_STG 10240
#define STG_BYTES 20480
#define NSTG  8
#define SMEM_DYN_G (NSTG * STG_BYTES)
#define NCH   (KDIM / 32)

__device__ __forceinline__ uint32_t smem_u32(const void* p) {
    uint32_t a;
    asm("{ .reg .u64 t; cvta.to.shared.u64 t, %1; cvt.u32.u64 %0, t; }"
        : "=r"(a) : "l"(p));
    return a;
}
__device__ __forceinline__ void cp16(uint32_t dst, const void* src) {
    asm volatile("cp.async.cg.shared.global [%0], [%1], 16;"
                 :: "r"(dst), "l"(src) : "memory");
}
__device__ __forceinline__ uint32_t pack2(float lo, float hi) {
    uint32_t r;
    asm("cvt.rn.f16x2.f32 %0, %1, %2;" : "=r"(r) : "f"(hi), "f"(lo));
    return r;
}
__device__ __forceinline__ void sts16u(uint32_t dst, uint32_t a, uint32_t b,
                                       uint32_t c, uint32_t d) {
    asm volatile("st.shared.v4.b32 [%0], {%1,%2,%3,%4};"
                 :: "r"(dst), "r"(a), "r"(b), "r"(c), "r"(d) : "memory");
}
__device__ __forceinline__ void ldsm4(uint32_t* r, uint32_t addr) {
    asm volatile("ldmatrix.sync.aligned.m8n8.x4.shared.b16 {%0,%1,%2,%3}, [%4];"
                 : "=r"(r[0]), "=r"(r[1]), "=r"(r[2]), "=r"(r[3]) : "r"(addr));
}
__device__ __forceinline__ void mma_f16(float* c, const uint32_t* a, const uint32_t* b) {
    asm volatile("mma.sync.aligned.m16n8k16.row.col.f32.f16.f16.f32 "
                 "{%0,%1,%2,%3}, {%4,%5,%6,%7}, {%8,%9}, {%0,%1,%2,%3};"
                 : "+f"(c[0]), "+f"(c[1]), "+f"(c[2]), "+f"(c[3])
                 : "r"(a[0]), "r"(a[1]), "r"(a[2]), "r"(a[3]),
                   "r"(b[0]), "r"(b[1]));
}

__device__ __forceinline__ void chunk_mma(uint32_t st, const uint32_t* aoff,
                                          const uint32_t* boff,
                                          float acc[2][4][4])
{
#pragma unroll
    for (int ks = 0; ks < 2; ks++) {
        uint32_t av[2][4], bv[2][4];
#pragma unroll
        for (int mf = 0; mf < 2; mf++)
            ldsm4(av[mf], st + aoff[mf] + ks * 32);
#pragma unroll
        for (int p = 0; p < 2; p++)
            ldsm4(bv[p], st + boff[p] + ks * 32);
#pragma unroll
        for (int mf = 0; mf < 2; mf++)
#pragma unroll
            for (int nf = 0; nf < 4; nf++)
                mma_f16(acc[mf][nf], av[mf], &bv[nf >> 1][(nf & 1) * 2]);
    }
}

template<int MODE>
__global__ void __launch_bounds__(512, 1)
gemm_fp16(const void* __restrict__ Ain, int astr,
          const __half* __restrict__ BT, int bstride,
          const float* __restrict__ bias, float* __restrict__ C, int cstr,
          __half* __restrict__ hout, float* __restrict__ qsum)
{
    extern __shared__ __align__(16) char sm[];
    const uint32_t u0 = smem_u32(sm);

    const int tid  = threadIdx.x;
    const int lane = tid & 31;
    const int warp = tid >> 5;
    const int wm   = warp & 3;
    const int wn   = warp >> 2;
    const int g    = lane >> 2;
    const int tig  = lane & 3;

    const int lrow = tid >> 2;
    const int lq   = tid & 3;
    const float*  Ag32 = (const float*)Ain + (size_t)(blockIdx.y * 128 + lrow) * astr + lq * 8;
    const __half* Agh  = (const __half*)Ain + (size_t)(blockIdx.y * 128 + lrow) * astr + lq * 8;
    const __half* Bg   = BT + (size_t)(blockIdx.y >> 5) * (size_t)bstride
                            + (size_t)(blockIdx.x * 128 + lrow) * KDIM + lq * 8;
    const uint32_t dstA = u0 + (uint32_t)(lrow * BROW + lq * 16);
    const uint32_t dstB = dstA + A_STG;

    const int rb = wm * 32;
    const int cb = wn * 32;

    uint32_t aoff[2];
#pragma unroll
    for (int mf = 0; mf < 2; mf++)
        aoff[mf] = (uint32_t)((rb + mf * 16 + (lane & 15)) * BROW + 16 * (lane >> 4));
    uint32_t boff[2];
#pragma unroll
    for (int p = 0; p < 2; p++)
        boff[p] = (uint32_t)(A_STG + (cb + p * 16 + ((lane >> 4) << 3) + (lane & 7)) * BROW
                             + 16 * ((lane >> 3) & 1));

    float acc[2][4][4];
#pragma unroll
    for (int i = 0; i < 2; i++)
#pragma unroll
        for (int j = 0; j < 4; j++)
#pragma unroll
            for (int r = 0; r < 4; r++) acc[i][j][r] = 0.f;

#pragma unroll
    for (int s = 0; s < NSTG - 1; s++) {
        const uint32_t sb = (uint32_t)(s * STG_BYTES);
        const int k0 = s * 32;
        if (MODE == 1) {
            float4 v0 = *(const float4*)(Ag32 + k0);
            float4 v1 = *(const float4*)(Ag32 + k0 + 4);
            sts16u(dstA + sb, pack2(v0.x, v0.y), pack2(v0.z, v0.w),
                   pack2(v1.x, v1.y), pack2(v1.z, v1.w));
        } else {
            cp16(dstA + sb, Agh + k0);
        }
        cp16(dstB + sb, Bg + k0);
        asm volatile("cp.async.commit_group;" ::: "memory");
    }
    asm volatile("cp.async.wait_group 6;" ::: "memory");
    __syncthreads();

    for (int c = 0; c < NCH - (NSTG - 1); c++) {
        const uint32_t sb = (uint32_t)(((c + NSTG - 1) % NSTG) * STG_BYTES);
        const int k0n = (c + NSTG - 1) * 32;
        float4 pa0, pa1;
        if (MODE == 1) {
            pa0 = *(const float4*)(Ag32 + k0n);
            pa1 = *(const float4*)(Ag32 + k0n + 4);
        } else {
            cp16(dstA + sb, Agh + k0n);
        }
        cp16(dstB + sb, Bg + k0n);
        asm volatile("cp.async.commit_group;" ::: "memory");

        const uint32_t st = u0 + (uint32_t)((c % NSTG) * STG_BYTES);
        chunk_mma(st, aoff, boff, acc);

        if (MODE == 1)
            sts16u(dstA + sb, pack2(pa0.x, pa0.y), pack2(pa0.z, pa0.w),
                   pack2(pa1.x, pa1.y), pack2(pa1.z, pa1.w));
        asm volatile("cp.async.wait_group 6;" ::: "memory");
        __syncthreads();
    }

    asm volatile("cp.async.wait_group 0;" ::: "memory");
    __syncthreads();
#pragma unroll
    for (int c = NCH - (NSTG - 1); c < NCH; c++) {
        const uint32_t st = u0 + (uint32_t)((c % NSTG) * STG_BYTES);
        chunk_mma(st, aoff, boff, acc);
    }

    const int row0 = blockIdx.y * 128 + rb + g;
    const int col0 = blockIdx.x * 128 + cb + tig * 2;
    const bool is_q = (MODE == 1) && (blockIdx.x < 8);
    float cs[4][2];
#pragma unroll
    for (int nf = 0; nf < 4; nf++) { cs[nf][0] = 0.f; cs[nf][1] = 0.f; }

#pragma unroll
    for (int nf = 0; nf < 4; nf++) {
        const int col = col0 + nf * 8;
        const float b0 = bias[col], b1 = bias[col + 1];
#pragma unroll
        for (int mf = 0; mf < 2; mf++) {
            const int r = row0 + mf * 16;
            float2 v0 = make_float2(acc[mf][nf][0] + b0, acc[mf][nf][1] + b1);
            float2 v1 = make_float2(acc[mf][nf][2] + b0, acc[mf][nf][3] + b1);
            if (MODE == 1) {
                if (is_q) {
                    cs[nf][0] += __expf(v0.x) + __expf(v1.x);
                    cs[nf][1] += __expf(v0.y) + __expf(v1.y);
                }
                *(__half2*)(hout + (size_t)r * QKVH + col)       = __float22half2_rn(v0);
                *(__half2*)(hout + (size_t)(r + 8) * QKVH + col) = __float22half2_rn(v1);
            } else {
                *(float2*)(C + (size_t)r * cstr + col)       = v0;
                *(float2*)(C + (size_t)(r + 8) * cstr + col) = v1;
            }
        }
    }
    if (is_q) {
        /* reduce across the 8 g-lanes (lane = g*4 + tig) */
#pragma unroll
        for (int nf = 0; nf < 4; nf++) {
#pragma unroll
            for (int o = 4; o < 32; o <<= 1) {
                cs[nf][0] += __shfl_xor_sync(0xFFFFFFFFu, cs[nf][0], o);
                cs[nf][1] += __shfl_xor_sync(0xFFFFFFFFu, cs[nf][1], o);
            }
        }
        if (g == 0) {
            const int bb = blockIdx.y >> 5;
#pragma unroll
            for (int nf = 0; nf < 4; nf++) {
                atomicAdd(&qsum[bb * DIMM + col0 + nf * 8],     cs[nf][0]);
                atomicAdd(&qsum[bb * DIMM + col0 + nf * 8 + 1], cs[nf][1]);
            }
        }
    }
}

/* ---- weight transpose -> fp16 ---- */
__global__ void transpose_h_kernel(const float* __restrict__ S, __half* __restrict__ D,
                                   int R, int Cc)
{
    __shared__ float t[32][33];
    const int bx = blockIdx.x * 32, by = blockIdx.y * 32;
    const int x = threadIdx.x, y = threadIdx.y;
#pragma unroll
    for (int j = 0; j < 32; j += 8)
        t[y + j][x] = S[(size_t)(by + y + j) * Cc + bx + x];
    __syncthreads();
#pragma unroll
    for (int j = 0; j < 32; j += 8)
        D[(size_t)(bx + y + j) * R + by + x] = __float2half_rn(t[x][y + j]);
}

/* ---- ktq on tensor cores (fused q-normalize from qsum + k softmax) ---- */
#define KTSTR 72
__global__ void __launch_bounds__(256, 4)
ktq_kernel(const __half* __restrict__ qkvh,
           const float* __restrict__ qsum,
           float* __restrict__ Apart)
{
    const int bh = blockIdx.x / TSPLIT;
    const int ts = blockIdx.x % TSPLIT;
    const int b = bh / HH, h = bh % HH;
    const int TCHUNK = SS / TSPLIT;   /* 512 */

    __shared__ __align__(16) __half ksT[64][KTSTR];
    __shared__ __align__(16) __half qsT[64][KTSTR];
    __shared__ float inv_sm[64];

    const int tid  = threadIdx.x;
    const int lane = tid & 31;
    const int warp = tid >> 5;
    const int wm   = warp & 1;
    const int wn   = warp >> 1;
    const int rb   = wm * 32;
    const int cb   = wn * 16;

    const uint32_t ubk = smem_u32(&ksT[0][0]);
    const uint32_t ubq = smem_u32(&qsT[0][0]);
    uint32_t aoff[2];
#pragma unroll
    for (int mf = 0; mf < 2; mf++)
        aoff[mf] = ubk + (uint32_t)(((rb + mf * 16 + (lane & 15)) * KTSTR
                                     + 8 * (lane >> 4)) * 2);
    const uint32_t boff = ubq + (uint32_t)(((cb + ((lane >> 4) << 3) + (lane & 7)) * KTSTR
                                            + 8 * ((lane >> 3) & 1)) * 2);

    if (tid < 64) inv_sm[tid] = SCALE_F / qsum[b * DIMM + h * HDD + tid];
    __syncthreads();

    float acc[2][2][4];
#pragma unroll
    for (int i = 0; i < 2; i++)
#pragma unroll
        for (int j = 0; j < 2; j++)
#pragma unroll
            for (int r = 0; r < 4; r++) acc[i][j][r] = 0.f;

    const int t4  = tid >> 2;
    const int c16 = tid & 3;

    for (int t0 = 0; t0 < TCHUNK; t0 += 64) {
        const __half2* qrow = (const __half2*)(qkvh
            + ((size_t)b * SS + (size_t)ts * TCHUNK + t0 + t4) * QKVH + h * HDD + c16 * 16);
        const __half2* krow = (const __half2*)((const __half*)qrow + DIMM);
#pragma unroll
        for (int m = 0; m < 8; m++) {
            float2 f = __half22float2(qrow[m]);
            const int d0 = c16 * 16 + 2 * m;
            qsT[d0][t4]     = __float2half_rn(__expf(f.x) * inv_sm[d0]);
            qsT[d0 + 1][t4] = __float2half_rn(__expf(f.y) * inv_sm[d0 + 1]);
        }
        {
            float e[16];
            float s = 0.f;
#pragma unroll
            for (int m = 0; m < 8; m++) {
                float2 f = __half22float2(krow[m]);
                e[2 * m]     = __expf(f.x);
                e[2 * m + 1] = __expf(f.y);
                s += e[2 * m] + e[2 * m + 1];
            }
            s += __shfl_xor_sync(0xFFFFFFFFu, s, 1);
            s += __shfl_xor_sync(0xFFFFFFFFu, s, 2);
            const float rinv = 1.f / s;
#pragma unroll
            for (int j = 0; j < 16; j++)
                ksT[c16 * 16 + j][t4] = __float2half_rn(e[j] * rinv);
        }
        __syncthreads();

#pragma unroll
        for (int ks = 0; ks < 4; ks++) {
            uint32_t av[2][4], bv[4];
            ldsm4(av[0], aoff[0] + ks * 32);
            ldsm4(av[1], aoff[1] + ks * 32);
            ldsm4(bv, boff + ks * 32);
#pragma unroll
            for (int mf = 0; mf < 2; mf++)
#pragma unroll
                for (int nf = 0; nf < 2; nf++)
                    mma_f16(acc[mf][nf], av[mf], &bv[nf * 2]);
        }
        __syncthreads();
    }

    const int g   = lane >> 2;
    const int tig = lane & 3;
    float* outp = Apart + ((size_t)ts * BB * HH + bh) * (HDD * HDD);
#pragma unroll
    for (int nf = 0; nf < 2; nf++) {
        const int col = cb + tig * 2 + nf * 8;
#pragma unroll
        for (int mf = 0; mf < 2; mf++) {
            const int r = rb + g + mf * 16;
            *(float2*)&outp[r * HDD + col] =
                make_float2(acc[mf][nf][0], acc[mf][nf][1]);
            *(float2*)&outp[(r + 8) * HDD + col] =
                make_float2(acc[mf][nf][2], acc[mf][nf][3]);
        }
    }
}

__global__ void a_reduce_kernel(const float* __restrict__ Apart, float* __restrict__ A)
{
    const int idx = blockIdx.x * 256 + threadIdx.x;
    const size_t stride = (size_t)BB * HH * HDD * HDD;
    float s = 0.f;
#pragma unroll
    for (int p = 0; p < TSPLIT; p++)
        s += Apart[(size_t)p * stride + idx];
    A[idx] = s;
}

/* ---- B~[b][j][h*64+d] = half(sum_e WprojT[j][h*64+e] * A[b,h,d,e]) ---- */
__global__ void wA_kernel(const __half* __restrict__ WprojT,
                          const float* __restrict__ Amat,
                          __half* __restrict__ btilde)
{
    const int jt = blockIdx.x;
    const int bh = blockIdx.y;
    const int b = bh >> 4, h = bh & 15;

    __shared__ __align__(16) float Xsm[64][68];
    __shared__ __align__(16) float Wsm[64][68];

    const int tid = threadIdx.x;
    const int tc = tid & 15;
    const int tr = tid >> 4;

    {
        const float* Ab = Amat + (size_t)bh * (HDD * HDD);
#pragma unroll
        for (int i = 0; i < 16; i++) {
            int idx = i * 256 + tid;
            Xsm[idx & 63][idx >> 6] = Ab[idx];
        }
    }
    {
        const int lr = tid >> 2;
        const int lc = tid & 3;
        const __half* wrow = WprojT + (size_t)(jt * 64 + lr) * KDIM + h * HDD;
#pragma unroll
        for (int m = 0; m < 4; m++) {
            const int cc = (lc + 4 * m) * 4;
            __half2 a = *(const __half2*)(wrow + cc);
            __half2 bb = *(const __half2*)(wrow + cc + 2);
            Wsm[lr][cc + 0] = __low2float(a);
            Wsm[lr][cc + 1] = __high2float(a);
            Wsm[lr][cc + 2] = __low2float(bb);
            Wsm[lr][cc + 3] = __high2float(bb);
        }
    }
    __syncthreads();

    float acc[4][4];
#pragma unroll
    for (int i = 0; i < 4; i++)
#pragma unroll
        for (int j = 0; j < 4; j++) acc[i][j] = 0.f;

#pragma unroll 8
    for (int e = 0; e < 64; e++) {
        float br[4];
        *(float4*)br = *(const float4*)&Xsm[e][tc * 4];
        float wr[4];
#pragma unroll
        for (int i = 0; i < 4; i++) wr[i] = Wsm[tr * 4 + i][e];
#pragma unroll
        for (int i = 0; i < 4; i++)
#pragma unroll
            for (int j = 0; j < 4; j++)
                acc[i][j] += wr[i] * br[j];
    }

#pragma unroll
    for (int i = 0; i < 4; i++) {
        const size_t row = (size_t)b * DIMM + jt * 64 + tr * 4 + i;
        __half* orow = btilde + row * DIMM + h * HDD + tc * 4;
        *(__half2*)(orow)     = __float22half2_rn(make_float2(acc[i][0], acc[i][1]));
        *(__half2*)(orow + 2) = __float22half2_rn(make_float2(acc[i][2], acc[i][3]));
    }
}

/* --------------------------------------------------------------- */
extern "C" void kernel_launch(void* const* d_in, const int* in_sizes, int n_in,
                              void* d_out, int out_size)
{
    (void)in_sizes; (void)n_in; (void)out_size;
    const float* x     = (const float*)d_in[0];
    const float* Wqkv  = (const float*)d_in[1];
    const float* bqkv  = (const float*)d_in[2];
    const float* Wproj = (const float*)d_in[3];
    const float* bproj = (const float*)d_in[4];
    float* out = (float*)d_out;

    float *Apart, *Amat, *qsum;
    __half *qkvh, *btilde, *WqkvT, *WprojT;
    cudaGetSymbolAddress((void**)&qkvh,   g_qkvh);
    cudaGetSymbolAddress((void**)&qsum,   g_qsum);
    cudaGetSymbolAddress((void**)&btilde, g_btilde);
    cudaGetSymbolAddress((void**)&Apart,  g_Apart);
    cudaGetSymbolAddress((void**)&Amat,   g_A);
    cudaGetSymbolAddress((void**)&WqkvT,  g_WqkvT);
    cudaGetSymbolAddress((void**)&WprojT, g_WprojT);

    cudaFuncSetAttribute((const void*)gemm_fp16<1>,
                         cudaFuncAttributeMaxDynamicSharedMemorySize, SMEM_DYN_G);
    cudaFuncSetAttribute((const void*)gemm_fp16<0>,
                         cudaFuncAttributeMaxDynamicSharedMemorySize, SMEM_DYN_G);

    /* 0) zero q-sums; weights -> transposed fp16 */
    cudaMemsetAsync(qsum, 0, (size_t)BB * DIMM * sizeof(float));
    {
        dim3 blk(32, 8);
        transpose_h_kernel<<<dim3(3 * DIMM / 32, DIMM / 32), blk>>>(Wqkv, WqkvT, DIMM, 3 * DIMM);
        transpose_h_kernel<<<dim3(DIMM / 32, DIMM / 32), blk>>>(Wproj, WprojT, DIMM, DIMM);
    }
    /* 1) qkvh = fp16(x @ Wqkv + bqkv); fused q exp-column-sums */
    gemm_fp16<1><<<dim3(3 * DIMM / 128, BSR / 128), 512, SMEM_DYN_G>>>(
        x, KDIM, WqkvT, 0, bqkv, nullptr, 0, qkvh, qsum);
    /* 2) A = K^T Q on tensor cores (fused softmaxes) */
    ktq_kernel<<<BB * HH * TSPLIT, 256>>>(qkvh, qsum, Apart);
    a_reduce_kernel<<<(BB * HH * HDD * HDD) / 256, 256>>>(Apart, Amat);
    /* 3) B~ = A (x) Wproj  (fp16) */
    wA_kernel<<<dim3(16, BB * HH), 256>>>(WprojT, Amat, btilde);
    /* 4) out = V @ B~ + bproj */
    gemm_fp16<0><<<dim3(DIMM / 128, BSR / 128), 512, SMEM_DYN_G>>>(
        (const void*)(qkvh + 2048), QKVH, btilde, DIMM * DIMM, bproj, out, DIMM, nullptr, nullptr);
}

// round 15
// speedup vs baseline: 2.3553x; 1.0189x over previous
#include <cuda_runtime.h>
#include <cuda_fp16.h>
#include <cstdint>
#include <math.h>

#define BB   8
#define SS   4096
#define DIMM 1024
#define HH   16
#define HDD  64
#define BSR  (BB * SS)          /* 32768 rows */
#define QKVH 3072               /* fp16 qkv row stride */
#define TSPLIT 8
#define SCALE_F 0.125f          /* 64^-0.5 */
#define KDIM 1024               /* K of both big GEMMs */

/* -------- scratch (device globals: allocation-free rule) -------- */
__device__ __half g_qkvh[(size_t)BSR * QKVH];                      /* 201 MB */
__device__ float  g_qsum[(size_t)BB * DIMM];                       /* 32 KB  */
__device__ __half g_btilde[(size_t)BB * DIMM * DIMM];              /* 16 MB  */
__device__ float  g_Apart[(size_t)TSPLIT * BB * HH * HDD * HDD];   /* 16 MB  */
__device__ float  g_A[(size_t)BB * HH * HDD * HDD];                /* 2 MB   */
__device__ __half g_WqkvT[(size_t)3 * DIMM * DIMM];                /* 6 MB   */
__device__ __half g_WprojT[(size_t)DIMM * DIMM];                   /* 2 MB   */

/* ===== fp16 mma.sync GEMM (unchanged) ===== */

#define BROW  80
#define A_STG 10240
#define STG_BYTES 20480
#define NSTG  8
#define SMEM_DYN_G (NSTG * STG_BYTES)
#define NCH   (KDIM / 32)

__device__ __forceinline__ uint32_t smem_u32(const void* p) {
    uint32_t a;
    asm("{ .reg .u64 t; cvta.to.shared.u64 t, %1; cvt.u32.u64 %0, t; }"
        : "=r"(a) : "l"(p));
    return a;
}
__device__ __forceinline__ void cp16(uint32_t dst, const void* src) {
    asm volatile("cp.async.cg.shared.global [%0], [%1], 16;"
                 :: "r"(dst), "l"(src) : "memory");
}
__device__ __forceinline__ uint32_t pack2(float lo, float hi) {
    uint32_t r;
    asm("cvt.rn.f16x2.f32 %0, %1, %2;" : "=r"(r) : "f"(hi), "f"(lo));
    return r;
}
__device__ __forceinline__ void sts16u(uint32_t dst, uint32_t a, uint32_t b,
                                       uint32_t c, uint32_t d) {
    asm volatile("st.shared.v4.b32 [%0], {%1,%2,%3,%4};"
                 :: "r"(dst), "r"(a), "r"(b), "r"(c), "r"(d) : "memory");
}
__device__ __forceinline__ void ldsm4(uint32_t* r, uint32_t addr) {
    asm volatile("ldmatrix.sync.aligned.m8n8.x4.shared.b16 {%0,%1,%2,%3}, [%4];"
                 : "=r"(r[0]), "=r"(r[1]), "=r"(r[2]), "=r"(r[3]) : "r"(addr));
}
__device__ __forceinline__ void ldsm4t(uint32_t* r, uint32_t addr) {
    asm volatile("ldmatrix.sync.aligned.m8n8.x4.trans.shared.b16 {%0,%1,%2,%3}, [%4];"
                 : "=r"(r[0]), "=r"(r[1]), "=r"(r[2]), "=r"(r[3]) : "r"(addr));
}
__device__ __forceinline__ void mma_f16(float* c, const uint32_t* a, const uint32_t* b) {
    asm volatile("mma.sync.aligned.m16n8k16.row.col.f32.f16.f16.f32 "
                 "{%0,%1,%2,%3}, {%4,%5,%6,%7}, {%8,%9}, {%0,%1,%2,%3};"
                 : "+f"(c[0]), "+f"(c[1]), "+f"(c[2]), "+f"(c[3])
                 : "r"(a[0]), "r"(a[1]), "r"(a[2]), "r"(a[3]),
                   "r"(b[0]), "r"(b[1]));
}

__device__ __forceinline__ void chunk_mma(uint32_t st, const uint32_t* aoff,
                                          const uint32_t* boff,
                                          float acc[2][4][4])
{
#pragma unroll
    for (int ks = 0; ks < 2; ks++) {
        uint32_t av[2][4], bv[2][4];
#pragma unroll
        for (int mf = 0; mf < 2; mf++)
            ldsm4(av[mf], st + aoff[mf] + ks * 32);
#pragma unroll
        for (int p = 0; p < 2; p++)
            ldsm4(bv[p], st + boff[p] + ks * 32);
#pragma unroll
        for (int mf = 0; mf < 2; mf++)
#pragma unroll
            for (int nf = 0; nf < 4; nf++)
                mma_f16(acc[mf][nf], av[mf], &bv[nf >> 1][(nf & 1) * 2]);
    }
}

template<int MODE>
__global__ void __launch_bounds__(512, 1)
gemm_fp16(const void* __restrict__ Ain, int astr,
          const __half* __restrict__ BT, int bstride,
          const float* __restrict__ bias, float* __restrict__ C, int cstr,
          __half* __restrict__ hout, float* __restrict__ qsum)
{
    extern __shared__ __align__(16) char sm[];
    const uint32_t u0 = smem_u32(sm);

    const int tid  = threadIdx.x;
    const int lane = tid & 31;
    const int warp = tid >> 5;
    const int wm   = warp & 3;
    const int wn   = warp >> 2;
    const int g    = lane >> 2;
    const int tig  = lane & 3;

    const int lrow = tid >> 2;
    const int lq   = tid & 3;
    const float*  Ag32 = (const float*)Ain + (size_t)(blockIdx.y * 128 + lrow) * astr + lq * 8;
    const __half* Agh  = (const __half*)Ain + (size_t)(blockIdx.y * 128 + lrow) * astr + lq * 8;
    const __half* Bg   = BT + (size_t)(blockIdx.y >> 5) * (size_t)bstride
                            + (size_t)(blockIdx.x * 128 + lrow) * KDIM + lq * 8;
    const uint32_t dstA = u0 + (uint32_t)(lrow * BROW + lq * 16);
    const uint32_t dstB = dstA + A_STG;

    const int rb = wm * 32;
    const int cb = wn * 32;

    uint32_t aoff[2];
#pragma unroll
    for (int mf = 0; mf < 2; mf++)
        aoff[mf] = (uint32_t)((rb + mf * 16 + (lane & 15)) * BROW + 16 * (lane >> 4));
    uint32_t boff[2];
#pragma unroll
    for (int p = 0; p < 2; p++)
        boff[p] = (uint32_t)(A_STG + (cb + p * 16 + ((lane >> 4) << 3) + (lane & 7)) * BROW
                             + 16 * ((lane >> 3) & 1));

    float acc[2][4][4];
#pragma unroll
    for (int i = 0; i < 2; i++)
#pragma unroll
        for (int j = 0; j < 4; j++)
#pragma unroll
            for (int r = 0; r < 4; r++) acc[i][j][r] = 0.f;

#pragma unroll
    for (int s = 0; s < NSTG - 1; s++) {
        const uint32_t sb = (uint32_t)(s * STG_BYTES);
        const int k0 = s * 32;
        if (MODE == 1) {
            float4 v0 = *(const float4*)(Ag32 + k0);
            float4 v1 = *(const float4*)(Ag32 + k0 + 4);
            sts16u(dstA + sb, pack2(v0.x, v0.y), pack2(v0.z, v0.w),
                   pack2(v1.x, v1.y), pack2(v1.z, v1.w));
        } else {
            cp16(dstA + sb, Agh + k0);
        }
        cp16(dstB + sb, Bg + k0);
        asm volatile("cp.async.commit_group;" ::: "memory");
    }
    asm volatile("cp.async.wait_group 6;" ::: "memory");
    __syncthreads();

    for (int c = 0; c < NCH - (NSTG - 1); c++) {
        const uint32_t sb = (uint32_t)(((c + NSTG - 1) % NSTG) * STG_BYTES);
        const int k0n = (c + NSTG - 1) * 32;
        float4 pa0, pa1;
        if (MODE == 1) {
            pa0 = *(const float4*)(Ag32 + k0n);
            pa1 = *(const float4*)(Ag32 + k0n + 4);
        } else {
            cp16(dstA + sb, Agh + k0n);
        }
        cp16(dstB + sb, Bg + k0n);
        asm volatile("cp.async.commit_group;" ::: "memory");

        const uint32_t st = u0 + (uint32_t)((c % NSTG) * STG_BYTES);
        chunk_mma(st, aoff, boff, acc);

        if (MODE == 1)
            sts16u(dstA + sb, pack2(pa0.x, pa0.y), pack2(pa0.z, pa0.w),
                   pack2(pa1.x, pa1.y), pack2(pa1.z, pa1.w));
        asm volatile("cp.async.wait_group 6;" ::: "memory");
        __syncthreads();
    }

    asm volatile("cp.async.wait_group 0;" ::: "memory");
    __syncthreads();
#pragma unroll
    for (int c = NCH - (NSTG - 1); c < NCH; c++) {
        const uint32_t st = u0 + (uint32_t)((c % NSTG) * STG_BYTES);
        chunk_mma(st, aoff, boff, acc);
    }

    const int row0 = blockIdx.y * 128 + rb + g;
    const int col0 = blockIdx.x * 128 + cb + tig * 2;
    const bool is_q = (MODE == 1) && (blockIdx.x < 8);
    float cs[4][2];
#pragma unroll
    for (int nf = 0; nf < 4; nf++) { cs[nf][0] = 0.f; cs[nf][1] = 0.f; }

#pragma unroll
    for (int nf = 0; nf < 4; nf++) {
        const int col = col0 + nf * 8;
        const float b0 = bias[col], b1 = bias[col + 1];
#pragma unroll
        for (int mf = 0; mf < 2; mf++) {
            const int r = row0 + mf * 16;
            float2 v0 = make_float2(acc[mf][nf][0] + b0, acc[mf][nf][1] + b1);
            float2 v1 = make_float2(acc[mf][nf][2] + b0, acc[mf][nf][3] + b1);
            if (MODE == 1) {
                if (is_q) {
                    cs[nf][0] += __expf(v0.x) + __expf(v1.x);
                    cs[nf][1] += __expf(v0.y) + __expf(v1.y);
                }
                *(__half2*)(hout + (size_t)r * QKVH + col)       = __float22half2_rn(v0);
                *(__half2*)(hout + (size_t)(r + 8) * QKVH + col) = __float22half2_rn(v1);
            } else {
                *(float2*)(C + (size_t)r * cstr + col)       = v0;
                *(float2*)(C + (size_t)(r + 8) * cstr + col) = v1;
            }
        }
    }
    if (is_q) {
#pragma unroll
        for (int nf = 0; nf < 4; nf++) {
#pragma unroll
            for (int o = 4; o < 32; o <<= 1) {
                cs[nf][0] += __shfl_xor_sync(0xFFFFFFFFu, cs[nf][0], o);
                cs[nf][1] += __shfl_xor_sync(0xFFFFFFFFu, cs[nf][1], o);
            }
        }
        if (g == 0) {
            const int bb = blockIdx.y >> 5;
#pragma unroll
            for (int nf = 0; nf < 4; nf++) {
                atomicAdd(&qsum[bb * DIMM + col0 + nf * 8],     cs[nf][0]);
                atomicAdd(&qsum[bb * DIMM + col0 + nf * 8 + 1], cs[nf][1]);
            }
        }
    }
}

/* ---- weight transpose -> fp16 ---- */
__global__ void transpose_h_kernel(const float* __restrict__ S, __half* __restrict__ D,
                                   int R, int Cc)
{
    __shared__ float t[32][33];
    const int bx = blockIdx.x * 32, by = blockIdx.y * 32;
    const int x = threadIdx.x, y = threadIdx.y;
#pragma unroll
    for (int j = 0; j < 32; j += 8)
        t[y + j][x] = S[(size_t)(by + y + j) * Cc + bx + x];
    __syncthreads();
#pragma unroll
    for (int j = 0; j < 32; j += 8)
        D[(size_t)(bx + y + j) * R + by + x] = __float2half_rn(t[x][y + j]);
}

/* ---- ktq on tensor cores: natural [t][d] tiles + ldmatrix.trans ---- */
#define KTSTR 72   /* half stride of [t][d] tiles */
__global__ void __launch_bounds__(256, 4)
ktq_kernel(const __half* __restrict__ qkvh,
           const float* __restrict__ qsum,
           float* __restrict__ Apart)
{
    const int bh = blockIdx.x / TSPLIT;
    const int ts = blockIdx.x % TSPLIT;
    const int b = bh / HH, h = bh % HH;
    const int TCHUNK = SS / TSPLIT;   /* 512 */

    __shared__ __align__(16) __half ks[64][KTSTR];   /* [t][d] */
    __shared__ __align__(16) __half qs[64][KTSTR];   /* [t][e] */
    __shared__ float inv_sm[64];

    const int tid  = threadIdx.x;
    const int lane = tid & 31;
    const int warp = tid >> 5;
    const int wm   = warp & 1;
    const int wn   = warp >> 1;
    const int rb   = wm * 32;
    const int cb   = wn * 16;

    const uint32_t ubk = smem_u32(&ks[0][0]);
    const uint32_t ubq = smem_u32(&qs[0][0]);
    /* trans ldmatrix per-lane offsets (bytes), t_base=0; step = 16 rows */
    const int a_toff = (lane & 7) + (((lane >> 4) & 1) << 3);
    const int a_doff = ((lane >> 3) & 1) * 8;
    uint32_t aoff[2];
#pragma unroll
    for (int mf = 0; mf < 2; mf++)
        aoff[mf] = ubk + (uint32_t)((a_toff * KTSTR + rb + mf * 16 + a_doff) * 2);
    const int b_toff = (lane & 7) + (((lane >> 3) & 1) << 3);
    const int b_eoff = (lane >> 4) * 8;
    const uint32_t boff = ubq + (uint32_t)((b_toff * KTSTR + cb + b_eoff) * 2);
#define KSTEP_B (16 * KTSTR * 2)

    if (tid < 64) inv_sm[tid] = SCALE_F / qsum[b * DIMM + h * HDD + tid];
    __syncthreads();

    float acc[2][2][4];
#pragma unroll
    for (int i = 0; i < 2; i++)
#pragma unroll
        for (int j = 0; j < 2; j++)
#pragma unroll
            for (int r = 0; r < 4; r++) acc[i][j][r] = 0.f;

    const int t4  = tid >> 2;   /* 0..63 local t */
    const int c16 = tid & 3;    /* 16 d/e values each */
    const uint32_t dq = ubq + (uint32_t)((t4 * KTSTR + c16 * 16) * 2);
    const uint32_t dk = ubk + (uint32_t)((t4 * KTSTR + c16 * 16) * 2);

    for (int t0 = 0; t0 < TCHUNK; t0 += 64) {
        const __half2* qrow = (const __half2*)(qkvh
            + ((size_t)b * SS + (size_t)ts * TCHUNK + t0 + t4) * QKVH + h * HDD + c16 * 16);
        const __half2* krow = (const __half2*)((const __half*)qrow + DIMM);
        /* q: exp * col-inv, packed stores */
        {
            uint32_t qu[8];
#pragma unroll
            for (int m = 0; m < 8; m++) {
                float2 f = __half22float2(qrow[m]);
                const int d0 = c16 * 16 + 2 * m;
                qu[m] = pack2(__expf(f.x) * inv_sm[d0], __expf(f.y) * inv_sm[d0 + 1]);
            }
            sts16u(dq,      qu[0], qu[1], qu[2], qu[3]);
            sts16u(dq + 16, qu[4], qu[5], qu[6], qu[7]);
        }
        /* k: row softmax over 64 (4 lanes x 16), packed stores */
        {
            float e[16];
            float s = 0.f;
#pragma unroll
            for (int m = 0; m < 8; m++) {
                float2 f = __half22float2(krow[m]);
                e[2 * m]     = __expf(f.x);
                e[2 * m + 1] = __expf(f.y);
                s += e[2 * m] + e[2 * m + 1];
            }
            s += __shfl_xor_sync(0xFFFFFFFFu, s, 1);
            s += __shfl_xor_sync(0xFFFFFFFFu, s, 2);
            const float rinv = 1.f / s;
            uint32_t ku[8];
#pragma unroll
            for (int m = 0; m < 8; m++)
                ku[m] = pack2(e[2 * m] * rinv, e[2 * m + 1] * rinv);
            sts16u(dk,      ku[0], ku[1], ku[2], ku[3]);
            sts16u(dk + 16, ku[4], ku[5], ku[6], ku[7]);
        }
        __syncthreads();

#pragma unroll
        for (int ks4 = 0; ks4 < 4; ks4++) {
            uint32_t av[2][4], bv[4];
            ldsm4t(av[0], aoff[0] + ks4 * KSTEP_B);
            ldsm4t(av[1], aoff[1] + ks4 * KSTEP_B);
            ldsm4t(bv, boff + ks4 * KSTEP_B);
#pragma unroll
            for (int mf = 0; mf < 2; mf++)
#pragma unroll
                for (int nf = 0; nf < 2; nf++)
                    mma_f16(acc[mf][nf], av[mf], &bv[nf * 2]);
        }
        __syncthreads();
    }

    const int g   = lane >> 2;
    const int tig = lane & 3;
    float* outp = Apart + ((size_t)ts * BB * HH + bh) * (HDD * HDD);
#pragma unroll
    for (int nf = 0; nf < 2; nf++) {
        const int col = cb + tig * 2 + nf * 8;
#pragma unroll
        for (int mf = 0; mf < 2; mf++) {
            const int r = rb + g + mf * 16;
            *(float2*)&outp[r * HDD + col] =
                make_float2(acc[mf][nf][0], acc[mf][nf][1]);
            *(float2*)&outp[(r + 8) * HDD + col] =
                make_float2(acc[mf][nf][2], acc[mf][nf][3]);
        }
    }
}

__global__ void a_reduce_kernel(const float* __restrict__ Apart, float* __restrict__ A)
{
    const int idx = blockIdx.x * 256 + threadIdx.x;
    const size_t stride = (size_t)BB * HH * HDD * HDD;
    float s = 0.f;
#pragma unroll
    for (int p = 0; p < TSPLIT; p++)
        s += Apart[(size_t)p * stride + idx];
    A[idx] = s;
}

/* ---- B~[b][j][h*64+d] = half(sum_e WprojT[j][h*64+e] * A[b,h,d,e]) ---- */
__global__ void wA_kernel(const __half* __restrict__ WprojT,
                          const float* __restrict__ Amat,
                          __half* __restrict__ btilde)
{
    const int jt = blockIdx.x;
    const int bh = blockIdx.y;
    const int b = bh >> 4, h = bh & 15;

    __shared__ __align__(16) float Xsm[64][68];
    __shared__ __align__(16) float Wsm[64][68];

    const int tid = threadIdx.x;
    const int tc = tid & 15;
    const int tr = tid >> 4;

    {
        const float* Ab = Amat + (size_t)bh * (HDD * HDD);
#pragma unroll
        for (int i = 0; i < 16; i++) {
            int idx = i * 256 + tid;
            Xsm[idx & 63][idx >> 6] = Ab[idx];
        }
    }
    {
        const int lr = tid >> 2;
        const int lc = tid & 3;
        const __half* wrow = WprojT + (size_t)(jt * 64 + lr) * KDIM + h * HDD;
#pragma unroll
        for (int m = 0; m < 4; m++) {
            const int cc = (lc + 4 * m) * 4;
            __half2 a = *(const __half2*)(wrow + cc);
            __half2 bb = *(const __half2*)(wrow + cc + 2);
            Wsm[lr][cc + 0] = __low2float(a);
            Wsm[lr][cc + 1] = __high2float(a);
            Wsm[lr][cc + 2] = __low2float(bb);
            Wsm[lr][cc + 3] = __high2float(bb);
        }
    }
    __syncthreads();

    float acc[4][4];
#pragma unroll
    for (int i = 0; i < 4; i++)
#pragma unroll
        for (int j = 0; j < 4; j++) acc[i][j] = 0.f;

#pragma unroll 8
    for (int e = 0; e < 64; e++) {
        float br[4];
        *(float4*)br = *(const float4*)&Xsm[e][tc * 4];
        float wr[4];
#pragma unroll
        for (int i = 0; i < 4; i++) wr[i] = Wsm[tr * 4 + i][e];
#pragma unroll
        for (int i = 0; i < 4; i++)
#pragma unroll
            for (int j = 0; j < 4; j++)
                acc[i][j] += wr[i] * br[j];
    }

#pragma unroll
    for (int i = 0; i < 4; i++) {
        const size_t row = (size_t)b * DIMM + jt * 64 + tr * 4 + i;
        __half* orow = btilde + row * DIMM + h * HDD + tc * 4;
        *(__half2*)(orow)     = __float22half2_rn(make_float2(acc[i][0], acc[i][1]));
        *(__half2*)(orow + 2) = __float22half2_rn(make_float2(acc[i][2], acc[i][3]));
    }
}

/* --------------------------------------------------------------- */
extern "C" void kernel_launch(void* const* d_in, const int* in_sizes, int n_in,
                              void* d_out, int out_size)
{
    (void)in_sizes; (void)n_in; (void)out_size;
    const float* x     = (const float*)d_in[0];
    const float* Wqkv  = (const float*)d_in[1];
    const float* bqkv  = (const float*)d_in[2];
    const float* Wproj = (const float*)d_in[3];
    const float* bproj = (const float*)d_in[4];
    float* out = (float*)d_out;

    float *Apart, *Amat, *qsum;
    __half *qkvh, *btilde, *WqkvT, *WprojT;
    cudaGetSymbolAddress((void**)&qkvh,   g_qkvh);
    cudaGetSymbolAddress((void**)&qsum,   g_qsum);
    cudaGetSymbolAddress((void**)&btilde, g_btilde);
    cudaGetSymbolAddress((void**)&Apart,  g_Apart);
    cudaGetSymbolAddress((void**)&Amat,   g_A);
    cudaGetSymbolAddress((void**)&WqkvT,  g_WqkvT);
    cudaGetSymbolAddress((void**)&WprojT, g_WprojT);

    cudaFuncSetAttribute((const void*)gemm_fp16<1>,
                         cudaFuncAttributeMaxDynamicSharedMemorySize, SMEM_DYN_G);
    cudaFuncSetAttribute((const void*)gemm_fp16<0>,
                         cudaFuncAttributeMaxDynamicSharedMemorySize, SMEM_DYN_G);

    /* 0) zero q-sums; weights -> transposed fp16 */
    cudaMemsetAsync(qsum, 0, (size_t)BB * DIMM * sizeof(float));
    {
        dim3 blk(32, 8);
        transpose_h_kernel<<<dim3(3 * DIMM / 32, DIMM / 32), blk>>>(Wqkv, WqkvT, DIMM, 3 * DIMM);
        transpose_h_kernel<<<dim3(DIMM / 32, DIMM / 32), blk>>>(Wproj, WprojT, DIMM, DIMM);
    }
    /* 1) qkvh = fp16(x @ Wqkv + bqkv); fused q exp-column-sums */
    gemm_fp16<1><<<dim3(3 * DIMM / 128, BSR / 128), 512, SMEM_DYN_G>>>(
        x, KDIM, WqkvT, 0, bqkv, nullptr, 0, qkvh, qsum);
    /* 2) A = K^T Q on tensor cores (fused softmaxes, trans ldmatrix) */
    ktq_kernel<<<BB * HH * TSPLIT, 256>>>(qkvh, qsum, Apart);
    a_reduce_kernel<<<(BB * HH * HDD * HDD) / 256, 256>>>(Apart, Amat);
    /* 3) B~ = A (x) Wproj  (fp16) */
    wA_kernel<<<dim3(16, BB * HH), 256>>>(WprojT, Amat, btilde);
    /* 4) out = V @ B~ + bproj */
    gemm_fp16<0><<<dim3(DIMM / 128, BSR / 128), 512, SMEM_DYN_G>>>(
        (const void*)(qkvh + 2048), QKVH, btilde, DIMM * DIMM, bproj, out, DIMM, nullptr, nullptr);
}

// round 16
// speedup vs baseline: 2.3857x; 1.0129x over previous
#include <cuda_runtime.h>
#include <cuda_fp16.h>
#include <cstdint>
#include <math.h>

#define BB   8
#define SS   4096
#define DIMM 1024
#define HH   16
#define HDD  64
#define BSR  (BB * SS)          /* 32768 rows */
#define QKVH 3072               /* fp16 qkv row stride */
#define TSPLIT 8
#define SCALE_F 0.125f          /* 64^-0.5 */
#define KDIM 1024               /* K of both big GEMMs */

/* -------- scratch (device globals: allocation-free rule) -------- */
__device__ __half g_qkvh[(size_t)BSR * QKVH];                      /* 201 MB */
__device__ float  g_qsum[(size_t)BB * DIMM];                       /* 32 KB  */
__device__ __half g_btilde[(size_t)BB * DIMM * DIMM];              /* 16 MB  */
__device__ float  g_Apart[(size_t)TSPLIT * BB * HH * HDD * HDD];   /* 16 MB  */
__device__ float  g_A[(size_t)BB * HH * HDD * HDD];                /* 2 MB   */
__device__ __half g_WqkvT[(size_t)3 * DIMM * DIMM];                /* 6 MB   */
__device__ __half g_WprojT[(size_t)DIMM * DIMM];                   /* 2 MB   */

/* ===== fp16 mma.sync GEMM (unchanged) ===== */

#define BROW  80
#define A_STG 10240
#define STG_BYTES 20480
#define NSTG  8
#define SMEM_DYN_G (NSTG * STG_BYTES)
#define NCH   (KDIM / 32)

__device__ __forceinline__ uint32_t smem_u32(const void* p) {
    uint32_t a;
    asm("{ .reg .u64 t; cvta.to.shared.u64 t, %1; cvt.u32.u64 %0, t; }"
        : "=r"(a) : "l"(p));
    return a;
}
__device__ __forceinline__ void cp16(uint32_t dst, const void* src) {
    asm volatile("cp.async.cg.shared.global [%0], [%1], 16;"
                 :: "r"(dst), "l"(src) : "memory");
}
__device__ __forceinline__ uint32_t pack2(float lo, float hi) {
    uint32_t r;
    asm("cvt.rn.f16x2.f32 %0, %1, %2;" : "=r"(r) : "f"(hi), "f"(lo));
    return r;
}
__device__ __forceinline__ void sts16u(uint32_t dst, uint32_t a, uint32_t b,
                                       uint32_t c, uint32_t d) {
    asm volatile("st.shared.v4.b32 [%0], {%1,%2,%3,%4};"
                 :: "r"(dst), "r"(a), "r"(b), "r"(c), "r"(d) : "memory");
}
__device__ __forceinline__ void ldsm4(uint32_t* r, uint32_t addr) {
    asm volatile("ldmatrix.sync.aligned.m8n8.x4.shared.b16 {%0,%1,%2,%3}, [%4];"
                 : "=r"(r[0]), "=r"(r[1]), "=r"(r[2]), "=r"(r[3]) : "r"(addr));
}
__device__ __forceinline__ void ldsm4t(uint32_t* r, uint32_t addr) {
    asm volatile("ldmatrix.sync.aligned.m8n8.x4.trans.shared.b16 {%0,%1,%2,%3}, [%4];"
                 : "=r"(r[0]), "=r"(r[1]), "=r"(r[2]), "=r"(r[3]) : "r"(addr));
}
__device__ __forceinline__ void mma_f16(float* c, const uint32_t* a, const uint32_t* b) {
    asm volatile("mma.sync.aligned.m16n8k16.row.col.f32.f16.f16.f32 "
                 "{%0,%1,%2,%3}, {%4,%5,%6,%7}, {%8,%9}, {%0,%1,%2,%3};"
                 : "+f"(c[0]), "+f"(c[1]), "+f"(c[2]), "+f"(c[3])
                 : "r"(a[0]), "r"(a[1]), "r"(a[2]), "r"(a[3]),
                   "r"(b[0]), "r"(b[1]));
}

__device__ __forceinline__ void chunk_mma(uint32_t st, const uint32_t* aoff,
                                          const uint32_t* boff,
                                          float acc[2][4][4])
{
#pragma unroll
    for (int ks = 0; ks < 2; ks++) {
        uint32_t av[2][4], bv[2][4];
#pragma unroll
        for (int mf = 0; mf < 2; mf++)
            ldsm4(av[mf], st + aoff[mf] + ks * 32);
#pragma unroll
        for (int p = 0; p < 2; p++)
            ldsm4(bv[p], st + boff[p] + ks * 32);
#pragma unroll
        for (int mf = 0; mf < 2; mf++)
#pragma unroll
            for (int nf = 0; nf < 4; nf++)
                mma_f16(acc[mf][nf], av[mf], &bv[nf >> 1][(nf & 1) * 2]);
    }
}

template<int MODE>
__global__ void __launch_bounds__(512, 1)
gemm_fp16(const void* __restrict__ Ain, int astr,
          const __half* __restrict__ BT, int bstride,
          const float* __restrict__ bias, float* __restrict__ C, int cstr,
          __half* __restrict__ hout, float* __restrict__ qsum)
{
    extern __shared__ __align__(16) char sm[];
    const uint32_t u0 = smem_u32(sm);

    const int tid  = threadIdx.x;
    const int lane = tid & 31;
    const int warp = tid >> 5;
    const int wm   = warp & 3;
    const int wn   = warp >> 2;
    const int g    = lane >> 2;
    const int tig  = lane & 3;

    const int lrow = tid >> 2;
    const int lq   = tid & 3;
    const float*  Ag32 = (const float*)Ain + (size_t)(blockIdx.y * 128 + lrow) * astr + lq * 8;
    const __half* Agh  = (const __half*)Ain + (size_t)(blockIdx.y * 128 + lrow) * astr + lq * 8;
    const __half* Bg   = BT + (size_t)(blockIdx.y >> 5) * (size_t)bstride
                            + (size_t)(blockIdx.x * 128 + lrow) * KDIM + lq * 8;
    const uint32_t dstA = u0 + (uint32_t)(lrow * BROW + lq * 16);
    const uint32_t dstB = dstA + A_STG;

    const int rb = wm * 32;
    const int cb = wn * 32;

    uint32_t aoff[2];
#pragma unroll
    for (int mf = 0; mf < 2; mf++)
        aoff[mf] = (uint32_t)((rb + mf * 16 + (lane & 15)) * BROW + 16 * (lane >> 4));
    uint32_t boff[2];
#pragma unroll
    for (int p = 0; p < 2; p++)
        boff[p] = (uint32_t)(A_STG + (cb + p * 16 + ((lane >> 4) << 3) + (lane & 7)) * BROW
                             + 16 * ((lane >> 3) & 1));

    float acc[2][4][4];
#pragma unroll
    for (int i = 0; i < 2; i++)
#pragma unroll
        for (int j = 0; j < 4; j++)
#pragma unroll
            for (int r = 0; r < 4; r++) acc[i][j][r] = 0.f;

#pragma unroll
    for (int s = 0; s < NSTG - 1; s++) {
        const uint32_t sb = (uint32_t)(s * STG_BYTES);
        const int k0 = s * 32;
        if (MODE == 1) {
            float4 v0 = *(const float4*)(Ag32 + k0);
            float4 v1 = *(const float4*)(Ag32 + k0 + 4);
            sts16u(dstA + sb, pack2(v0.x, v0.y), pack2(v0.z, v0.w),
                   pack2(v1.x, v1.y), pack2(v1.z, v1.w));
        } else {
            cp16(dstA + sb, Agh + k0);
        }
        cp16(dstB + sb, Bg + k0);
        asm volatile("cp.async.commit_group;" ::: "memory");
    }
    asm volatile("cp.async.wait_group 6;" ::: "memory");
    __syncthreads();

    for (int c = 0; c < NCH - (NSTG - 1); c++) {
        const uint32_t sb = (uint32_t)(((c + NSTG - 1) % NSTG) * STG_BYTES);
        const int k0n = (c + NSTG - 1) * 32;
        float4 pa0, pa1;
        if (MODE == 1) {
            pa0 = *(const float4*)(Ag32 + k0n);
            pa1 = *(const float4*)(Ag32 + k0n + 4);
        } else {
            cp16(dstA + sb, Agh + k0n);
        }
        cp16(dstB + sb, Bg + k0n);
        asm volatile("cp.async.commit_group;" ::: "memory");

        const uint32_t st = u0 + (uint32_t)((c % NSTG) * STG_BYTES);
        chunk_mma(st, aoff, boff, acc);

        if (MODE == 1)
            sts16u(dstA + sb, pack2(pa0.x, pa0.y), pack2(pa0.z, pa0.w),
                   pack2(pa1.x, pa1.y), pack2(pa1.z, pa1.w));
        asm volatile("cp.async.wait_group 6;" ::: "memory");
        __syncthreads();
    }

    asm volatile("cp.async.wait_group 0;" ::: "memory");
    __syncthreads();
#pragma unroll
    for (int c = NCH - (NSTG - 1); c < NCH; c++) {
        const uint32_t st = u0 + (uint32_t)((c % NSTG) * STG_BYTES);
        chunk_mma(st, aoff, boff, acc);
    }

    const int row0 = blockIdx.y * 128 + rb + g;
    const int col0 = blockIdx.x * 128 + cb + tig * 2;
    const bool is_q = (MODE == 1) && (blockIdx.x < 8);
    float cs[4][2];
#pragma unroll
    for (int nf = 0; nf < 4; nf++) { cs[nf][0] = 0.f; cs[nf][1] = 0.f; }

#pragma unroll
    for (int nf = 0; nf < 4; nf++) {
        const int col = col0 + nf * 8;
        const float b0 = bias[col], b1 = bias[col + 1];
#pragma unroll
        for (int mf = 0; mf < 2; mf++) {
            const int r = row0 + mf * 16;
            float2 v0 = make_float2(acc[mf][nf][0] + b0, acc[mf][nf][1] + b1);
            float2 v1 = make_float2(acc[mf][nf][2] + b0, acc[mf][nf][3] + b1);
            if (MODE == 1) {
                if (is_q) {
                    cs[nf][0] += __expf(v0.x) + __expf(v1.x);
                    cs[nf][1] += __expf(v0.y) + __expf(v1.y);
                }
                *(__half2*)(hout + (size_t)r * QKVH + col)       = __float22half2_rn(v0);
                *(__half2*)(hout + (size_t)(r + 8) * QKVH + col) = __float22half2_rn(v1);
            } else {
                *(float2*)(C + (size_t)r * cstr + col)       = v0;
                *(float2*)(C + (size_t)(r + 8) * cstr + col) = v1;
            }
        }
    }
    if (is_q) {
#pragma unroll
        for (int nf = 0; nf < 4; nf++) {
#pragma unroll
            for (int o = 4; o < 32; o <<= 1) {
                cs[nf][0] += __shfl_xor_sync(0xFFFFFFFFu, cs[nf][0], o);
                cs[nf][1] += __shfl_xor_sync(0xFFFFFFFFu, cs[nf][1], o);
            }
        }
        if (g == 0) {
            const int bb = blockIdx.y >> 5;
#pragma unroll
            for (int nf = 0; nf < 4; nf++) {
                atomicAdd(&qsum[bb * DIMM + col0 + nf * 8],     cs[nf][0]);
                atomicAdd(&qsum[bb * DIMM + col0 + nf * 8 + 1], cs[nf][1]);
            }
        }
    }
}

/* ---- weight transpose -> fp16 ---- */
__global__ void transpose_h_kernel(const float* __restrict__ S, __half* __restrict__ D,
                                   int R, int Cc)
{
    __shared__ float t[32][33];
    const int bx = blockIdx.x * 32, by = blockIdx.y * 32;
    const int x = threadIdx.x, y = threadIdx.y;
#pragma unroll
    for (int j = 0; j < 32; j += 8)
        t[y + j][x] = S[(size_t)(by + y + j) * Cc + bx + x];
    __syncthreads();
#pragma unroll
    for (int j = 0; j < 32; j += 8)
        D[(size_t)(bx + y + j) * R + by + x] = __float2half_rn(t[x][y + j]);
}

/* ---- ktq on tensor cores: [t][d] tiles, float4 LDG, ldmatrix.trans ---- */
#define KTSTR 72   /* half stride of [t][d] tiles */
__global__ void __launch_bounds__(256, 4)
ktq_kernel(const __half* __restrict__ qkvh,
           const float* __restrict__ qsum,
           float* __restrict__ Apart)
{
    const int bh = blockIdx.x / TSPLIT;
    const int ts = blockIdx.x % TSPLIT;
    const int b = bh / HH, h = bh % HH;
    const int TCHUNK = SS / TSPLIT;   /* 512 */

    __shared__ __align__(16) __half ks[64][KTSTR];   /* [t][d] */
    __shared__ __align__(16) __half qs[64][KTSTR];   /* [t][e] */
    __shared__ float inv_sm[64];

    const int tid  = threadIdx.x;
    const int lane = tid & 31;
    const int warp = tid >> 5;
    const int wm   = warp & 1;
    const int wn   = warp >> 1;
    const int rb   = wm * 32;
    const int cb   = wn * 16;

    const uint32_t ubk = smem_u32(&ks[0][0]);
    const uint32_t ubq = smem_u32(&qs[0][0]);
    const int a_toff = (lane & 7) + (((lane >> 4) & 1) << 3);
    const int a_doff = ((lane >> 3) & 1) * 8;
    uint32_t aoff[2];
#pragma unroll
    for (int mf = 0; mf < 2; mf++)
        aoff[mf] = ubk + (uint32_t)((a_toff * KTSTR + rb + mf * 16 + a_doff) * 2);
    const int b_toff = (lane & 7) + (((lane >> 3) & 1) << 3);
    const int b_eoff = (lane >> 4) * 8;
    const uint32_t boff = ubq + (uint32_t)((b_toff * KTSTR + cb + b_eoff) * 2);
#define KSTEP_B (16 * KTSTR * 2)

    if (tid < 64) inv_sm[tid] = SCALE_F / qsum[b * DIMM + h * HDD + tid];
    __syncthreads();

    float acc[2][2][4];
#pragma unroll
    for (int i = 0; i < 2; i++)
#pragma unroll
        for (int j = 0; j < 2; j++)
#pragma unroll
            for (int r = 0; r < 4; r++) acc[i][j][r] = 0.f;

    const int t4  = tid >> 2;   /* 0..63 local t */
    const int c16 = tid & 3;    /* 16 d/e values each */
    const uint32_t dq = ubq + (uint32_t)((t4 * KTSTR + c16 * 16) * 2);
    const uint32_t dk = ubk + (uint32_t)((t4 * KTSTR + c16 * 16) * 2);

    for (int t0 = 0; t0 < TCHUNK; t0 += 64) {
        const __half* rowp = qkvh
            + ((size_t)b * SS + (size_t)ts * TCHUNK + t0 + t4) * QKVH + h * HDD + c16 * 16;
        /* q: 2x float4 LDG, exp * col-inv, packed stores */
        {
            float4 r0 = *(const float4*)rowp;
            float4 r1 = *(const float4*)(rowp + 8);
            const __half2* hp0 = (const __half2*)&r0;
            const __half2* hp1 = (const __half2*)&r1;
            uint32_t qu[8];
#pragma unroll
            for (int m = 0; m < 4; m++) {
                float2 f = __half22float2(hp0[m]);
                const int d0 = c16 * 16 + 2 * m;
                qu[m] = pack2(__expf(f.x) * inv_sm[d0], __expf(f.y) * inv_sm[d0 + 1]);
            }
#pragma unroll
            for (int m = 0; m < 4; m++) {
                float2 f = __half22float2(hp1[m]);
                const int d0 = c16 * 16 + 8 + 2 * m;
                qu[4 + m] = pack2(__expf(f.x) * inv_sm[d0], __expf(f.y) * inv_sm[d0 + 1]);
            }
            sts16u(dq,      qu[0], qu[1], qu[2], qu[3]);
            sts16u(dq + 16, qu[4], qu[5], qu[6], qu[7]);
        }
        /* k: 2x float4 LDG, row softmax over 64 (4 lanes x 16) */
        {
            float4 r0 = *(const float4*)(rowp + DIMM);
            float4 r1 = *(const float4*)(rowp + DIMM + 8);
            const __half2* hp0 = (const __half2*)&r0;
            const __half2* hp1 = (const __half2*)&r1;
            float e[16];
            float s = 0.f;
#pragma unroll
            for (int m = 0; m < 4; m++) {
                float2 f = __half22float2(hp0[m]);
                e[2 * m]     = __expf(f.x);
                e[2 * m + 1] = __expf(f.y);
                s += e[2 * m] + e[2 * m + 1];
            }
#pragma unroll
            for (int m = 0; m < 4; m++) {
                float2 f = __half22float2(hp1[m]);
                e[8 + 2 * m]     = __expf(f.x);
                e[8 + 2 * m + 1] = __expf(f.y);
                s += e[8 + 2 * m] + e[8 + 2 * m + 1];
            }
            s += __shfl_xor_sync(0xFFFFFFFFu, s, 1);
            s += __shfl_xor_sync(0xFFFFFFFFu, s, 2);
            const float rinv = 1.f / s;
            uint32_t ku[8];
#pragma unroll
            for (int m = 0; m < 8; m++)
                ku[m] = pack2(e[2 * m] * rinv, e[2 * m + 1] * rinv);
            sts16u(dk,      ku[0], ku[1], ku[2], ku[3]);
            sts16u(dk + 16, ku[4], ku[5], ku[6], ku[7]);
        }
        __syncthreads();

#pragma unroll
        for (int ks4 = 0; ks4 < 4; ks4++) {
            uint32_t av[2][4], bv[4];
            ldsm4t(av[0], aoff[0] + ks4 * KSTEP_B);
            ldsm4t(av[1], aoff[1] + ks4 * KSTEP_B);
            ldsm4t(bv, boff + ks4 * KSTEP_B);
#pragma unroll
            for (int mf = 0; mf < 2; mf++)
#pragma unroll
                for (int nf = 0; nf < 2; nf++)
                    mma_f16(acc[mf][nf], av[mf], &bv[nf * 2]);
        }
        __syncthreads();
    }

    const int g   = lane >> 2;
    const int tig = lane & 3;
    float* outp = Apart + ((size_t)ts * BB * HH + bh) * (HDD * HDD);
#pragma unroll
    for (int nf = 0; nf < 2; nf++) {
        const int col = cb + tig * 2 + nf * 8;
#pragma unroll
        for (int mf = 0; mf < 2; mf++) {
            const int r = rb + g + mf * 16;
            *(float2*)&outp[r * HDD + col] =
                make_float2(acc[mf][nf][0], acc[mf][nf][1]);
            *(float2*)&outp[(r + 8) * HDD + col] =
                make_float2(acc[mf][nf][2], acc[mf][nf][3]);
        }
    }
}

__global__ void a_reduce_kernel(const float* __restrict__ Apart, float* __restrict__ A)
{
    const int idx = blockIdx.x * 256 + threadIdx.x;
    const size_t stride = (size_t)BB * HH * HDD * HDD;
    float s = 0.f;
#pragma unroll
    for (int p = 0; p < TSPLIT; p++)
        s += Apart[(size_t)p * stride + idx];
    A[idx] = s;
}

/* ---- B~[b][j][h*64+d] = half(sum_e WprojT[j][h*64+e] * A[b,h,d,e]) ---- */
__global__ void wA_kernel(const __half* __restrict__ WprojT,
                          const float* __restrict__ Amat,
                          __half* __restrict__ btilde)
{
    const int jt = blockIdx.x;
    const int bh = blockIdx.y;
    const int b = bh >> 4, h = bh & 15;

    __shared__ __align__(16) float Xsm[64][68];
    __shared__ __align__(16) float Wsm[64][68];

    const int tid = threadIdx.x;
    const int tc = tid & 15;
    const int tr = tid >> 4;

    {
        const float* Ab = Amat + (size_t)bh * (HDD * HDD);
#pragma unroll
        for (int i = 0; i < 16; i++) {
            int idx = i * 256 + tid;
            Xsm[idx & 63][idx >> 6] = Ab[idx];
        }
    }
    {
        const int lr = tid >> 2;
        const int lc = tid & 3;
        const __half* wrow = WprojT + (size_t)(jt * 64 + lr) * KDIM + h * HDD;
#pragma unroll
        for (int m = 0; m < 4; m++) {
            const int cc = (lc + 4 * m) * 4;
            __half2 a = *(const __half2*)(wrow + cc);
            __half2 bb = *(const __half2*)(wrow + cc + 2);
            Wsm[lr][cc + 0] = __low2float(a);
            Wsm[lr][cc + 1] = __high2float(a);
            Wsm[lr][cc + 2] = __low2float(bb);
            Wsm[lr][cc + 3] = __high2float(bb);
        }
    }
    __syncthreads();

    float acc[4][4];
#pragma unroll
    for (int i = 0; i < 4; i++)
#pragma unroll
        for (int j = 0; j < 4; j++) acc[i][j] = 0.f;

#pragma unroll 8
    for (int e = 0; e < 64; e++) {
        float br[4];
        *(float4*)br = *(const float4*)&Xsm[e][tc * 4];
        float wr[4];
#pragma unroll
        for (int i = 0; i < 4; i++) wr[i] = Wsm[tr * 4 + i][e];
#pragma unroll
        for (int i = 0; i < 4; i++)
#pragma unroll
            for (int j = 0; j < 4; j++)
                acc[i][j] += wr[i] * br[j];
    }

#pragma unroll
    for (int i = 0; i < 4; i++) {
        const size_t row = (size_t)b * DIMM + jt * 64 + tr * 4 + i;
        __half* orow = btilde + row * DIMM + h * HDD + tc * 4;
        *(__half2*)(orow)     = __float22half2_rn(make_float2(acc[i][0], acc[i][1]));
        *(__half2*)(orow + 2) = __float22half2_rn(make_float2(acc[i][2], acc[i][3]));
    }
}

/* --------------------------------------------------------------- */
extern "C" void kernel_launch(void* const* d_in, const int* in_sizes, int n_in,
                              void* d_out, int out_size)
{
    (void)in_sizes; (void)n_in; (void)out_size;
    const float* x     = (const float*)d_in[0];
    const float* Wqkv  = (const float*)d_in[1];
    const float* bqkv  = (const float*)d_in[2];
    const float* Wproj = (const float*)d_in[3];
    const float* bproj = (const float*)d_in[4];
    float* out = (float*)d_out;

    float *Apart, *Amat, *qsum;
    __half *qkvh, *btilde, *WqkvT, *WprojT;
    cudaGetSymbolAddress((void**)&qkvh,   g_qkvh);
    cudaGetSymbolAddress((void**)&qsum,   g_qsum);
    cudaGetSymbolAddress((void**)&btilde, g_btilde);
    cudaGetSymbolAddress((void**)&Apart,  g_Apart);
    cudaGetSymbolAddress((void**)&Amat,   g_A);
    cudaGetSymbolAddress((void**)&WqkvT,  g_WqkvT);
    cudaGetSymbolAddress((void**)&WprojT, g_WprojT);

    cudaFuncSetAttribute((const void*)gemm_fp16<1>,
                         cudaFuncAttributeMaxDynamicSharedMemorySize, SMEM_DYN_G);
    cudaFuncSetAttribute((const void*)gemm_fp16<0>,
                         cudaFuncAttributeMaxDynamicSharedMemorySize, SMEM_DYN_G);

    /* 0) zero q-sums; weights -> transposed fp16 */
    cudaMemsetAsync(qsum, 0, (size_t)BB * DIMM * sizeof(float));
    {
        dim3 blk(32, 8);
        transpose_h_kernel<<<dim3(3 * DIMM / 32, DIMM / 32), blk>>>(Wqkv, WqkvT, DIMM, 3 * DIMM);
        transpose_h_kernel<<<dim3(DIMM / 32, DIMM / 32), blk>>>(Wproj, WprojT, DIMM, DIMM);
    }
    /* 1) qkvh = fp16(x @ Wqkv + bqkv); fused q exp-column-sums */
    gemm_fp16<1><<<dim3(3 * DIMM / 128, BSR / 128), 512, SMEM_DYN_G>>>(
        x, KDIM, WqkvT, 0, bqkv, nullptr, 0, qkvh, qsum);
    /* 2) A = K^T Q on tensor cores (fused softmaxes, trans ldmatrix) */
    ktq_kernel<<<BB * HH * TSPLIT, 256>>>(qkvh, qsum, Apart);
    a_reduce_kernel<<<(BB * HH * HDD * HDD) / 256, 256>>>(Apart, Amat);
    /* 3) B~ = A (x) Wproj  (fp16) */
    wA_kernel<<<dim3(16, BB * HH), 256>>>(WprojT, Amat, btilde);
    /* 4) out = V @ B~ + bproj */
    gemm_fp16<0><<<dim3(DIMM / 128, BSR / 128), 512, SMEM_DYN_G>>>(
        (const void*)(qkvh + 2048), QKVH, btilde, DIMM * DIMM, bproj, out, DIMM, nullptr, nullptr);
}

// round 17
// speedup vs baseline: 2.3878x; 1.0009x over previous
#include <cuda_runtime.h>
#include <cuda_fp16.h>
#include <cstdint>
#include <math.h>

#define BB   8
#define SS   4096
#define DIMM 1024
#define HH   16
#define HDD  64
#define BSR  (BB * SS)          /* 32768 rows */
#define QKVH 3072               /* fp16 qkv row stride */
#define TSPLIT 8
#define SCALE_F 0.125f          /* 64^-0.5 */
#define KDIM 1024               /* K of both big GEMMs */

/* -------- scratch (device globals: allocation-free rule) -------- */
__device__ __half g_qkvh[(size_t)BSR * QKVH];                      /* 201 MB */
__device__ float  g_qsum[(size_t)BB * DIMM];                       /* 32 KB  */
__device__ __half g_btilde[(size_t)BB * DIMM * DIMM];              /* 16 MB  */
__device__ float  g_Apart[(size_t)TSPLIT * BB * HH * HDD * HDD];   /* 16 MB  */
__device__ float  g_A[(size_t)BB * HH * HDD * HDD];                /* 2 MB   */
__device__ __half g_WqkvT[(size_t)3 * DIMM * DIMM];                /* 6 MB   */
__device__ __half g_WprojT[(size_t)DIMM * DIMM];                   /* 2 MB   */

/* ===== fp16 mma.sync GEMM (unchanged) ===== */

#define BROW  80
#define A_STG 10240
#define STG_BYTES 20480
#define NSTG  8
#define SMEM_DYN_G (NSTG * STG_BYTES)
#define NCH   (KDIM / 32)

__device__ __forceinline__ uint32_t smem_u32(const void* p) {
    uint32_t a;
    asm("{ .reg .u64 t; cvta.to.shared.u64 t, %1; cvt.u32.u64 %0, t; }"
        : "=r"(a) : "l"(p));
    return a;
}
__device__ __forceinline__ void cp16(uint32_t dst, const void* src) {
    asm volatile("cp.async.cg.shared.global [%0], [%1], 16;"
                 :: "r"(dst), "l"(src) : "memory");
}
__device__ __forceinline__ uint32_t pack2(float lo, float hi) {
    uint32_t r;
    asm("cvt.rn.f16x2.f32 %0, %1, %2;" : "=r"(r) : "f"(hi), "f"(lo));
    return r;
}
__device__ __forceinline__ void sts16u(uint32_t dst, uint32_t a, uint32_t b,
                                       uint32_t c, uint32_t d) {
    asm volatile("st.shared.v4.b32 [%0], {%1,%2,%3,%4};"
                 :: "r"(dst), "r"(a), "r"(b), "r"(c), "r"(d) : "memory");
}
__device__ __forceinline__ void ldsm4(uint32_t* r, uint32_t addr) {
    asm volatile("ldmatrix.sync.aligned.m8n8.x4.shared.b16 {%0,%1,%2,%3}, [%4];"
                 : "=r"(r[0]), "=r"(r[1]), "=r"(r[2]), "=r"(r[3]) : "r"(addr));
}
__device__ __forceinline__ void ldsm4t(uint32_t* r, uint32_t addr) {
    asm volatile("ldmatrix.sync.aligned.m8n8.x4.trans.shared.b16 {%0,%1,%2,%3}, [%4];"
                 : "=r"(r[0]), "=r"(r[1]), "=r"(r[2]), "=r"(r[3]) : "r"(addr));
}
__device__ __forceinline__ void mma_f16(float* c, const uint32_t* a, const uint32_t* b) {
    asm volatile("mma.sync.aligned.m16n8k16.row.col.f32.f16.f16.f32 "
                 "{%0,%1,%2,%3}, {%4,%5,%6,%7}, {%8,%9}, {%0,%1,%2,%3};"
                 : "+f"(c[0]), "+f"(c[1]), "+f"(c[2]), "+f"(c[3])
                 : "r"(a[0]), "r"(a[1]), "r"(a[2]), "r"(a[3]),
                   "r"(b[0]), "r"(b[1]));
}

__device__ __forceinline__ void chunk_mma(uint32_t st, const uint32_t* aoff,
                                          const uint32_t* boff,
                                          float acc[2][4][4])
{
#pragma unroll
    for (int ks = 0; ks < 2; ks++) {
        uint32_t av[2][4], bv[2][4];
#pragma unroll
        for (int mf = 0; mf < 2; mf++)
            ldsm4(av[mf], st + aoff[mf] + ks * 32);
#pragma unroll
        for (int p = 0; p < 2; p++)
            ldsm4(bv[p], st + boff[p] + ks * 32);
#pragma unroll
        for (int mf = 0; mf < 2; mf++)
#pragma unroll
            for (int nf = 0; nf < 4; nf++)
                mma_f16(acc[mf][nf], av[mf], &bv[nf >> 1][(nf & 1) * 2]);
    }
}

template<int MODE>
__global__ void __launch_bounds__(512, 1)
gemm_fp16(const void* __restrict__ Ain, int astr,
          const __half* __restrict__ BT, int bstride,
          const float* __restrict__ bias, float* __restrict__ C, int cstr,
          __half* __restrict__ hout, float* __restrict__ qsum)
{
    extern __shared__ __align__(16) char sm[];
    const uint32_t u0 = smem_u32(sm);

    const int tid  = threadIdx.x;
    const int lane = tid & 31;
    const int warp = tid >> 5;
    const int wm   = warp & 3;
    const int wn   = warp >> 2;
    const int g    = lane >> 2;
    const int tig  = lane & 3;

    const int lrow = tid >> 2;
    const int lq   = tid & 3;
    const float*  Ag32 = (const float*)Ain + (size_t)(blockIdx.y * 128 + lrow) * astr + lq * 8;
    const __half* Agh  = (const __half*)Ain + (size_t)(blockIdx.y * 128 + lrow) * astr + lq * 8;
    const __half* Bg   = BT + (size_t)(blockIdx.y >> 5) * (size_t)bstride
                            + (size_t)(blockIdx.x * 128 + lrow) * KDIM + lq * 8;
    const uint32_t dstA = u0 + (uint32_t)(lrow * BROW + lq * 16);
    const uint32_t dstB = dstA + A_STG;

    const int rb = wm * 32;
    const int cb = wn * 32;

    uint32_t aoff[2];
#pragma unroll
    for (int mf = 0; mf < 2; mf++)
        aoff[mf] = (uint32_t)((rb + mf * 16 + (lane & 15)) * BROW + 16 * (lane >> 4));
    uint32_t boff[2];
#pragma unroll
    for (int p = 0; p < 2; p++)
        boff[p] = (uint32_t)(A_STG + (cb + p * 16 + ((lane >> 4) << 3) + (lane & 7)) * BROW
                             + 16 * ((lane >> 3) & 1));

    float acc[2][4][4];
#pragma unroll
    for (int i = 0; i < 2; i++)
#pragma unroll
        for (int j = 0; j < 4; j++)
#pragma unroll
            for (int r = 0; r < 4; r++) acc[i][j][r] = 0.f;

#pragma unroll
    for (int s = 0; s < NSTG - 1; s++) {
        const uint32_t sb = (uint32_t)(s * STG_BYTES);
        const int k0 = s * 32;
        if (MODE == 1) {
            float4 v0 = *(const float4*)(Ag32 + k0);
            float4 v1 = *(const float4*)(Ag32 + k0 + 4);
            sts16u(dstA + sb, pack2(v0.x, v0.y), pack2(v0.z, v0.w),
                   pack2(v1.x, v1.y), pack2(v1.z, v1.w));
        } else {
            cp16(dstA + sb, Agh + k0);
        }
        cp16(dstB + sb, Bg + k0);
        asm volatile("cp.async.commit_group;" ::: "memory");
    }
    asm volatile("cp.async.wait_group 6;" ::: "memory");
    __syncthreads();

    for (int c = 0; c < NCH - (NSTG - 1); c++) {
        const uint32_t sb = (uint32_t)(((c + NSTG - 1) % NSTG) * STG_BYTES);
        const int k0n = (c + NSTG - 1) * 32;
        float4 pa0, pa1;
        if (MODE == 1) {
            pa0 = *(const float4*)(Ag32 + k0n);
            pa1 = *(const float4*)(Ag32 + k0n + 4);
        } else {
            cp16(dstA + sb, Agh + k0n);
        }
        cp16(dstB + sb, Bg + k0n);
        asm volatile("cp.async.commit_group;" ::: "memory");

        const uint32_t st = u0 + (uint32_t)((c % NSTG) * STG_BYTES);
        chunk_mma(st, aoff, boff, acc);

        if (MODE == 1)
            sts16u(dstA + sb, pack2(pa0.x, pa0.y), pack2(pa0.z, pa0.w),
                   pack2(pa1.x, pa1.y), pack2(pa1.z, pa1.w));
        asm volatile("cp.async.wait_group 6;" ::: "memory");
        __syncthreads();
    }

    asm volatile("cp.async.wait_group 0;" ::: "memory");
    __syncthreads();
#pragma unroll
    for (int c = NCH - (NSTG - 1); c < NCH; c++) {
        const uint32_t st = u0 + (uint32_t)((c % NSTG) * STG_BYTES);
        chunk_mma(st, aoff, boff, acc);
    }

    const int row0 = blockIdx.y * 128 + rb + g;
    const int col0 = blockIdx.x * 128 + cb + tig * 2;
    const bool is_q = (MODE == 1) && (blockIdx.x < 8);
    float cs[4][2];
#pragma unroll
    for (int nf = 0; nf < 4; nf++) { cs[nf][0] = 0.f; cs[nf][1] = 0.f; }

#pragma unroll
    for (int nf = 0; nf < 4; nf++) {
        const int col = col0 + nf * 8;
        const float b0 = bias[col], b1 = bias[col + 1];
#pragma unroll
        for (int mf = 0; mf < 2; mf++) {
            const int r = row0 + mf * 16;
            float2 v0 = make_float2(acc[mf][nf][0] + b0, acc[mf][nf][1] + b1);
            float2 v1 = make_float2(acc[mf][nf][2] + b0, acc[mf][nf][3] + b1);
            if (MODE == 1) {
                if (is_q) {
                    cs[nf][0] += __expf(v0.x) + __expf(v1.x);
                    cs[nf][1] += __expf(v0.y) + __expf(v1.y);
                }
                *(__half2*)(hout + (size_t)r * QKVH + col)       = __float22half2_rn(v0);
                *(__half2*)(hout + (size_t)(r + 8) * QKVH + col) = __float22half2_rn(v1);
            } else {
                *(float2*)(C + (size_t)r * cstr + col)       = v0;
                *(float2*)(C + (size_t)(r + 8) * cstr + col) = v1;
            }
        }
    }
    if (is_q) {
#pragma unroll
        for (int nf = 0; nf < 4; nf++) {
#pragma unroll
            for (int o = 4; o < 32; o <<= 1) {
                cs[nf][0] += __shfl_xor_sync(0xFFFFFFFFu, cs[nf][0], o);
                cs[nf][1] += __shfl_xor_sync(0xFFFFFFFFu, cs[nf][1], o);
            }
        }
        if (g == 0) {
            const int bb = blockIdx.y >> 5;
#pragma unroll
            for (int nf = 0; nf < 4; nf++) {
                atomicAdd(&qsum[bb * DIMM + col0 + nf * 8],     cs[nf][0]);
                atomicAdd(&qsum[bb * DIMM + col0 + nf * 8 + 1], cs[nf][1]);
            }
        }
    }
}

/* ---- weight transpose -> fp16 ---- */
__global__ void transpose_h_kernel(const float* __restrict__ S, __half* __restrict__ D,
                                   int R, int Cc)
{
    __shared__ float t[32][33];
    const int bx = blockIdx.x * 32, by = blockIdx.y * 32;
    const int x = threadIdx.x, y = threadIdx.y;
#pragma unroll
    for (int j = 0; j < 32; j += 8)
        t[y + j][x] = S[(size_t)(by + y + j) * Cc + bx + x];
    __syncthreads();
#pragma unroll
    for (int j = 0; j < 32; j += 8)
        D[(size_t)(bx + y + j) * R + by + x] = __float2half_rn(t[x][y + j]);
}

/* ---- ktq: [t][d] tiles, PIPELINED float4 LDG, ldmatrix.trans ---- */
#define KTSTR 72   /* half stride of [t][d] tiles */
__global__ void __launch_bounds__(256, 3)
ktq_kernel(const __half* __restrict__ qkvh,
           const float* __restrict__ qsum,
           float* __restrict__ Apart)
{
    const int bh = blockIdx.x / TSPLIT;
    const int ts = blockIdx.x % TSPLIT;
    const int b = bh / HH, h = bh % HH;
    const int TCHUNK = SS / TSPLIT;   /* 512 */

    __shared__ __align__(16) __half ks[64][KTSTR];   /* [t][d] */
    __shared__ __align__(16) __half qs[64][KTSTR];   /* [t][e] */
    __shared__ float inv_sm[64];

    const int tid  = threadIdx.x;
    const int lane = tid & 31;
    const int warp = tid >> 5;
    const int wm   = warp & 1;
    const int wn   = warp >> 1;
    const int rb   = wm * 32;
    const int cb   = wn * 16;

    const uint32_t ubk = smem_u32(&ks[0][0]);
    const uint32_t ubq = smem_u32(&qs[0][0]);
    const int a_toff = (lane & 7) + (((lane >> 4) & 1) << 3);
    const int a_doff = ((lane >> 3) & 1) * 8;
    uint32_t aoff[2];
#pragma unroll
    for (int mf = 0; mf < 2; mf++)
        aoff[mf] = ubk + (uint32_t)((a_toff * KTSTR + rb + mf * 16 + a_doff) * 2);
    const int b_toff = (lane & 7) + (((lane >> 3) & 1) << 3);
    const int b_eoff = (lane >> 4) * 8;
    const uint32_t boff = ubq + (uint32_t)((b_toff * KTSTR + cb + b_eoff) * 2);
#define KSTEP_B (16 * KTSTR * 2)

    if (tid < 64) inv_sm[tid] = SCALE_F / qsum[b * DIMM + h * HDD + tid];
    __syncthreads();

    float acc[2][2][4];
#pragma unroll
    for (int i = 0; i < 2; i++)
#pragma unroll
        for (int j = 0; j < 2; j++)
#pragma unroll
            for (int r = 0; r < 4; r++) acc[i][j][r] = 0.f;

    const int t4  = tid >> 2;   /* 0..63 local t */
    const int c16 = tid & 3;    /* 16 d/e values each */
    const uint32_t dq = ubq + (uint32_t)((t4 * KTSTR + c16 * 16) * 2);
    const uint32_t dk = ubk + (uint32_t)((t4 * KTSTR + c16 * 16) * 2);

    const __half* rowbase = qkvh
        + ((size_t)b * SS + (size_t)ts * TCHUNK + t4) * QKVH + h * HDD + c16 * 16;
    const size_t rowstep = (size_t)64 * QKVH;

    /* prefetch iter 0 */
    float4 q0 = *(const float4*)rowbase;
    float4 q1 = *(const float4*)(rowbase + 8);
    float4 k0 = *(const float4*)(rowbase + DIMM);
    float4 k1 = *(const float4*)(rowbase + DIMM + 8);

    const int NIT = TCHUNK / 64;   /* 8 */
    for (int it = 0; it < NIT; it++) {
        /* stage current regs: q exp*inv, k row-softmax, packed STS */
        {
            const __half2* hp0 = (const __half2*)&q0;
            const __half2* hp1 = (const __half2*)&q1;
            uint32_t qu[8];
#pragma unroll
            for (int m = 0; m < 4; m++) {
                float2 f = __half22float2(hp0[m]);
                const int d0 = c16 * 16 + 2 * m;
                qu[m] = pack2(__expf(f.x) * inv_sm[d0], __expf(f.y) * inv_sm[d0 + 1]);
            }
#pragma unroll
            for (int m = 0; m < 4; m++) {
                float2 f = __half22float2(hp1[m]);
                const int d0 = c16 * 16 + 8 + 2 * m;
                qu[4 + m] = pack2(__expf(f.x) * inv_sm[d0], __expf(f.y) * inv_sm[d0 + 1]);
            }
            sts16u(dq,      qu[0], qu[1], qu[2], qu[3]);
            sts16u(dq + 16, qu[4], qu[5], qu[6], qu[7]);
        }
        {
            const __half2* hp0 = (const __half2*)&k0;
            const __half2* hp1 = (const __half2*)&k1;
            float e[16];
            float s = 0.f;
#pragma unroll
            for (int m = 0; m < 4; m++) {
                float2 f = __half22float2(hp0[m]);
                e[2 * m]     = __expf(f.x);
                e[2 * m + 1] = __expf(f.y);
                s += e[2 * m] + e[2 * m + 1];
            }
#pragma unroll
            for (int m = 0; m < 4; m++) {
                float2 f = __half22float2(hp1[m]);
                e[8 + 2 * m]     = __expf(f.x);
                e[8 + 2 * m + 1] = __expf(f.y);
                s += e[8 + 2 * m] + e[8 + 2 * m + 1];
            }
            s += __shfl_xor_sync(0xFFFFFFFFu, s, 1);
            s += __shfl_xor_sync(0xFFFFFFFFu, s, 2);
            const float rinv = 1.f / s;
            uint32_t ku[8];
#pragma unroll
            for (int m = 0; m < 8; m++)
                ku[m] = pack2(e[2 * m] * rinv, e[2 * m + 1] * rinv);
            sts16u(dk,      ku[0], ku[1], ku[2], ku[3]);
            sts16u(dk + 16, ku[4], ku[5], ku[6], ku[7]);
        }
        __syncthreads();

        /* prefetch iter it+1 while MMAs run */
        if (it + 1 < NIT) {
            const __half* rp = rowbase + (size_t)(it + 1) * rowstep;
            q0 = *(const float4*)rp;
            q1 = *(const float4*)(rp + 8);
            k0 = *(const float4*)(rp + DIMM);
            k1 = *(const float4*)(rp + DIMM + 8);
        }

#pragma unroll
        for (int ks4 = 0; ks4 < 4; ks4++) {
            uint32_t av[2][4], bv[4];
            ldsm4t(av[0], aoff[0] + ks4 * KSTEP_B);
            ldsm4t(av[1], aoff[1] + ks4 * KSTEP_B);
            ldsm4t(bv, boff + ks4 * KSTEP_B);
#pragma unroll
            for (int mf = 0; mf < 2; mf++)
#pragma unroll
                for (int nf = 0; nf < 2; nf++)
                    mma_f16(acc[mf][nf], av[mf], &bv[nf * 2]);
        }
        __syncthreads();
    }

    const int g   = lane >> 2;
    const int tig = lane & 3;
    float* outp = Apart + ((size_t)ts * BB * HH + bh) * (HDD * HDD);
#pragma unroll
    for (int nf = 0; nf < 2; nf++) {
        const int col = cb + tig * 2 + nf * 8;
#pragma unroll
        for (int mf = 0; mf < 2; mf++) {
            const int r = rb + g + mf * 16;
            *(float2*)&outp[r * HDD + col] =
                make_float2(acc[mf][nf][0], acc[mf][nf][1]);
            *(float2*)&outp[(r + 8) * HDD + col] =
                make_float2(acc[mf][nf][2], acc[mf][nf][3]);
        }
    }
}

__global__ void a_reduce_kernel(const float* __restrict__ Apart, float* __restrict__ A)
{
    const int idx = blockIdx.x * 256 + threadIdx.x;
    const size_t stride = (size_t)BB * HH * HDD * HDD;
    float s = 0.f;
#pragma unroll
    for (int p = 0; p < TSPLIT; p++)
        s += Apart[(size_t)p * stride + idx];
    A[idx] = s;
}

/* ---- B~[b][j][h*64+d] = half(sum_e WprojT[j][h*64+e] * A[b,h,d,e]) ---- */
__global__ void wA_kernel(const __half* __restrict__ WprojT,
                          const float* __restrict__ Amat,
                          __half* __restrict__ btilde)
{
    const int jt = blockIdx.x;
    const int bh = blockIdx.y;
    const int b = bh >> 4, h = bh & 15;

    __shared__ __align__(16) float Xsm[64][68];
    __shared__ __align__(16) float Wsm[64][68];

    const int tid = threadIdx.x;
    const int tc = tid & 15;
    const int tr = tid >> 4;

    {
        const float* Ab = Amat + (size_t)bh * (HDD * HDD);
#pragma unroll
        for (int i = 0; i < 16; i++) {
            int idx = i * 256 + tid;
            Xsm[idx & 63][idx >> 6] = Ab[idx];
        }
    }
    {
        const int lr = tid >> 2;
        const int lc = tid & 3;
        const __half* wrow = WprojT + (size_t)(jt * 64 + lr) * KDIM + h * HDD;
#pragma unroll
        for (int m = 0; m < 4; m++) {
            const int cc = (lc + 4 * m) * 4;
            __half2 a = *(const __half2*)(wrow + cc);
            __half2 bb = *(const __half2*)(wrow + cc + 2);
            Wsm[lr][cc + 0] = __low2float(a);
            Wsm[lr][cc + 1] = __high2float(a);
            Wsm[lr][cc + 2] = __low2float(bb);
            Wsm[lr][cc + 3] = __high2float(bb);
        }
    }
    __syncthreads();

    float acc[4][4];
#pragma unroll
    for (int i = 0; i < 4; i++)
#pragma unroll
        for (int j = 0; j < 4; j++) acc[i][j] = 0.f;

#pragma unroll 8
    for (int e = 0; e < 64; e++) {
        float br[4];
        *(float4*)br = *(const float4*)&Xsm[e][tc * 4];
        float wr[4];
#pragma unroll
        for (int i = 0; i < 4; i++) wr[i] = Wsm[tr * 4 + i][e];
#pragma unroll
        for (int i = 0; i < 4; i++)
#pragma unroll
            for (int j = 0; j < 4; j++)
                acc[i][j] += wr[i] * br[j];
    }

#pragma unroll
    for (int i = 0; i < 4; i++) {
        const size_t row = (size_t)b * DIMM + jt * 64 + tr * 4 + i;
        __half* orow = btilde + row * DIMM + h * HDD + tc * 4;
        *(__half2*)(orow)     = __float22half2_rn(make_float2(acc[i][0], acc[i][1]));
        *(__half2*)(orow + 2) = __float22half2_rn(make_float2(acc[i][2], acc[i][3]));
    }
}

/* --------------------------------------------------------------- */
extern "C" void kernel_launch(void* const* d_in, const int* in_sizes, int n_in,
                              void* d_out, int out_size)
{
    (void)in_sizes; (void)n_in; (void)out_size;
    const float* x     = (const float*)d_in[0];
    const float* Wqkv  = (const float*)d_in[1];
    const float* bqkv  = (const float*)d_in[2];
    const float* Wproj = (const float*)d_in[3];
    const float* bproj = (const float*)d_in[4];
    float* out = (float*)d_out;

    float *Apart, *Amat, *qsum;
    __half *qkvh, *btilde, *WqkvT, *WprojT;
    cudaGetSymbolAddress((void**)&qkvh,   g_qkvh);
    cudaGetSymbolAddress((void**)&qsum,   g_qsum);
    cudaGetSymbolAddress((void**)&btilde, g_btilde);
    cudaGetSymbolAddress((void**)&Apart,  g_Apart);
    cudaGetSymbolAddress((void**)&Amat,   g_A);
    cudaGetSymbolAddress((void**)&WqkvT,  g_WqkvT);
    cudaGetSymbolAddress((void**)&WprojT, g_WprojT);

    cudaFuncSetAttribute((const void*)gemm_fp16<1>,
                         cudaFuncAttributeMaxDynamicSharedMemorySize, SMEM_DYN_G);
    cudaFuncSetAttribute((const void*)gemm_fp16<0>,
                         cudaFuncAttributeMaxDynamicSharedMemorySize, SMEM_DYN_G);

    /* 0) zero q-sums; weights -> transposed fp16 */
    cudaMemsetAsync(qsum, 0, (size_t)BB * DIMM * sizeof(float));
    {
        dim3 blk(32, 8);
        transpose_h_kernel<<<dim3(3 * DIMM / 32, DIMM / 32), blk>>>(Wqkv, WqkvT, DIMM, 3 * DIMM);
        transpose_h_kernel<<<dim3(DIMM / 32, DIMM / 32), blk>>>(Wproj, WprojT, DIMM, DIMM);
    }
    /* 1) qkvh = fp16(x @ Wqkv + bqkv); fused q exp-column-sums */
    gemm_fp16<1><<<dim3(3 * DIMM / 128, BSR / 128), 512, SMEM_DYN_G>>>(
        x, KDIM, WqkvT, 0, bqkv, nullptr, 0, qkvh, qsum);
    /* 2) A = K^T Q on tensor cores (fused softmaxes, pipelined loads) */
    ktq_kernel<<<BB * HH * TSPLIT, 256>>>(qkvh, qsum, Apart);
    a_reduce_kernel<<<(BB * HH * HDD * HDD) / 256, 256>>>(Apart, Amat);
    /* 3) B~ = A (x) Wproj  (fp16) */
    wA_kernel<<<dim3(16, BB * HH), 256>>>(WprojT, Amat, btilde);
    /* 4) out = V @ B~ + bproj */
    gemm_fp16<0><<<dim3(DIMM / 128, BSR / 128), 512, SMEM_DYN_G>>>(
        (const void*)(qkvh + 2048), QKVH, btilde, DIMM * DIMM, bproj, out, DIMM, nullptr, nullptr);
}